// round 2
// baseline (speedup 1.0000x reference)
#include <cuda_runtime.h>
#include <math.h>

#define LSEQ 4096
#define NTOK 8192

// ---------------- scratch offsets (floats) ----------------
#define OFF_QL    ((size_t)0)
#define OFF_KL    ((size_t)8388608)
#define OFF_VL    ((size_t)16777216)
#define OFF_Q     ((size_t)25165824)
#define OFF_K     ((size_t)33554432)
#define OFF_V     ((size_t)41943040)
#define OFF_U     ((size_t)50331648)
#define OFF_W     ((size_t)58720256)
#define OFF_DELTA ((size_t)67108864)
#define OFF_FS    ((size_t)75497472)
#define OFF_FL    ((size_t)83886080)
#define OFF_OMIX  ((size_t)92274688)
#define OFF_RIN   ((size_t)100663296)
#define OFF_HMID  ((size_t)109248512)
#define OFF_ATTN  ((size_t)126025728)
#define OFF_BETA  ((size_t)127074304)
#define OFF_SID   ((size_t)127107072)
#define OFF_P     ((size_t)127139840)
#define BUF_TOTAL ((size_t)127238144)

__device__ float g_buf[BUF_TOTAL];

__device__ __forceinline__ float sigm(float x){ return 1.0f/(1.0f+expf(-x)); }

__device__ __forceinline__ float blockReduceSum(float val, float* red) {
    int lane = threadIdx.x & 31, w = threadIdx.x >> 5;
    #pragma unroll
    for (int o=16;o;o>>=1) val += __shfl_xor_sync(0xffffffffu, val, o);
    if (lane==0) red[w]=val;
    __syncthreads();
    if (w==0) {
        float v2 = (lane<8)? red[lane] : 0.f;
        #pragma unroll
        for (int o=4;o;o>>=1) v2 += __shfl_xor_sync(0xffffffffu, v2, o);
        if (lane==0) red[0]=v2;
    }
    __syncthreads();
    float r = red[0];
    __syncthreads();
    return r;
}

// ---------------- generic 128x128 SGEMM. EPI: 0=none, 1=bias+gelu(exact) ----
template<int EPI>
__global__ void __launch_bounds__(256) sgemm_kernel(
    const float* __restrict__ A, const float* __restrict__ B,
    const float* __restrict__ bias, float* __restrict__ C,
    int M, int N, int K)
{
    __shared__ float As[8][128];
    __shared__ float Bs[8][128];
    const int tid = threadIdx.x;
    const int brow = blockIdx.y * 128;
    const int bcol = blockIdx.x * 128;
    const int arow = tid >> 1;
    const int acol = (tid & 1) << 2;
    const int brl  = tid >> 5;
    const int bcl  = (tid & 31) << 2;
    const int ty = (tid >> 4) << 3;
    const int tx = (tid & 15) << 3;
    float acc[8][8];
    #pragma unroll
    for (int i=0;i<8;i++)
        #pragma unroll
        for (int j=0;j<8;j++) acc[i][j]=0.f;
    const float* Ap = A + (size_t)(brow + arow) * K + acol;
    const float* Bp = B + (size_t)brl * N + bcol + bcl;
    for (int kt = 0; kt < K; kt += 8) {
        float4 av = *(const float4*)(Ap + kt);
        As[acol+0][arow]=av.x; As[acol+1][arow]=av.y;
        As[acol+2][arow]=av.z; As[acol+3][arow]=av.w;
        *(float4*)&Bs[brl][bcl] = *(const float4*)(Bp + (size_t)kt * N);
        __syncthreads();
        #pragma unroll
        for (int kk=0; kk<8; kk++) {
            float4 a0 = *(const float4*)&As[kk][ty];
            float4 a1 = *(const float4*)&As[kk][ty+4];
            float4 b0 = *(const float4*)&Bs[kk][tx];
            float4 b1 = *(const float4*)&Bs[kk][tx+4];
            float ar[8] = {a0.x,a0.y,a0.z,a0.w,a1.x,a1.y,a1.z,a1.w};
            float br[8] = {b0.x,b0.y,b0.z,b0.w,b1.x,b1.y,b1.z,b1.w};
            #pragma unroll
            for (int i=0;i<8;i++)
                #pragma unroll
                for (int j=0;j<8;j++) acc[i][j] += ar[i]*br[j];
        }
        __syncthreads();
    }
    #pragma unroll
    for (int i=0;i<8;i++) {
        float* Cp = C + (size_t)(brow+ty+i)*N + bcol + tx;
        #pragma unroll
        for (int j=0;j<8;j++) {
            float v = acc[i][j];
            if (EPI==1) {
                v += bias[bcol+tx+j];
                v = 0.5f*v*(1.0f+erff(v*0.70710678118654752f));
            }
            Cp[j] = v;
        }
    }
}

// ---------------- beta + id-gate projections ----------------
__global__ void __launch_bounds__(256) proj_beta_id_kernel(
    const float* __restrict__ x, const float* __restrict__ Wb,
    const float* __restrict__ Wid, const float* __restrict__ bid,
    float* __restrict__ beta, float* __restrict__ sid)
{
    int n = blockIdx.x;
    __shared__ float xs[1024];
    int tid = threadIdx.x;
    *(float4*)&xs[tid*4] = *(const float4*)(x + (size_t)n*1024 + tid*4);
    __syncthreads();
    int w = tid >> 5, lane = tid & 31;
    float s = 0.f;
    if (w < 4) { for (int d=lane; d<1024; d+=32) s += xs[d]*Wb[(size_t)d*4 + w]; }
    else       { int h=w-4; for (int d=lane; d<1024; d+=32) s += xs[d]*Wid[(size_t)d*4 + h]; }
    #pragma unroll
    for (int o=16;o;o>>=1) s += __shfl_xor_sync(0xffffffffu,s,o);
    if (lane==0) {
        if (w<4) beta[(size_t)n*4+w] = sigm(s);
        else     sid[(size_t)n*4+(w-4)] = sigm(s + bid[w-4]);
    }
}

// ---------------- causal depthwise conv (k=4) + silu ----------------
__global__ void __launch_bounds__(256) conv_silu_kernel(
    const float* __restrict__ in, const float* __restrict__ cw, float* __restrict__ out)
{
    int idx = blockIdx.x*256 + threadIdx.x;
    int c = idx & 1023;
    int n = idx >> 10;
    int l = n & (LSEQ-1);
    float4 wv = *(const float4*)(cw + (size_t)c*4);
    float wj[4] = {wv.x, wv.y, wv.z, wv.w};
    float acc = 0.f;
    #pragma unroll
    for (int j=0;j<4;j++){
        int t = l - 3 + j;
        if (t >= 0) acc += in[(size_t)(n-3+j)*1024 + c] * wj[j];
    }
    out[idx] = acc / (1.0f + expf(-acc));
}

// ---------------- per-chunk prep: l2norm, T, u, w, attn ----------------
__global__ void __launch_bounds__(256) chunk_prep_kernel(
    float* __restrict__ q, float* __restrict__ k, const float* __restrict__ v,
    const float* __restrict__ beta, float* __restrict__ u, float* __restrict__ w,
    float* __restrict__ attn)
{
    extern __shared__ float sh[];
    float* qs = sh;                 // 32*260
    float* ks = qs + 32*260;
    float* vs = ks + 32*260;
    float* T  = vs + 32*260;        // 32*33
    float* bet = T + 32*33;         // 32
    int ci = blockIdx.x;
    int c = ci & 127;
    int h = (ci >> 7) & 3;
    int b = ci >> 9;
    int tid = threadIdx.x;
    size_t base = ((size_t)(b*LSEQ + c*32))*1024 + (size_t)h*256;
    for (int i=tid; i<2048; i+=256) {
        int r = i>>6; int d4 = (i&63)<<2;
        size_t off = base + (size_t)r*1024 + d4;
        *(float4*)&qs[r*260+d4] = *(const float4*)(q + off);
        *(float4*)&ks[r*260+d4] = *(const float4*)(k + off);
        *(float4*)&vs[r*260+d4] = *(const float4*)(v + off);
    }
    if (tid < 32) bet[tid] = beta[(size_t)(b*LSEQ + c*32 + tid)*4 + h];
    __syncthreads();
    {
        int wi = tid>>5, lane = tid&31;
        for (int r = wi*4; r < wi*4+4; r++) {
            float sq=0.f, sk2=0.f;
            for (int dd=lane; dd<256; dd+=32){
                float a=qs[r*260+dd]; sq+=a*a;
                float bb=ks[r*260+dd]; sk2+=bb*bb;
            }
            #pragma unroll
            for (int o=16;o;o>>=1){
                sq+=__shfl_xor_sync(0xffffffffu,sq,o);
                sk2+=__shfl_xor_sync(0xffffffffu,sk2,o);
            }
            float rq = rsqrtf(sq+1e-6f), rk = rsqrtf(sk2+1e-6f);
            for (int dd=lane; dd<256; dd+=32){ qs[r*260+dd]*=rq; ks[r*260+dd]*=rk; }
        }
    }
    __syncthreads();
    size_t abase = (size_t)ci*1024;
    for (int pp=tid; pp<1024; pp+=256) {
        int i = pp>>5, j = pp&31;
        float dkk=0.f, dqq=0.f;
        for (int dd=0; dd<256; dd++){
            float kj = ks[j*260+dd];
            dkk += ks[i*260+dd]*kj;
            dqq += qs[i*260+dd]*kj;
        }
        T[i*33+j] = (j<i)? (-bet[i]*dkk) : 0.f;
        attn[abase+pp] = (j<=i)? dqq : 0.f;
    }
    __syncthreads();
    if (tid<32) {
        int lane = tid;
        for (int i=1;i<32;i++){
            float rowv = T[i*33+lane];
            float add = 0.f;
            for (int j=0;j<i;j++) add += __shfl_sync(0xffffffffu, rowv, j)*T[j*33+lane];
            T[i*33+lane] = rowv + add;
            __syncwarp();
        }
        T[lane*33+lane] += 1.0f;
    }
    __syncthreads();
    for (int pp=tid; pp<8192; pp+=256){
        int r = pp>>8, dd = pp&255;
        float su=0.f, sw=0.f;
        #pragma unroll
        for (int j=0;j<32;j++){
            float tj = T[r*33+j]*bet[j];
            su += tj*vs[j*260+dd];
            sw += tj*ks[j*260+dd];
        }
        size_t off = base + (size_t)r*1024 + dd;
        u[off]=su; w[off]=sw;
        q[off]=qs[r*260+dd]; k[off]=ks[r*260+dd];
    }
}

// ---------------- sequential chunk scan, dv-sliced (8 slices of 32) --------
__global__ void __launch_bounds__(256) scan_kernel(
    const float* __restrict__ q, const float* __restrict__ k,
    const float* __restrict__ u, const float* __restrict__ w,
    const float* __restrict__ attn, float* __restrict__ outp)
{
    extern __shared__ float sh[];
    float* S  = sh;              // 256*32
    float* qs = S + 8192;        // 32*260
    float* ks = qs + 32*260;
    float* ws = ks + 32*260;
    float* as = ws + 32*260;     // 32*32
    float* u2 = as + 1024;       // 32*32
    int bid = blockIdx.x;
    int sl = bid & 7;
    int bh = bid >> 3;
    int h = bh & 3, b = bh >> 2;
    int tid = threadIdx.x;
    for (int i=tid;i<8192;i+=256) S[i]=0.f;
    int iRow = tid >> 3;
    int q4 = (tid & 7) << 2;
    size_t abh = (size_t)bh * 128 * 1024;
    for (int c=0;c<128;c++){
        size_t base = ((size_t)(b*LSEQ + c*32))*1024 + (size_t)h*256;
        __syncthreads();
        for (int i=tid;i<2048;i+=256){
            int r=i>>6; int d4=(i&63)<<2;
            size_t off = base + (size_t)r*1024 + d4;
            *(float4*)&qs[r*260+d4] = *(const float4*)(q+off);
            *(float4*)&ks[r*260+d4] = *(const float4*)(k+off);
            *(float4*)&ws[r*260+d4] = *(const float4*)(w+off);
        }
        *(float4*)&as[tid*4] = *(const float4*)(attn + abh + (size_t)c*1024 + tid*4);
        __syncthreads();
        float4 au = *(const float4*)(u + base + (size_t)iRow*1024 + sl*32 + q4);
        float4 ao = make_float4(0.f,0.f,0.f,0.f);
        #pragma unroll 4
        for (int dd=0; dd<256; dd++){
            float wv = ws[iRow*260+dd];
            float qv = qs[iRow*260+dd];
            float4 Sv = *(float4*)&S[dd*32+q4];
            au.x -= wv*Sv.x; au.y -= wv*Sv.y; au.z -= wv*Sv.z; au.w -= wv*Sv.w;
            ao.x += qv*Sv.x; ao.y += qv*Sv.y; ao.z += qv*Sv.z; ao.w += qv*Sv.w;
        }
        *(float4*)&u2[iRow*32+q4] = au;
        __syncthreads();
        #pragma unroll 8
        for (int j=0;j<32;j++){
            float av = as[iRow*32+j];
            float4 uv = *(float4*)&u2[j*32+q4];
            ao.x += av*uv.x; ao.y += av*uv.y; ao.z += av*uv.z; ao.w += av*uv.w;
        }
        *(float4*)(outp + base + (size_t)iRow*1024 + sl*32 + q4) = ao;
        #pragma unroll
        for (int s2=0; s2<8; s2++){
            int t2 = tid + s2*256;
            int dd = t2>>3; int qq = (t2&7)<<2;
            float4 Sv = *(float4*)&S[dd*32+qq];
            #pragma unroll 8
            for (int j=0;j<32;j++){
                float kv = ks[j*260+dd];
                float4 uv = *(float4*)&u2[j*32+qq];
                Sv.x += kv*uv.x; Sv.y += kv*uv.y; Sv.z += kv*uv.z; Sv.w += kv*uv.w;
            }
            *(float4*)&S[dd*32+qq] = Sv;
        }
    }
}

// ---------------- FIR short/long + stats + router input --------------------
__global__ void __launch_bounds__(256) fir_stats_kernel(
    const float* __restrict__ v, const float* __restrict__ dlt,
    const float* __restrict__ x, const float* __restrict__ firS,
    const float* __restrict__ firL,
    float* __restrict__ fs, float* __restrict__ fl, float* __restrict__ rin)
{
    int n = blockIdx.x;
    int l = n & (LSEQ-1);
    int d = threadIdx.x;
    __shared__ float red[8];
    {
        const float4* xs = (const float4*)(x + (size_t)n*1024);
        float4* rp = (float4*)(rin + (size_t)n*1048);
        rp[d] = xs[d];
    }
    for (int h=0; h<4; h++) {
        int cidx = h*256 + d;
        float accS = 0.f;
        #pragma unroll
        for (int j=0;j<3;j++){
            int t = l-2+j;
            if (t>=0) accS += v[(size_t)(n-2+j)*1024 + cidx]*firS[(size_t)cidx*3+j];
        }
        float accL = 0.f;
        #pragma unroll
        for (int j=0;j<31;j++){
            int t = l-30+j;
            if (t>=0) accL += v[(size_t)(n-30+j)*1024 + cidx]*firL[(size_t)cidx*31+j];
        }
        float dv = dlt[(size_t)n*1024 + cidx];
        fs[(size_t)n*1024+cidx]=accS;
        fl[(size_t)n*1024+cidx]=accL;
        float s1 = blockReduceSum(accS, red);
        float s2 = blockReduceSum(accS*accS, red);
        float s3 = blockReduceSum(accL, red);
        float s4 = blockReduceSum(accL*accL, red);
        float s5 = blockReduceSum(dv, red);
        float s6 = blockReduceSum(dv*dv, red);
        if (threadIdx.x==0) {
            float* rp = rin + (size_t)n*1048 + 1024;
            float m1 = s1*(1.f/256.f), m3 = s3*(1.f/256.f), m5 = s5*(1.f/256.f);
            rp[h]    = m1;
            rp[4+h]  = sqrtf(fmaxf(s2*(1.f/256.f) - m1*m1, 0.f));
            rp[8+h]  = m3;
            rp[12+h] = sqrtf(fmaxf(s4*(1.f/256.f) - m3*m3, 0.f));
            rp[16+h] = m5;
            rp[20+h] = sqrtf(fmaxf(s6*(1.f/256.f) - m5*m5, 0.f));
        }
        __syncthreads();
    }
}

// ---------------- router logits + tempered softmax --------------------------
__global__ void __launch_bounds__(256) router_kernel(
    const float* __restrict__ hmid, const float* __restrict__ Wr2,
    const float* __restrict__ br2, const float* __restrict__ ltg,
    float* __restrict__ p)
{
    int n = blockIdx.x;
    __shared__ float hrow[2048];
    __shared__ float lg[12];
    int tid = threadIdx.x;
    for (int i=tid;i<512;i+=256)
        *(float4*)&hrow[i*4] = *(const float4*)(hmid + (size_t)n*2048 + i*4);
    __syncthreads();
    int w = tid>>5, lane = tid&31;
    for (int out = w; out < 12; out += 8) {
        float s=0.f;
        for (int kk=lane; kk<2048; kk+=32) s += hrow[kk]*Wr2[(size_t)kk*12+out];
        #pragma unroll
        for (int o=16;o;o>>=1) s += __shfl_xor_sync(0xffffffffu,s,o);
        if (lane==0) lg[out] = s + br2[out];
    }
    __syncthreads();
    if (tid < 4) {
        int h = tid;
        float tau = expf(ltg[h>>1]);
        float a = lg[h*3+0]/tau, bq = lg[h*3+1]/tau, cq = lg[h*3+2]/tau;
        float m = fmaxf(a, fmaxf(bq,cq));
        float ea=expf(a-m), eb=expf(bq-m), ec=expf(cq-m);
        float inv = 1.f/(ea+eb+ec);
        p[(size_t)n*12 + h*3+0] = ea*inv*0.925f + 0.025f;
        p[(size_t)n*12 + h*3+1] = eb*inv*0.925f + 0.025f;
        p[(size_t)n*12 + h*3+2] = ec*inv*0.925f + 0.025f;
    }
}

// ---------------- gated mix + id path + per-head RMS norm -------------------
__global__ void __launch_bounds__(256) mix_norm_kernel(
    const float* __restrict__ p, const float* __restrict__ fs,
    const float* __restrict__ fl, const float* __restrict__ dlt,
    const float* __restrict__ v, const float* __restrict__ sid,
    const float* __restrict__ alpha_id, const float* __restrict__ onw,
    float* __restrict__ omix)
{
    int n = blockIdx.x;
    int d = threadIdx.x;
    __shared__ float red[8];
    for (int h=0;h<4;h++){
        size_t idx = (size_t)n*1024 + h*256 + d;
        float p0 = p[(size_t)n*12+h*3+0];
        float p1 = p[(size_t)n*12+h*3+1];
        float p2 = p[(size_t)n*12+h*3+2];
        float ids = 0.06f + sigm(alpha_id[h]) * sid[(size_t)n*4+h];
        float o = p0*fs[idx] + p1*fl[idx] + p2*dlt[idx] + ids*v[idx];
        float ss = blockReduceSum(o*o, red);
        float r = rsqrtf(ss*(1.f/256.f) + 1e-5f);
        omix[idx] = o*r*onw[d];
    }
}

extern "C" void kernel_launch(void* const* d_in, const int* in_sizes, int n_in,
                              void* d_out, int out_size) {
    const float* x    = (const float*)d_in[0];
    const float* Wq   = (const float*)d_in[1];
    const float* Wk   = (const float*)d_in[2];
    const float* Wv   = (const float*)d_in[3];
    const float* Wb   = (const float*)d_in[4];
    const float* cq   = (const float*)d_in[5];
    const float* ck   = (const float*)d_in[6];
    const float* cv   = (const float*)d_in[7];
    const float* firS = (const float*)d_in[8];
    const float* firL = (const float*)d_in[9];
    const float* aid  = (const float*)d_in[10];
    const float* Wid  = (const float*)d_in[11];
    const float* bid  = (const float*)d_in[12];
    const float* Wr1  = (const float*)d_in[13];
    const float* br1  = (const float*)d_in[14];
    const float* Wr2  = (const float*)d_in[15];
    const float* br2  = (const float*)d_in[16];
    const float* ltg  = (const float*)d_in[17];
    const float* onw  = (const float*)d_in[19];
    const float* Wo   = (const float*)d_in[20];
    float* out = (float*)d_out;

    void* bufv = nullptr;
    cudaGetSymbolAddress(&bufv, g_buf);
    float* buf = (float*)bufv;
    float* qlin = buf + OFF_QL;
    float* klin = buf + OFF_KL;
    float* vlin = buf + OFF_VL;
    float* qb   = buf + OFF_Q;
    float* kb   = buf + OFF_K;
    float* vb   = buf + OFF_V;
    float* ub   = buf + OFF_U;
    float* wb   = buf + OFF_W;
    float* dlt  = buf + OFF_DELTA;
    float* fsb  = buf + OFF_FS;
    float* flb  = buf + OFF_FL;
    float* omix = buf + OFF_OMIX;
    float* rin  = buf + OFF_RIN;
    float* hmid = buf + OFF_HMID;
    float* attn = buf + OFF_ATTN;
    float* beta = buf + OFF_BETA;
    float* sidb = buf + OFF_SID;
    float* pb   = buf + OFF_P;

    int smem_prep = (3*32*260 + 32*33 + 32) * 4;
    int smem_scan = (8192 + 3*32*260 + 1024 + 1024) * 4;
    cudaFuncSetAttribute(chunk_prep_kernel, cudaFuncAttributeMaxDynamicSharedMemorySize, smem_prep);
    cudaFuncSetAttribute(scan_kernel, cudaFuncAttributeMaxDynamicSharedMemorySize, smem_scan);

    dim3 g1(8, 64), blk(256);
    sgemm_kernel<0><<<g1, blk>>>(x, Wq, nullptr, qlin, NTOK, 1024, 1024);
    sgemm_kernel<0><<<g1, blk>>>(x, Wk, nullptr, klin, NTOK, 1024, 1024);
    sgemm_kernel<0><<<g1, blk>>>(x, Wv, nullptr, vlin, NTOK, 1024, 1024);
    proj_beta_id_kernel<<<NTOK, 256>>>(x, Wb, Wid, bid, beta, sidb);
    conv_silu_kernel<<<NTOK*4, 256>>>(qlin, cq, qb);
    conv_silu_kernel<<<NTOK*4, 256>>>(klin, ck, kb);
    conv_silu_kernel<<<NTOK*4, 256>>>(vlin, cv, vb);
    chunk_prep_kernel<<<1024, 256, smem_prep>>>(qb, kb, vb, beta, ub, wb, attn);
    scan_kernel<<<64, 256, smem_scan>>>(qb, kb, ub, wb, attn, dlt);
    fir_stats_kernel<<<NTOK, 256>>>(vb, dlt, x, firS, firL, fsb, flb, rin);
    dim3 g2(16, 64);
    sgemm_kernel<1><<<g2, blk>>>(rin, Wr1, br1, hmid, NTOK, 2048, 1048);
    router_kernel<<<NTOK, 256>>>(hmid, Wr2, br2, ltg, pb);
    mix_norm_kernel<<<NTOK, 256>>>(pb, fsb, flb, dlt, vb, sidb, aid, onw, omix);
    sgemm_kernel<0><<<g1, blk>>>(omix, Wo, nullptr, out, NTOK, 1024, 1024);
}

// round 3
// speedup vs baseline: 1.3679x; 1.3679x over previous
#include <cuda_runtime.h>
#include <cuda_bf16.h>
#include <math.h>

#define LSEQ 4096
#define NTOK 8192

// ---------------- scratch offsets (floats) ----------------
#define OFF_QL    ((size_t)0)
#define OFF_KL    ((size_t)8388608)
#define OFF_VL    ((size_t)16777216)
#define OFF_Q     ((size_t)25165824)
#define OFF_K     ((size_t)33554432)
#define OFF_V     ((size_t)41943040)
#define OFF_U     ((size_t)50331648)
#define OFF_W     ((size_t)58720256)
#define OFF_DELTA ((size_t)67108864)
#define OFF_FS    ((size_t)75497472)
#define OFF_FL    ((size_t)83886080)
#define OFF_OMIX  ((size_t)92274688)
#define OFF_RIN   ((size_t)100663296)   // 8192 x 1056
#define OFF_HMID  ((size_t)109314048)   // 8192 x 2048
#define OFF_ATTN  ((size_t)126091264)   // 1024 x 1024
#define OFF_BETA  ((size_t)127139840)
#define OFF_SID   ((size_t)127172608)
#define OFF_P     ((size_t)127205376)
#define OFF_W1P   ((size_t)127303680)   // 1056 x 2048
#define BUF_TOTAL ((size_t)129466368)

__device__ float g_buf[BUF_TOTAL];

__device__ __forceinline__ float sigm(float x){ return 1.0f/(1.0f+expf(-x)); }

__device__ __forceinline__ unsigned short f2bf(float f){
    __nv_bfloat16 h = __float2bfloat16(f);
    return *(unsigned short*)&h;
}
__device__ __forceinline__ float bf2f(unsigned short u){
    __nv_bfloat16 h = *(__nv_bfloat16*)&u;
    return __bfloat162float(h);
}

__device__ __forceinline__ float blockReduceSum(float val, float* red) {
    int lane = threadIdx.x & 31, w = threadIdx.x >> 5;
    #pragma unroll
    for (int o=16;o;o>>=1) val += __shfl_xor_sync(0xffffffffu, val, o);
    if (lane==0) red[w]=val;
    __syncthreads();
    if (w==0) {
        float v2 = (lane<8)? red[lane] : 0.f;
        #pragma unroll
        for (int o=4;o;o>>=1) v2 += __shfl_xor_sync(0xffffffffu, v2, o);
        if (lane==0) red[0]=v2;
    }
    __syncthreads();
    float r = red[0];
    __syncthreads();
    return r;
}

#define LDSM_X4(R0,R1,R2,R3,ADDR) \
    asm volatile("ldmatrix.sync.aligned.m8n8.x4.shared.b16 {%0,%1,%2,%3}, [%4];" \
        : "=r"(R0),"=r"(R1),"=r"(R2),"=r"(R3) : "r"(ADDR))
#define LDSM_X4T(R0,R1,R2,R3,ADDR) \
    asm volatile("ldmatrix.sync.aligned.m8n8.x4.trans.shared.b16 {%0,%1,%2,%3}, [%4];" \
        : "=r"(R0),"=r"(R1),"=r"(R2),"=r"(R3) : "r"(ADDR))
#define MMA_BF16(C,A0,A1,A2,A3,B0,B1) \
    asm volatile("mma.sync.aligned.m16n8k16.row.col.f32.bf16.bf16.f32 " \
        "{%0,%1,%2,%3},{%4,%5,%6,%7},{%8,%9},{%0,%1,%2,%3};" \
        : "+f"(C[0]),"+f"(C[1]),"+f"(C[2]),"+f"(C[3]) \
        : "r"(A0),"r"(A1),"r"(A2),"r"(A3),"r"(B0),"r"(B1))

// ---------------- tensor-core GEMM, split-bf16 (3 MMA), 128x128x32 tiles ----
// EPI: 0 = none, 1 = bias + exact gelu
template<int EPI>
__global__ void __launch_bounds__(256) tgemm_kernel(
    const float* __restrict__ A, const float* __restrict__ B,
    const float* __restrict__ bias, float* __restrict__ C,
    int M, int N, int K)
{
    __shared__ unsigned short Ah[128][40];
    __shared__ unsigned short Al[128][40];
    __shared__ unsigned short Bh[32][136];
    __shared__ unsigned short Bl[32][136];

    const int tid  = threadIdx.x;
    const int lane = tid & 31;
    const int warp = tid >> 5;
    const int warp_m = warp & 3;       // 4 warps over 128 rows (32 each)
    const int warp_n = warp >> 2;      // 2 warps over 128 cols (64 each)
    const int brow = blockIdx.y * 128;
    const int bcol = blockIdx.x * 128;

    float c[2][8][4];
    #pragma unroll
    for (int i=0;i<2;i++)
        #pragma unroll
        for (int j=0;j<8;j++)
            #pragma unroll
            for (int t=0;t<4;t++) c[i][j][t]=0.f;

    const unsigned sAh = (unsigned)__cvta_generic_to_shared(&Ah[0][0]);
    const unsigned sAl = (unsigned)__cvta_generic_to_shared(&Al[0][0]);
    const unsigned sBh = (unsigned)__cvta_generic_to_shared(&Bh[0][0]);
    const unsigned sBl = (unsigned)__cvta_generic_to_shared(&Bl[0][0]);

    // tile-fill indices
    const int a_row = tid >> 1;              // 0..127
    const int a_col = (tid & 1) * 16;        // 0 or 16
    const int b_row = tid >> 3;              // 0..31
    const int b_col = (tid & 7) * 16;        // 0..112

    const float* Ag = A + (size_t)(brow + a_row) * K + a_col;
    const float* Bg = B + (size_t)b_row * N + bcol + b_col;

    for (int kt = 0; kt < K; kt += 32) {
        // ---- fill A tile (hi/lo bf16) ----
        #pragma unroll
        for (int c4 = 0; c4 < 4; c4++) {
            float4 v = *(const float4*)(Ag + kt + c4*4);
            int col = a_col + c4*4;
            unsigned short h0=f2bf(v.x), h1=f2bf(v.y), h2=f2bf(v.z), h3=f2bf(v.w);
            unsigned short l0=f2bf(v.x-bf2f(h0)), l1=f2bf(v.y-bf2f(h1));
            unsigned short l2=f2bf(v.z-bf2f(h2)), l3=f2bf(v.w-bf2f(h3));
            *(unsigned*)&Ah[a_row][col]   = (unsigned)h0 | ((unsigned)h1<<16);
            *(unsigned*)&Ah[a_row][col+2] = (unsigned)h2 | ((unsigned)h3<<16);
            *(unsigned*)&Al[a_row][col]   = (unsigned)l0 | ((unsigned)l1<<16);
            *(unsigned*)&Al[a_row][col+2] = (unsigned)l2 | ((unsigned)l3<<16);
        }
        // ---- fill B tile ----
        #pragma unroll
        for (int c4 = 0; c4 < 4; c4++) {
            float4 v = *(const float4*)(Bg + (size_t)kt * N + c4*4);
            int col = b_col + c4*4;
            unsigned short h0=f2bf(v.x), h1=f2bf(v.y), h2=f2bf(v.z), h3=f2bf(v.w);
            unsigned short l0=f2bf(v.x-bf2f(h0)), l1=f2bf(v.y-bf2f(h1));
            unsigned short l2=f2bf(v.z-bf2f(h2)), l3=f2bf(v.w-bf2f(h3));
            *(unsigned*)&Bh[b_row][col]   = (unsigned)h0 | ((unsigned)h1<<16);
            *(unsigned*)&Bh[b_row][col+2] = (unsigned)h2 | ((unsigned)h3<<16);
            *(unsigned*)&Bl[b_row][col]   = (unsigned)l0 | ((unsigned)l1<<16);
            *(unsigned*)&Bl[b_row][col+2] = (unsigned)l2 | ((unsigned)l3<<16);
        }
        __syncthreads();

        #pragma unroll
        for (int ks = 0; ks < 2; ks++) {
            unsigned ah[2][4], al[2][4], bh[4][4], bl[4][4];
            #pragma unroll
            for (int mt = 0; mt < 2; mt++) {
                int ar = warp_m*32 + mt*16 + (lane & 15);
                int ac = ((lane >> 4) << 3) + ks*16;
                unsigned off = (unsigned)(ar*40 + ac)*2u;
                LDSM_X4(ah[mt][0],ah[mt][1],ah[mt][2],ah[mt][3], sAh + off);
                LDSM_X4(al[mt][0],al[mt][1],al[mt][2],al[mt][3], sAl + off);
            }
            #pragma unroll
            for (int np = 0; np < 4; np++) {
                int bk = (lane & 7) + (((lane >> 3) & 1) << 3) + ks*16;
                int bn = warp_n*64 + np*16 + ((lane >> 4) << 3);
                unsigned off = (unsigned)(bk*136 + bn)*2u;
                LDSM_X4T(bh[np][0],bh[np][1],bh[np][2],bh[np][3], sBh + off);
                LDSM_X4T(bl[np][0],bl[np][1],bl[np][2],bl[np][3], sBl + off);
            }
            #pragma unroll
            for (int mt = 0; mt < 2; mt++) {
                #pragma unroll
                for (int j = 0; j < 8; j++) {
                    int np = j >> 1, o = (j & 1) * 2;
                    MMA_BF16(c[mt][j], ah[mt][0],ah[mt][1],ah[mt][2],ah[mt][3],
                             bh[np][o], bh[np][o+1]);
                    MMA_BF16(c[mt][j], ah[mt][0],ah[mt][1],ah[mt][2],ah[mt][3],
                             bl[np][o], bl[np][o+1]);
                    MMA_BF16(c[mt][j], al[mt][0],al[mt][1],al[mt][2],al[mt][3],
                             bh[np][o], bh[np][o+1]);
                }
            }
        }
        __syncthreads();
    }

    // ---- epilogue ----
    #pragma unroll
    for (int mt = 0; mt < 2; mt++) {
        int r0 = brow + warp_m*32 + mt*16 + (lane >> 2);
        #pragma unroll
        for (int j = 0; j < 8; j++) {
            int col = bcol + warp_n*64 + j*8 + (lane & 3)*2;
            float2 v0 = make_float2(c[mt][j][0], c[mt][j][1]);
            float2 v1 = make_float2(c[mt][j][2], c[mt][j][3]);
            if (EPI == 1) {
                float b0 = bias[col], b1 = bias[col+1];
                v0.x += b0; v0.y += b1; v1.x += b0; v1.y += b1;
                v0.x = 0.5f*v0.x*(1.0f+erff(v0.x*0.70710678118654752f));
                v0.y = 0.5f*v0.y*(1.0f+erff(v0.y*0.70710678118654752f));
                v1.x = 0.5f*v1.x*(1.0f+erff(v1.x*0.70710678118654752f));
                v1.y = 0.5f*v1.y*(1.0f+erff(v1.y*0.70710678118654752f));
            }
            *(float2*)&C[(size_t)r0*N + col]     = v0;
            *(float2*)&C[(size_t)(r0+8)*N + col] = v1;
        }
    }
}

// ---------------- pad Wr1 [1048][2048] -> [1056][2048] ----------------
__global__ void __launch_bounds__(256) pad_w1_kernel(
    const float* __restrict__ Wr1, float* __restrict__ W1p)
{
    int idx = blockIdx.x*256 + threadIdx.x;   // float4 index
    if (idx >= 1056*512) return;
    int row = idx / 512;
    float4 v = make_float4(0.f,0.f,0.f,0.f);
    if (row < 1048) v = *(const float4*)(Wr1 + (size_t)idx*4);
    *(float4*)(W1p + (size_t)idx*4) = v;
}

// ---------------- beta + id-gate projections ----------------
__global__ void __launch_bounds__(256) proj_beta_id_kernel(
    const float* __restrict__ x, const float* __restrict__ Wb,
    const float* __restrict__ Wid, const float* __restrict__ bid,
    float* __restrict__ beta, float* __restrict__ sid)
{
    int n = blockIdx.x;
    __shared__ float xs[1024];
    int tid = threadIdx.x;
    *(float4*)&xs[tid*4] = *(const float4*)(x + (size_t)n*1024 + tid*4);
    __syncthreads();
    int w = tid >> 5, lane = tid & 31;
    float s = 0.f;
    if (w < 4) { for (int d=lane; d<1024; d+=32) s += xs[d]*Wb[(size_t)d*4 + w]; }
    else       { int h=w-4; for (int d=lane; d<1024; d+=32) s += xs[d]*Wid[(size_t)d*4 + h]; }
    #pragma unroll
    for (int o=16;o;o>>=1) s += __shfl_xor_sync(0xffffffffu,s,o);
    if (lane==0) {
        if (w<4) beta[(size_t)n*4+w] = sigm(s);
        else     sid[(size_t)n*4+(w-4)] = sigm(s + bid[w-4]);
    }
}

// ---------------- causal depthwise conv (k=4) + silu ----------------
__global__ void __launch_bounds__(256) conv_silu_kernel(
    const float* __restrict__ in, const float* __restrict__ cw, float* __restrict__ out)
{
    int idx = blockIdx.x*256 + threadIdx.x;
    int c = idx & 1023;
    int n = idx >> 10;
    int l = n & (LSEQ-1);
    float4 wv = *(const float4*)(cw + (size_t)c*4);
    float wj[4] = {wv.x, wv.y, wv.z, wv.w};
    float acc = 0.f;
    #pragma unroll
    for (int j=0;j<4;j++){
        int t = l - 3 + j;
        if (t >= 0) acc += in[(size_t)(n-3+j)*1024 + c] * wj[j];
    }
    out[idx] = acc / (1.0f + expf(-acc));
}

// ---------------- per-chunk prep: l2norm, T, u, w, attn ----------------
__global__ void __launch_bounds__(256) chunk_prep_kernel(
    float* __restrict__ q, float* __restrict__ k, const float* __restrict__ v,
    const float* __restrict__ beta, float* __restrict__ u, float* __restrict__ w,
    float* __restrict__ attn)
{
    extern __shared__ float sh[];
    float* qs = sh;
    float* ks = qs + 32*260;
    float* vs = ks + 32*260;
    float* T  = vs + 32*260;
    float* bet = T + 32*33;
    int ci = blockIdx.x;
    int c = ci & 127;
    int h = (ci >> 7) & 3;
    int b = ci >> 9;
    int tid = threadIdx.x;
    size_t base = ((size_t)(b*LSEQ + c*32))*1024 + (size_t)h*256;
    for (int i=tid; i<2048; i+=256) {
        int r = i>>6; int d4 = (i&63)<<2;
        size_t off = base + (size_t)r*1024 + d4;
        *(float4*)&qs[r*260+d4] = *(const float4*)(q + off);
        *(float4*)&ks[r*260+d4] = *(const float4*)(k + off);
        *(float4*)&vs[r*260+d4] = *(const float4*)(v + off);
    }
    if (tid < 32) bet[tid] = beta[(size_t)(b*LSEQ + c*32 + tid)*4 + h];
    __syncthreads();
    {
        int wi = tid>>5, lane = tid&31;
        for (int r = wi*4; r < wi*4+4; r++) {
            float sq=0.f, sk2=0.f;
            for (int dd=lane; dd<256; dd+=32){
                float a=qs[r*260+dd]; sq+=a*a;
                float bb=ks[r*260+dd]; sk2+=bb*bb;
            }
            #pragma unroll
            for (int o=16;o;o>>=1){
                sq+=__shfl_xor_sync(0xffffffffu,sq,o);
                sk2+=__shfl_xor_sync(0xffffffffu,sk2,o);
            }
            float rq = rsqrtf(sq+1e-6f), rk = rsqrtf(sk2+1e-6f);
            for (int dd=lane; dd<256; dd+=32){ qs[r*260+dd]*=rq; ks[r*260+dd]*=rk; }
        }
    }
    __syncthreads();
    size_t abase = (size_t)ci*1024;
    for (int pp=tid; pp<1024; pp+=256) {
        int i = pp>>5, j = pp&31;
        float dkk=0.f, dqq=0.f;
        for (int dd=0; dd<256; dd++){
            float kj = ks[j*260+dd];
            dkk += ks[i*260+dd]*kj;
            dqq += qs[i*260+dd]*kj;
        }
        T[i*33+j] = (j<i)? (-bet[i]*dkk) : 0.f;
        attn[abase+pp] = (j<=i)? dqq : 0.f;
    }
    __syncthreads();
    if (tid<32) {
        int lane = tid;
        for (int i=1;i<32;i++){
            float rowv = T[i*33+lane];
            float add = 0.f;
            for (int j=0;j<i;j++) add += __shfl_sync(0xffffffffu, rowv, j)*T[j*33+lane];
            T[i*33+lane] = rowv + add;
            __syncwarp();
        }
        T[lane*33+lane] += 1.0f;
    }
    __syncthreads();
    for (int pp=tid; pp<8192; pp+=256){
        int r = pp>>8, dd = pp&255;
        float su=0.f, sw=0.f;
        #pragma unroll
        for (int j=0;j<32;j++){
            float tj = T[r*33+j]*bet[j];
            su += tj*vs[j*260+dd];
            sw += tj*ks[j*260+dd];
        }
        size_t off = base + (size_t)r*1024 + dd;
        u[off]=su; w[off]=sw;
        q[off]=qs[r*260+dd]; k[off]=ks[r*260+dd];
    }
}

// ---------------- sequential chunk scan, dv-sliced (8 slices of 32) --------
__global__ void __launch_bounds__(256) scan_kernel(
    const float* __restrict__ q, const float* __restrict__ k,
    const float* __restrict__ u, const float* __restrict__ w,
    const float* __restrict__ attn, float* __restrict__ outp)
{
    extern __shared__ float sh[];
    float* S  = sh;
    float* qs = S + 8192;
    float* ks = qs + 32*260;
    float* ws = ks + 32*260;
    float* as = ws + 32*260;
    float* u2 = as + 1024;
    int bid = blockIdx.x;
    int sl = bid & 7;
    int bh = bid >> 3;
    int h = bh & 3, b = bh >> 2;
    int tid = threadIdx.x;
    for (int i=tid;i<8192;i+=256) S[i]=0.f;
    int iRow = tid >> 3;
    int q4 = (tid & 7) << 2;
    size_t abh = (size_t)bh * 128 * 1024;
    for (int c=0;c<128;c++){
        size_t base = ((size_t)(b*LSEQ + c*32))*1024 + (size_t)h*256;
        __syncthreads();
        for (int i=tid;i<2048;i+=256){
            int r=i>>6; int d4=(i&63)<<2;
            size_t off = base + (size_t)r*1024 + d4;
            *(float4*)&qs[r*260+d4] = *(const float4*)(q+off);
            *(float4*)&ks[r*260+d4] = *(const float4*)(k+off);
            *(float4*)&ws[r*260+d4] = *(const float4*)(w+off);
        }
        *(float4*)&as[tid*4] = *(const float4*)(attn + abh + (size_t)c*1024 + tid*4);
        __syncthreads();
        float4 au = *(const float4*)(u + base + (size_t)iRow*1024 + sl*32 + q4);
        float4 ao = make_float4(0.f,0.f,0.f,0.f);
        #pragma unroll 4
        for (int dd=0; dd<256; dd++){
            float wv = ws[iRow*260+dd];
            float qv = qs[iRow*260+dd];
            float4 Sv = *(float4*)&S[dd*32+q4];
            au.x -= wv*Sv.x; au.y -= wv*Sv.y; au.z -= wv*Sv.z; au.w -= wv*Sv.w;
            ao.x += qv*Sv.x; ao.y += qv*Sv.y; ao.z += qv*Sv.z; ao.w += qv*Sv.w;
        }
        *(float4*)&u2[iRow*32+q4] = au;
        __syncthreads();
        #pragma unroll 8
        for (int j=0;j<32;j++){
            float av = as[iRow*32+j];
            float4 uv = *(float4*)&u2[j*32+q4];
            ao.x += av*uv.x; ao.y += av*uv.y; ao.z += av*uv.z; ao.w += av*uv.w;
        }
        *(float4*)(outp + base + (size_t)iRow*1024 + sl*32 + q4) = ao;
        #pragma unroll
        for (int s2=0; s2<8; s2++){
            int t2 = tid + s2*256;
            int dd = t2>>3; int qq = (t2&7)<<2;
            float4 Sv = *(float4*)&S[dd*32+qq];
            #pragma unroll 8
            for (int j=0;j<32;j++){
                float kv = ks[j*260+dd];
                float4 uv = *(float4*)&u2[j*32+qq];
                Sv.x += kv*uv.x; Sv.y += kv*uv.y; Sv.z += kv*uv.z; Sv.w += kv*uv.w;
            }
            *(float4*)&S[dd*32+qq] = Sv;
        }
    }
}

// ---------------- FIR short/long + stats + router input --------------------
__global__ void __launch_bounds__(256) fir_stats_kernel(
    const float* __restrict__ v, const float* __restrict__ dlt,
    const float* __restrict__ x, const float* __restrict__ firS,
    const float* __restrict__ firL,
    float* __restrict__ fs, float* __restrict__ fl, float* __restrict__ rin)
{
    int n = blockIdx.x;
    int l = n & (LSEQ-1);
    int d = threadIdx.x;
    __shared__ float red[8];
    {
        const float4* xs = (const float4*)(x + (size_t)n*1024);
        float4* rp = (float4*)(rin + (size_t)n*1056);
        rp[d] = xs[d];
    }
    if (d < 8) rin[(size_t)n*1056 + 1048 + d] = 0.f;
    for (int h=0; h<4; h++) {
        int cidx = h*256 + d;
        float accS = 0.f;
        #pragma unroll
        for (int j=0;j<3;j++){
            int t = l-2+j;
            if (t>=0) accS += v[(size_t)(n-2+j)*1024 + cidx]*firS[(size_t)cidx*3+j];
        }
        float accL = 0.f;
        #pragma unroll
        for (int j=0;j<31;j++){
            int t = l-30+j;
            if (t>=0) accL += v[(size_t)(n-30+j)*1024 + cidx]*firL[(size_t)cidx*31+j];
        }
        float dv = dlt[(size_t)n*1024 + cidx];
        fs[(size_t)n*1024+cidx]=accS;
        fl[(size_t)n*1024+cidx]=accL;
        float s1 = blockReduceSum(accS, red);
        float s2 = blockReduceSum(accS*accS, red);
        float s3 = blockReduceSum(accL, red);
        float s4 = blockReduceSum(accL*accL, red);
        float s5 = blockReduceSum(dv, red);
        float s6 = blockReduceSum(dv*dv, red);
        if (threadIdx.x==0) {
            float* rp = rin + (size_t)n*1056 + 1024;
            float m1 = s1*(1.f/256.f), m3 = s3*(1.f/256.f), m5 = s5*(1.f/256.f);
            rp[h]    = m1;
            rp[4+h]  = sqrtf(fmaxf(s2*(1.f/256.f) - m1*m1, 0.f));
            rp[8+h]  = m3;
            rp[12+h] = sqrtf(fmaxf(s4*(1.f/256.f) - m3*m3, 0.f));
            rp[16+h] = m5;
            rp[20+h] = sqrtf(fmaxf(s6*(1.f/256.f) - m5*m5, 0.f));
        }
        __syncthreads();
    }
}

// ---------------- router logits + tempered softmax --------------------------
__global__ void __launch_bounds__(256) router_kernel(
    const float* __restrict__ hmid, const float* __restrict__ Wr2,
    const float* __restrict__ br2, const float* __restrict__ ltg,
    float* __restrict__ p)
{
    int n = blockIdx.x;
    __shared__ float hrow[2048];
    __shared__ float lg[12];
    int tid = threadIdx.x;
    for (int i=tid;i<512;i+=256)
        *(float4*)&hrow[i*4] = *(const float4*)(hmid + (size_t)n*2048 + i*4);
    __syncthreads();
    int w = tid>>5, lane = tid&31;
    for (int out = w; out < 12; out += 8) {
        float s=0.f;
        for (int kk=lane; kk<2048; kk+=32) s += hrow[kk]*Wr2[(size_t)kk*12+out];
        #pragma unroll
        for (int o=16;o;o>>=1) s += __shfl_xor_sync(0xffffffffu,s,o);
        if (lane==0) lg[out] = s + br2[out];
    }
    __syncthreads();
    if (tid < 4) {
        int h = tid;
        float tau = expf(ltg[h>>1]);
        float a = lg[h*3+0]/tau, bq = lg[h*3+1]/tau, cq = lg[h*3+2]/tau;
        float m = fmaxf(a, fmaxf(bq,cq));
        float ea=expf(a-m), eb=expf(bq-m), ec=expf(cq-m);
        float inv = 1.f/(ea+eb+ec);
        p[(size_t)n*12 + h*3+0] = ea*inv*0.925f + 0.025f;
        p[(size_t)n*12 + h*3+1] = eb*inv*0.925f + 0.025f;
        p[(size_t)n*12 + h*3+2] = ec*inv*0.925f + 0.025f;
    }
}

// ---------------- gated mix + id path + per-head RMS norm -------------------
__global__ void __launch_bounds__(256) mix_norm_kernel(
    const float* __restrict__ p, const float* __restrict__ fs,
    const float* __restrict__ fl, const float* __restrict__ dlt,
    const float* __restrict__ v, const float* __restrict__ sid,
    const float* __restrict__ alpha_id, const float* __restrict__ onw,
    float* __restrict__ omix)
{
    int n = blockIdx.x;
    int d = threadIdx.x;
    __shared__ float red[8];
    for (int h=0;h<4;h++){
        size_t idx = (size_t)n*1024 + h*256 + d;
        float p0 = p[(size_t)n*12+h*3+0];
        float p1 = p[(size_t)n*12+h*3+1];
        float p2 = p[(size_t)n*12+h*3+2];
        float ids = 0.06f + sigm(alpha_id[h]) * sid[(size_t)n*4+h];
        float o = p0*fs[idx] + p1*fl[idx] + p2*dlt[idx] + ids*v[idx];
        float ss = blockReduceSum(o*o, red);
        float r = rsqrtf(ss*(1.f/256.f) + 1e-5f);
        omix[idx] = o*r*onw[d];
    }
}

extern "C" void kernel_launch(void* const* d_in, const int* in_sizes, int n_in,
                              void* d_out, int out_size) {
    const float* x    = (const float*)d_in[0];
    const float* Wq   = (const float*)d_in[1];
    const float* Wk   = (const float*)d_in[2];
    const float* Wv   = (const float*)d_in[3];
    const float* Wb   = (const float*)d_in[4];
    const float* cq   = (const float*)d_in[5];
    const float* ck   = (const float*)d_in[6];
    const float* cv   = (const float*)d_in[7];
    const float* firS = (const float*)d_in[8];
    const float* firL = (const float*)d_in[9];
    const float* aid  = (const float*)d_in[10];
    const float* Wid  = (const float*)d_in[11];
    const float* bid  = (const float*)d_in[12];
    const float* Wr1  = (const float*)d_in[13];
    const float* br1  = (const float*)d_in[14];
    const float* Wr2  = (const float*)d_in[15];
    const float* br2  = (const float*)d_in[16];
    const float* ltg  = (const float*)d_in[17];
    const float* onw  = (const float*)d_in[19];
    const float* Wo   = (const float*)d_in[20];
    float* out = (float*)d_out;

    void* bufv = nullptr;
    cudaGetSymbolAddress(&bufv, g_buf);
    float* buf = (float*)bufv;
    float* qlin = buf + OFF_QL;
    float* klin = buf + OFF_KL;
    float* vlin = buf + OFF_VL;
    float* qb   = buf + OFF_Q;
    float* kb   = buf + OFF_K;
    float* vb   = buf + OFF_V;
    float* ub   = buf + OFF_U;
    float* wb   = buf + OFF_W;
    float* dlt  = buf + OFF_DELTA;
    float* fsb  = buf + OFF_FS;
    float* flb  = buf + OFF_FL;
    float* omix = buf + OFF_OMIX;
    float* rin  = buf + OFF_RIN;
    float* hmid = buf + OFF_HMID;
    float* attn = buf + OFF_ATTN;
    float* beta = buf + OFF_BETA;
    float* sidb = buf + OFF_SID;
    float* pb   = buf + OFF_P;
    float* w1p  = buf + OFF_W1P;

    int smem_prep = (3*32*260 + 32*33 + 32) * 4;
    int smem_scan = (8192 + 3*32*260 + 1024 + 1024) * 4;
    cudaFuncSetAttribute(chunk_prep_kernel, cudaFuncAttributeMaxDynamicSharedMemorySize, smem_prep);
    cudaFuncSetAttribute(scan_kernel, cudaFuncAttributeMaxDynamicSharedMemorySize, smem_scan);

    dim3 blk(256);
    dim3 g1(8, 64);
    pad_w1_kernel<<<(1056*512 + 255)/256, blk>>>(Wr1, w1p);
    tgemm_kernel<0><<<g1, blk>>>(x, Wq, nullptr, qlin, NTOK, 1024, 1024);
    tgemm_kernel<0><<<g1, blk>>>(x, Wk, nullptr, klin, NTOK, 1024, 1024);
    tgemm_kernel<0><<<g1, blk>>>(x, Wv, nullptr, vlin, NTOK, 1024, 1024);
    proj_beta_id_kernel<<<NTOK, 256>>>(x, Wb, Wid, bid, beta, sidb);
    conv_silu_kernel<<<NTOK*4, 256>>>(qlin, cq, qb);
    conv_silu_kernel<<<NTOK*4, 256>>>(klin, ck, kb);
    conv_silu_kernel<<<NTOK*4, 256>>>(vlin, cv, vb);
    chunk_prep_kernel<<<1024, 256, smem_prep>>>(qb, kb, vb, beta, ub, wb, attn);
    scan_kernel<<<64, 256, smem_scan>>>(qb, kb, ub, wb, attn, dlt);
    fir_stats_kernel<<<NTOK, 256>>>(vb, dlt, x, firS, firL, fsb, flb, rin);
    dim3 g2(16, 64);
    tgemm_kernel<1><<<g2, blk>>>(rin, w1p, br1, hmid, NTOK, 2048, 1056);
    router_kernel<<<NTOK, 256>>>(hmid, Wr2, br2, ltg, pb);
    mix_norm_kernel<<<NTOK, 256>>>(pb, fsb, flb, dlt, vb, sidb, aid, onw, omix);
    tgemm_kernel<0><<<g1, blk>>>(omix, Wo, nullptr, out, NTOK, 1024, 1024);
}

// round 4
// speedup vs baseline: 1.5411x; 1.1266x over previous
#include <cuda_runtime.h>
#include <cuda_bf16.h>
#include <math.h>

#define LSEQ 4096
#define NTOK 8192

// ---------------- scratch offsets (floats) ----------------
#define OFF_QL    ((size_t)0)
#define OFF_KL    ((size_t)8388608)
#define OFF_VL    ((size_t)16777216)
#define OFF_Q     ((size_t)25165824)
#define OFF_K     ((size_t)33554432)
#define OFF_V     ((size_t)41943040)
#define OFF_U     ((size_t)50331648)
#define OFF_W     ((size_t)58720256)
#define OFF_DELTA ((size_t)67108864)
#define OFF_FS    ((size_t)75497472)
#define OFF_FL    ((size_t)83886080)
#define OFF_OMIX  ((size_t)92274688)
#define OFF_RIN   ((size_t)100663296)   // 8192 x 1056
#define OFF_HMID  ((size_t)109314048)   // 8192 x 2048
#define OFF_ATTN  ((size_t)126091264)   // 1024 x 1024
#define OFF_BETA  ((size_t)127139840)
#define OFF_SID   ((size_t)127172608)
#define OFF_P     ((size_t)127205376)
#define OFF_W1P   ((size_t)127303680)   // 1056 x 2048
#define BUF_TOTAL ((size_t)129466368)

__device__ float g_buf[BUF_TOTAL];

__device__ __forceinline__ float sigm(float x){ return 1.0f/(1.0f+expf(-x)); }

__device__ __forceinline__ unsigned short f2bf(float f){
    __nv_bfloat16 h = __float2bfloat16(f);
    return *(unsigned short*)&h;
}
__device__ __forceinline__ float bf2f(unsigned short u){
    __nv_bfloat16 h = *(__nv_bfloat16*)&u;
    return __bfloat162float(h);
}

__device__ __forceinline__ float blockReduceSum(float val, float* red) {
    int lane = threadIdx.x & 31, w = threadIdx.x >> 5;
    #pragma unroll
    for (int o=16;o;o>>=1) val += __shfl_xor_sync(0xffffffffu, val, o);
    if (lane==0) red[w]=val;
    __syncthreads();
    if (w==0) {
        float v2 = (lane<8)? red[lane] : 0.f;
        #pragma unroll
        for (int o=4;o;o>>=1) v2 += __shfl_xor_sync(0xffffffffu, v2, o);
        if (lane==0) red[0]=v2;
    }
    __syncthreads();
    float r = red[0];
    __syncthreads();
    return r;
}

#define LDSM_X4(R0,R1,R2,R3,ADDR) \
    asm volatile("ldmatrix.sync.aligned.m8n8.x4.shared.b16 {%0,%1,%2,%3}, [%4];" \
        : "=r"(R0),"=r"(R1),"=r"(R2),"=r"(R3) : "r"(ADDR))
#define LDSM_X4T(R0,R1,R2,R3,ADDR) \
    asm volatile("ldmatrix.sync.aligned.m8n8.x4.trans.shared.b16 {%0,%1,%2,%3}, [%4];" \
        : "=r"(R0),"=r"(R1),"=r"(R2),"=r"(R3) : "r"(ADDR))
#define MMA_BF16(C,A0,A1,A2,A3,B0,B1) \
    asm volatile("mma.sync.aligned.m16n8k16.row.col.f32.bf16.bf16.f32 " \
        "{%0,%1,%2,%3},{%4,%5,%6,%7},{%8,%9},{%0,%1,%2,%3};" \
        : "+f"(C[0]),"+f"(C[1]),"+f"(C[2]),"+f"(C[3]) \
        : "r"(A0),"r"(A1),"r"(A2),"r"(A3),"r"(B0),"r"(B1))

// ---------------- tensor-core GEMM, split-bf16 (3 MMA), 128x128x32 tiles ----
// 512 threads, 16 warps each computing 32x32. EPI: 0=none, 1=bias+gelu(exact)
template<int EPI>
__global__ void __launch_bounds__(512) tgemm_kernel(
    const float* __restrict__ A, const float* __restrict__ B,
    const float* __restrict__ bias, float* __restrict__ C,
    int M, int N, int K)
{
    __shared__ unsigned short Ah[128][40];
    __shared__ unsigned short Al[128][40];
    __shared__ unsigned short Bh[32][136];
    __shared__ unsigned short Bl[32][136];

    const int tid  = threadIdx.x;
    const int lane = tid & 31;
    const int warp = tid >> 5;
    const int warp_m = warp & 3;       // 4 warps over 128 rows (32 each)
    const int warp_n = warp >> 2;      // 4 warps over 128 cols (32 each)
    const int brow = blockIdx.y * 128;
    const int bcol = blockIdx.x * 128;

    float c[2][4][4];
    #pragma unroll
    for (int i=0;i<2;i++)
        #pragma unroll
        for (int j=0;j<4;j++)
            #pragma unroll
            for (int t=0;t<4;t++) c[i][j][t]=0.f;

    const unsigned sAh = (unsigned)__cvta_generic_to_shared(&Ah[0][0]);
    const unsigned sAl = (unsigned)__cvta_generic_to_shared(&Al[0][0]);
    const unsigned sBh = (unsigned)__cvta_generic_to_shared(&Bh[0][0]);
    const unsigned sBl = (unsigned)__cvta_generic_to_shared(&Bl[0][0]);

    const int a_row = tid >> 2;              // 0..127
    const int a_col = (tid & 3) * 8;         // 0,8,16,24
    const int b_row = tid >> 4;              // 0..31
    const int b_col = (tid & 15) * 8;        // 0..120

    const float* Ag = A + (size_t)(brow + a_row) * K + a_col;
    const float* Bg = B + (size_t)b_row * N + bcol + b_col;

    for (int kt = 0; kt < K; kt += 32) {
        #pragma unroll
        for (int c4 = 0; c4 < 2; c4++) {
            float4 v = *(const float4*)(Ag + kt + c4*4);
            int col = a_col + c4*4;
            unsigned short h0=f2bf(v.x), h1=f2bf(v.y), h2=f2bf(v.z), h3=f2bf(v.w);
            unsigned short l0=f2bf(v.x-bf2f(h0)), l1=f2bf(v.y-bf2f(h1));
            unsigned short l2=f2bf(v.z-bf2f(h2)), l3=f2bf(v.w-bf2f(h3));
            *(unsigned*)&Ah[a_row][col]   = (unsigned)h0 | ((unsigned)h1<<16);
            *(unsigned*)&Ah[a_row][col+2] = (unsigned)h2 | ((unsigned)h3<<16);
            *(unsigned*)&Al[a_row][col]   = (unsigned)l0 | ((unsigned)l1<<16);
            *(unsigned*)&Al[a_row][col+2] = (unsigned)l2 | ((unsigned)l3<<16);
        }
        #pragma unroll
        for (int c4 = 0; c4 < 2; c4++) {
            float4 v = *(const float4*)(Bg + (size_t)kt * N + c4*4);
            int col = b_col + c4*4;
            unsigned short h0=f2bf(v.x), h1=f2bf(v.y), h2=f2bf(v.z), h3=f2bf(v.w);
            unsigned short l0=f2bf(v.x-bf2f(h0)), l1=f2bf(v.y-bf2f(h1));
            unsigned short l2=f2bf(v.z-bf2f(h2)), l3=f2bf(v.w-bf2f(h3));
            *(unsigned*)&Bh[b_row][col]   = (unsigned)h0 | ((unsigned)h1<<16);
            *(unsigned*)&Bh[b_row][col+2] = (unsigned)h2 | ((unsigned)h3<<16);
            *(unsigned*)&Bl[b_row][col]   = (unsigned)l0 | ((unsigned)l1<<16);
            *(unsigned*)&Bl[b_row][col+2] = (unsigned)l2 | ((unsigned)l3<<16);
        }
        __syncthreads();

        #pragma unroll
        for (int ks = 0; ks < 2; ks++) {
            unsigned ah[2][4], al[2][4], bh[2][4], bl[2][4];
            #pragma unroll
            for (int mt = 0; mt < 2; mt++) {
                int ar = warp_m*32 + mt*16 + (lane & 15);
                int ac = ((lane >> 4) << 3) + ks*16;
                unsigned off = (unsigned)(ar*40 + ac)*2u;
                LDSM_X4(ah[mt][0],ah[mt][1],ah[mt][2],ah[mt][3], sAh + off);
                LDSM_X4(al[mt][0],al[mt][1],al[mt][2],al[mt][3], sAl + off);
            }
            #pragma unroll
            for (int np = 0; np < 2; np++) {
                int bk = (lane & 7) + (((lane >> 3) & 1) << 3) + ks*16;
                int bn = warp_n*32 + np*16 + ((lane >> 4) << 3);
                unsigned off = (unsigned)(bk*136 + bn)*2u;
                LDSM_X4T(bh[np][0],bh[np][1],bh[np][2],bh[np][3], sBh + off);
                LDSM_X4T(bl[np][0],bl[np][1],bl[np][2],bl[np][3], sBl + off);
            }
            #pragma unroll
            for (int mt = 0; mt < 2; mt++) {
                #pragma unroll
                for (int j = 0; j < 4; j++) {
                    int np = j >> 1, o = (j & 1) * 2;
                    MMA_BF16(c[mt][j], ah[mt][0],ah[mt][1],ah[mt][2],ah[mt][3],
                             bh[np][o], bh[np][o+1]);
                    MMA_BF16(c[mt][j], ah[mt][0],ah[mt][1],ah[mt][2],ah[mt][3],
                             bl[np][o], bl[np][o+1]);
                    MMA_BF16(c[mt][j], al[mt][0],al[mt][1],al[mt][2],al[mt][3],
                             bh[np][o], bh[np][o+1]);
                }
            }
        }
        __syncthreads();
    }

    #pragma unroll
    for (int mt = 0; mt < 2; mt++) {
        int r0 = brow + warp_m*32 + mt*16 + (lane >> 2);
        #pragma unroll
        for (int j = 0; j < 4; j++) {
            int col = bcol + warp_n*32 + j*8 + (lane & 3)*2;
            float2 v0 = make_float2(c[mt][j][0], c[mt][j][1]);
            float2 v1 = make_float2(c[mt][j][2], c[mt][j][3]);
            if (EPI == 1) {
                float b0 = bias[col], b1 = bias[col+1];
                v0.x += b0; v0.y += b1; v1.x += b0; v1.y += b1;
                v0.x = 0.5f*v0.x*(1.0f+erff(v0.x*0.70710678118654752f));
                v0.y = 0.5f*v0.y*(1.0f+erff(v0.y*0.70710678118654752f));
                v1.x = 0.5f*v1.x*(1.0f+erff(v1.x*0.70710678118654752f));
                v1.y = 0.5f*v1.y*(1.0f+erff(v1.y*0.70710678118654752f));
            }
            *(float2*)&C[(size_t)r0*N + col]     = v0;
            *(float2*)&C[(size_t)(r0+8)*N + col] = v1;
        }
    }
}

// ---------------- pad Wr1 [1048][2048] -> [1056][2048] ----------------
__global__ void __launch_bounds__(256) pad_w1_kernel(
    const float* __restrict__ Wr1, float* __restrict__ W1p)
{
    int idx = blockIdx.x*256 + threadIdx.x;
    if (idx >= 1056*512) return;
    int row = idx / 512;
    float4 v = make_float4(0.f,0.f,0.f,0.f);
    if (row < 1048) v = *(const float4*)(Wr1 + (size_t)idx*4);
    *(float4*)(W1p + (size_t)idx*4) = v;
}

// ---------------- beta + id-gate projections ----------------
__global__ void __launch_bounds__(256) proj_beta_id_kernel(
    const float* __restrict__ x, const float* __restrict__ Wb,
    const float* __restrict__ Wid, const float* __restrict__ bid,
    float* __restrict__ beta, float* __restrict__ sid)
{
    int n = blockIdx.x;
    __shared__ float xs[1024];
    int tid = threadIdx.x;
    *(float4*)&xs[tid*4] = *(const float4*)(x + (size_t)n*1024 + tid*4);
    __syncthreads();
    int w = tid >> 5, lane = tid & 31;
    float s = 0.f;
    if (w < 4) { for (int d=lane; d<1024; d+=32) s += xs[d]*Wb[(size_t)d*4 + w]; }
    else       { int h=w-4; for (int d=lane; d<1024; d+=32) s += xs[d]*Wid[(size_t)d*4 + h]; }
    #pragma unroll
    for (int o=16;o;o>>=1) s += __shfl_xor_sync(0xffffffffu,s,o);
    if (lane==0) {
        if (w<4) beta[(size_t)n*4+w] = sigm(s);
        else     sid[(size_t)n*4+(w-4)] = sigm(s + bid[w-4]);
    }
}

// ---------------- causal depthwise conv (k=4) + silu ----------------
__global__ void __launch_bounds__(256) conv_silu_kernel(
    const float* __restrict__ in, const float* __restrict__ cw, float* __restrict__ out)
{
    int idx = blockIdx.x*256 + threadIdx.x;
    int c = idx & 1023;
    int n = idx >> 10;
    int l = n & (LSEQ-1);
    float4 wv = *(const float4*)(cw + (size_t)c*4);
    float wj[4] = {wv.x, wv.y, wv.z, wv.w};
    float acc = 0.f;
    #pragma unroll
    for (int j=0;j<4;j++){
        int t = l - 3 + j;
        if (t >= 0) acc += in[(size_t)(n-3+j)*1024 + c] * wj[j];
    }
    out[idx] = acc / (1.0f + expf(-acc));
}

// ---------------- per-chunk prep: l2norm, T, u, w, attn ----------------
__global__ void __launch_bounds__(256) chunk_prep_kernel(
    float* __restrict__ q, float* __restrict__ k, const float* __restrict__ v,
    const float* __restrict__ beta, float* __restrict__ u, float* __restrict__ w,
    float* __restrict__ attn)
{
    extern __shared__ float sh[];
    float* qs = sh;
    float* ks = qs + 32*260;
    float* vs = ks + 32*260;
    float* T  = vs + 32*260;
    float* bet = T + 32*33;
    int ci = blockIdx.x;
    int c = ci & 127;
    int h = (ci >> 7) & 3;
    int b = ci >> 9;
    int tid = threadIdx.x;
    size_t base = ((size_t)(b*LSEQ + c*32))*1024 + (size_t)h*256;
    for (int i=tid; i<2048; i+=256) {
        int r = i>>6; int d4 = (i&63)<<2;
        size_t off = base + (size_t)r*1024 + d4;
        *(float4*)&qs[r*260+d4] = *(const float4*)(q + off);
        *(float4*)&ks[r*260+d4] = *(const float4*)(k + off);
        *(float4*)&vs[r*260+d4] = *(const float4*)(v + off);
    }
    if (tid < 32) bet[tid] = beta[(size_t)(b*LSEQ + c*32 + tid)*4 + h];
    __syncthreads();
    {
        int wi = tid>>5, lane = tid&31;
        for (int r = wi*4; r < wi*4+4; r++) {
            float sq=0.f, sk2=0.f;
            for (int dd=lane; dd<256; dd+=32){
                float a=qs[r*260+dd]; sq+=a*a;
                float bb=ks[r*260+dd]; sk2+=bb*bb;
            }
            #pragma unroll
            for (int o=16;o;o>>=1){
                sq+=__shfl_xor_sync(0xffffffffu,sq,o);
                sk2+=__shfl_xor_sync(0xffffffffu,sk2,o);
            }
            float rq = rsqrtf(sq+1e-6f), rk = rsqrtf(sk2+1e-6f);
            for (int dd=lane; dd<256; dd+=32){ qs[r*260+dd]*=rq; ks[r*260+dd]*=rk; }
        }
    }
    __syncthreads();
    size_t abase = (size_t)ci*1024;
    for (int pp=tid; pp<1024; pp+=256) {
        int i = pp>>5, j = pp&31;
        float dkk=0.f, dqq=0.f;
        for (int dd=0; dd<256; dd++){
            float kj = ks[j*260+dd];
            dkk += ks[i*260+dd]*kj;
            dqq += qs[i*260+dd]*kj;
        }
        T[i*33+j] = (j<i)? (-bet[i]*dkk) : 0.f;
        attn[abase+pp] = (j<=i)? dqq : 0.f;
    }
    __syncthreads();
    if (tid<32) {
        int lane = tid;
        for (int i=1;i<32;i++){
            float rowv = T[i*33+lane];
            float add = 0.f;
            for (int j=0;j<i;j++) add += __shfl_sync(0xffffffffu, rowv, j)*T[j*33+lane];
            T[i*33+lane] = rowv + add;
            __syncwarp();
        }
        T[lane*33+lane] += 1.0f;
    }
    __syncthreads();
    for (int pp=tid; pp<8192; pp+=256){
        int r = pp>>8, dd = pp&255;
        float su=0.f, sw=0.f;
        #pragma unroll
        for (int j=0;j<32;j++){
            float tj = T[r*33+j]*bet[j];
            su += tj*vs[j*260+dd];
            sw += tj*ks[j*260+dd];
        }
        size_t off = base + (size_t)r*1024 + dd;
        u[off]=su; w[off]=sw;
        q[off]=qs[r*260+dd]; k[off]=ks[r*260+dd];
    }
}

// ---------------- sequential chunk scan, dv-sliced (16 slices of 16) -------
__global__ void __launch_bounds__(512) scan_kernel(
    const float* __restrict__ q, const float* __restrict__ k,
    const float* __restrict__ u, const float* __restrict__ w,
    const float* __restrict__ attn, float* __restrict__ outp)
{
    extern __shared__ float sh[];
    float* S  = sh;              // 256*16
    float* qs = S + 4096;        // 32*260
    float* ks = qs + 8320;
    float* ws = ks + 8320;
    float* as = ws + 8320;       // 32*32
    float* u2 = as + 1024;       // 32*16
    int bid = blockIdx.x;
    int sl = bid & 15;
    int bh = bid >> 4;
    int h = bh & 3, b = bh >> 2;
    int tid = threadIdx.x;
    for (int i=tid;i<4096;i+=512) S[i]=0.f;
    const int iRow = tid >> 4;       // 0..31
    const int q1 = tid & 15;         // 0..15
    const int dd0 = tid >> 2;        // 0..127
    const int c4 = (tid & 3) * 4;    // 0,4,8,12
    size_t abh = (size_t)bh * 128 * 1024;
    for (int c=0;c<128;c++){
        size_t base = ((size_t)(b*LSEQ + c*32))*1024 + (size_t)h*256;
        __syncthreads();
        for (int i=tid;i<2048;i+=512){
            int r=i>>6; int d4=(i&63)<<2;
            size_t off = base + (size_t)r*1024 + d4;
            *(float4*)&qs[r*260+d4] = *(const float4*)(q+off);
            *(float4*)&ks[r*260+d4] = *(const float4*)(k+off);
            *(float4*)&ws[r*260+d4] = *(const float4*)(w+off);
        }
        if (tid < 256)
            *(float4*)&as[tid*4] = *(const float4*)(attn + abh + (size_t)c*1024 + tid*4);
        __syncthreads();
        float au = u[base + (size_t)iRow*1024 + sl*16 + q1];
        float ao = 0.f;
        #pragma unroll 8
        for (int dd=0; dd<256; dd++){
            float Sv = S[dd*16+q1];
            au -= ws[iRow*260+dd]*Sv;
            ao += qs[iRow*260+dd]*Sv;
        }
        u2[iRow*16+q1] = au;
        __syncthreads();
        #pragma unroll
        for (int j=0;j<32;j++) ao += as[iRow*32+j]*u2[j*16+q1];
        outp[base + (size_t)iRow*1024 + sl*16 + q1] = ao;
        #pragma unroll
        for (int s2=0; s2<2; s2++){
            int dd = dd0 + s2*128;
            float4 Sv = *(float4*)&S[dd*16+c4];
            #pragma unroll 8
            for (int j=0;j<32;j++){
                float kv = ks[j*260+dd];
                float4 uv = *(float4*)&u2[j*16+c4];
                Sv.x += kv*uv.x; Sv.y += kv*uv.y; Sv.z += kv*uv.z; Sv.w += kv*uv.w;
            }
            *(float4*)&S[dd*16+c4] = Sv;
        }
    }
}

// ---------------- FIR short/long + stats + router input --------------------
__global__ void __launch_bounds__(256) fir_stats_kernel(
    const float* __restrict__ v, const float* __restrict__ dlt,
    const float* __restrict__ x, const float* __restrict__ firS,
    const float* __restrict__ firL,
    float* __restrict__ fs, float* __restrict__ fl, float* __restrict__ rin)
{
    int n = blockIdx.x;
    int l = n & (LSEQ-1);
    int d = threadIdx.x;
    __shared__ float red[8];
    {
        const float4* xs = (const float4*)(x + (size_t)n*1024);
        float4* rp = (float4*)(rin + (size_t)n*1056);
        rp[d] = xs[d];
    }
    if (d < 8) rin[(size_t)n*1056 + 1048 + d] = 0.f;
    for (int h=0; h<4; h++) {
        int cidx = h*256 + d;
        float accS = 0.f;
        #pragma unroll
        for (int j=0;j<3;j++){
            int t = l-2+j;
            if (t>=0) accS += v[(size_t)(n-2+j)*1024 + cidx]*firS[(size_t)cidx*3+j];
        }
        float accL = 0.f;
        #pragma unroll
        for (int j=0;j<31;j++){
            int t = l-30+j;
            if (t>=0) accL += v[(size_t)(n-30+j)*1024 + cidx]*firL[(size_t)cidx*31+j];
        }
        float dv = dlt[(size_t)n*1024 + cidx];
        fs[(size_t)n*1024+cidx]=accS;
        fl[(size_t)n*1024+cidx]=accL;
        float s1 = blockReduceSum(accS, red);
        float s2 = blockReduceSum(accS*accS, red);
        float s3 = blockReduceSum(accL, red);
        float s4 = blockReduceSum(accL*accL, red);
        float s5 = blockReduceSum(dv, red);
        float s6 = blockReduceSum(dv*dv, red);
        if (threadIdx.x==0) {
            float* rp = rin + (size_t)n*1056 + 1024;
            float m1 = s1*(1.f/256.f), m3 = s3*(1.f/256.f), m5 = s5*(1.f/256.f);
            rp[h]    = m1;
            rp[4+h]  = sqrtf(fmaxf(s2*(1.f/256.f) - m1*m1, 0.f));
            rp[8+h]  = m3;
            rp[12+h] = sqrtf(fmaxf(s4*(1.f/256.f) - m3*m3, 0.f));
            rp[16+h] = m5;
            rp[20+h] = sqrtf(fmaxf(s6*(1.f/256.f) - m5*m5, 0.f));
        }
        __syncthreads();
    }
}

// ---------------- router logits + tempered softmax --------------------------
__global__ void __launch_bounds__(256) router_kernel(
    const float* __restrict__ hmid, const float* __restrict__ Wr2,
    const float* __restrict__ br2, const float* __restrict__ ltg,
    float* __restrict__ p)
{
    int n = blockIdx.x;
    __shared__ float hrow[2048];
    __shared__ float lg[12];
    int tid = threadIdx.x;
    for (int i=tid;i<512;i+=256)
        *(float4*)&hrow[i*4] = *(const float4*)(hmid + (size_t)n*2048 + i*4);
    __syncthreads();
    int w = tid>>5, lane = tid&31;
    for (int out = w; out < 12; out += 8) {
        float s=0.f;
        for (int kk=lane; kk<2048; kk+=32) s += hrow[kk]*Wr2[(size_t)kk*12+out];
        #pragma unroll
        for (int o=16;o;o>>=1) s += __shfl_xor_sync(0xffffffffu,s,o);
        if (lane==0) lg[out] = s + br2[out];
    }
    __syncthreads();
    if (tid < 4) {
        int h = tid;
        float tau = expf(ltg[h>>1]);
        float a = lg[h*3+0]/tau, bq = lg[h*3+1]/tau, cq = lg[h*3+2]/tau;
        float m = fmaxf(a, fmaxf(bq,cq));
        float ea=expf(a-m), eb=expf(bq-m), ec=expf(cq-m);
        float inv = 1.f/(ea+eb+ec);
        p[(size_t)n*12 + h*3+0] = ea*inv*0.925f + 0.025f;
        p[(size_t)n*12 + h*3+1] = eb*inv*0.925f + 0.025f;
        p[(size_t)n*12 + h*3+2] = ec*inv*0.925f + 0.025f;
    }
}

// ---------------- gated mix + id path + per-head RMS norm -------------------
__global__ void __launch_bounds__(256) mix_norm_kernel(
    const float* __restrict__ p, const float* __restrict__ fs,
    const float* __restrict__ fl, const float* __restrict__ dlt,
    const float* __restrict__ v, const float* __restrict__ sid,
    const float* __restrict__ alpha_id, const float* __restrict__ onw,
    float* __restrict__ omix)
{
    int n = blockIdx.x;
    int d = threadIdx.x;
    __shared__ float red[8];
    for (int h=0;h<4;h++){
        size_t idx = (size_t)n*1024 + h*256 + d;
        float p0 = p[(size_t)n*12+h*3+0];
        float p1 = p[(size_t)n*12+h*3+1];
        float p2 = p[(size_t)n*12+h*3+2];
        float ids = 0.06f + sigm(alpha_id[h]) * sid[(size_t)n*4+h];
        float o = p0*fs[idx] + p1*fl[idx] + p2*dlt[idx] + ids*v[idx];
        float ss = blockReduceSum(o*o, red);
        float r = rsqrtf(ss*(1.f/256.f) + 1e-5f);
        omix[idx] = o*r*onw[d];
    }
}

extern "C" void kernel_launch(void* const* d_in, const int* in_sizes, int n_in,
                              void* d_out, int out_size) {
    const float* x    = (const float*)d_in[0];
    const float* Wq   = (const float*)d_in[1];
    const float* Wk   = (const float*)d_in[2];
    const float* Wv   = (const float*)d_in[3];
    const float* Wb   = (const float*)d_in[4];
    const float* cq   = (const float*)d_in[5];
    const float* ck   = (const float*)d_in[6];
    const float* cv   = (const float*)d_in[7];
    const float* firS = (const float*)d_in[8];
    const float* firL = (const float*)d_in[9];
    const float* aid  = (const float*)d_in[10];
    const float* Wid  = (const float*)d_in[11];
    const float* bid  = (const float*)d_in[12];
    const float* Wr1  = (const float*)d_in[13];
    const float* br1  = (const float*)d_in[14];
    const float* Wr2  = (const float*)d_in[15];
    const float* br2  = (const float*)d_in[16];
    const float* ltg  = (const float*)d_in[17];
    const float* onw  = (const float*)d_in[19];
    const float* Wo   = (const float*)d_in[20];
    float* out = (float*)d_out;

    void* bufv = nullptr;
    cudaGetSymbolAddress(&bufv, g_buf);
    float* buf = (float*)bufv;
    float* qlin = buf + OFF_QL;
    float* klin = buf + OFF_KL;
    float* vlin = buf + OFF_VL;
    float* qb   = buf + OFF_Q;
    float* kb   = buf + OFF_K;
    float* vb   = buf + OFF_V;
    float* ub   = buf + OFF_U;
    float* wb   = buf + OFF_W;
    float* dlt  = buf + OFF_DELTA;
    float* fsb  = buf + OFF_FS;
    float* flb  = buf + OFF_FL;
    float* omix = buf + OFF_OMIX;
    float* rin  = buf + OFF_RIN;
    float* hmid = buf + OFF_HMID;
    float* attn = buf + OFF_ATTN;
    float* beta = buf + OFF_BETA;
    float* sidb = buf + OFF_SID;
    float* pb   = buf + OFF_P;
    float* w1p  = buf + OFF_W1P;

    int smem_prep = (3*32*260 + 32*33 + 32) * 4;
    int smem_scan = (4096 + 3*8320 + 1024 + 512) * 4;
    cudaFuncSetAttribute(chunk_prep_kernel, cudaFuncAttributeMaxDynamicSharedMemorySize, smem_prep);
    cudaFuncSetAttribute(scan_kernel, cudaFuncAttributeMaxDynamicSharedMemorySize, smem_scan);

    dim3 blk(512);
    dim3 g1(8, 64);
    pad_w1_kernel<<<(1056*512 + 255)/256, 256>>>(Wr1, w1p);
    tgemm_kernel<0><<<g1, blk>>>(x, Wq, nullptr, qlin, NTOK, 1024, 1024);
    tgemm_kernel<0><<<g1, blk>>>(x, Wk, nullptr, klin, NTOK, 1024, 1024);
    tgemm_kernel<0><<<g1, blk>>>(x, Wv, nullptr, vlin, NTOK, 1024, 1024);
    proj_beta_id_kernel<<<NTOK, 256>>>(x, Wb, Wid, bid, beta, sidb);
    conv_silu_kernel<<<NTOK*4, 256>>>(qlin, cq, qb);
    conv_silu_kernel<<<NTOK*4, 256>>>(klin, ck, kb);
    conv_silu_kernel<<<NTOK*4, 256>>>(vlin, cv, vb);
    chunk_prep_kernel<<<1024, 256, smem_prep>>>(qb, kb, vb, beta, ub, wb, attn);
    scan_kernel<<<128, 512, smem_scan>>>(qb, kb, ub, wb, attn, dlt);
    fir_stats_kernel<<<NTOK, 256>>>(vb, dlt, x, firS, firL, fsb, flb, rin);
    dim3 g2(16, 64);
    tgemm_kernel<1><<<g2, blk>>>(rin, w1p, br1, hmid, NTOK, 2048, 1056);
    router_kernel<<<NTOK, 256>>>(hmid, Wr2, br2, ltg, pb);
    mix_norm_kernel<<<NTOK, 256>>>(pb, fsb, flb, dlt, vb, sidb, aid, onw, omix);
    tgemm_kernel<0><<<g1, blk>>>(omix, Wo, nullptr, out, NTOK, 1024, 1024);
}

// round 5
// speedup vs baseline: 1.6953x; 1.1001x over previous
#include <cuda_runtime.h>
#include <cuda_bf16.h>
#include <math.h>

#define LSEQ 4096
#define NTOK 8192

// ---------------- float scratch offsets ----------------
#define OFF_QL    ((size_t)0)
#define OFF_KL    ((size_t)8388608)
#define OFF_VL    ((size_t)16777216)
#define OFF_Q     ((size_t)25165824)
#define OFF_K     ((size_t)33554432)
#define OFF_V     ((size_t)41943040)
#define OFF_U     ((size_t)50331648)
#define OFF_W     ((size_t)58720256)
#define OFF_DELTA ((size_t)67108864)
#define OFF_FS    ((size_t)75497472)
#define OFF_FL    ((size_t)83886080)
#define OFF_OMIX  ((size_t)92274688)
#define OFF_RIN   ((size_t)100663296)   // 8192 x 1056
#define OFF_HMID  ((size_t)109314048)   // 8192 x 2048
#define OFF_ATTN  ((size_t)126091264)   // 1024 x 1024
#define OFF_BETA  ((size_t)127139840)
#define OFF_SID   ((size_t)127172608)
#define OFF_P     ((size_t)127205376)
#define BUF_TOTAL ((size_t)127303680)

__device__ float g_buf[BUF_TOTAL];

// ---------------- bf16 plane offsets (ushort units) ----------------
#define BOFF_X_HI    ((size_t)0)
#define BOFF_X_LO    ((size_t)8388608)
#define BOFF_OM_HI   ((size_t)16777216)
#define BOFF_OM_LO   ((size_t)25165824)
#define BOFF_RIN_HI  ((size_t)33554432)
#define BOFF_RIN_LO  ((size_t)42205184)
#define BOFF_WQ_HI   ((size_t)50855936)
#define BOFF_WQ_LO   ((size_t)51904512)
#define BOFF_WK_HI   ((size_t)52953088)
#define BOFF_WK_LO   ((size_t)54001664)
#define BOFF_WV_HI   ((size_t)55050240)
#define BOFF_WV_LO   ((size_t)56098816)
#define BOFF_WO_HI   ((size_t)57147392)
#define BOFF_WO_LO   ((size_t)58195968)
#define BOFF_W1_HI   ((size_t)59244544)
#define BOFF_W1_LO   ((size_t)61407232)
#define BBUF_TOTAL   ((size_t)63569920)

__device__ unsigned short g_bf[BBUF_TOTAL];

__device__ __forceinline__ float sigm(float x){ return 1.0f/(1.0f+expf(-x)); }

__device__ __forceinline__ unsigned short f2bf(float f){
    __nv_bfloat16 h = __float2bfloat16(f);
    return *(unsigned short*)&h;
}
__device__ __forceinline__ float bf2f(unsigned short u){
    __nv_bfloat16 h = *(__nv_bfloat16*)&u;
    return __bfloat162float(h);
}

__device__ __forceinline__ float blockReduceSum(float val, float* red) {
    int lane = threadIdx.x & 31, w = threadIdx.x >> 5;
    #pragma unroll
    for (int o=16;o;o>>=1) val += __shfl_xor_sync(0xffffffffu, val, o);
    if (lane==0) red[w]=val;
    __syncthreads();
    if (w==0) {
        float v2 = (lane<8)? red[lane] : 0.f;
        #pragma unroll
        for (int o=4;o;o>>=1) v2 += __shfl_xor_sync(0xffffffffu, v2, o);
        if (lane==0) red[0]=v2;
    }
    __syncthreads();
    float r = red[0];
    __syncthreads();
    return r;
}

#define LDSM_X4(R0,R1,R2,R3,ADDR) \
    asm volatile("ldmatrix.sync.aligned.m8n8.x4.shared.b16 {%0,%1,%2,%3}, [%4];" \
        : "=r"(R0),"=r"(R1),"=r"(R2),"=r"(R3) : "r"(ADDR))
#define LDSM_X4T(R0,R1,R2,R3,ADDR) \
    asm volatile("ldmatrix.sync.aligned.m8n8.x4.trans.shared.b16 {%0,%1,%2,%3}, [%4];" \
        : "=r"(R0),"=r"(R1),"=r"(R2),"=r"(R3) : "r"(ADDR))
#define MMA_BF16(C,A0,A1,A2,A3,B0,B1) \
    asm volatile("mma.sync.aligned.m16n8k16.row.col.f32.bf16.bf16.f32 " \
        "{%0,%1,%2,%3},{%4,%5,%6,%7},{%8,%9},{%0,%1,%2,%3};" \
        : "+f"(C[0]),"+f"(C[1]),"+f"(C[2]),"+f"(C[3]) \
        : "r"(A0),"r"(A1),"r"(A2),"r"(A3),"r"(B0),"r"(B1))

// ---------------- fp32 -> bf16 hi/lo split (8 elems/thread) ----------------
__global__ void __launch_bounds__(256) f2bf_split_kernel(
    const float* __restrict__ src, unsigned short* __restrict__ hi,
    unsigned short* __restrict__ lo, int n8)
{
    int idx = blockIdx.x*256 + threadIdx.x;
    if (idx >= n8) return;
    const float4* s = (const float4*)(src) + (size_t)idx*2;
    float4 v0 = s[0], v1 = s[1];
    float f[8] = {v0.x,v0.y,v0.z,v0.w,v1.x,v1.y,v1.z,v1.w};
    unsigned hh[4], ll[4];
    #pragma unroll
    for (int i=0;i<4;i++){
        unsigned short h0 = f2bf(f[i*2]), h1 = f2bf(f[i*2+1]);
        unsigned short l0 = f2bf(f[i*2]-bf2f(h0)), l1 = f2bf(f[i*2+1]-bf2f(h1));
        hh[i] = (unsigned)h0 | ((unsigned)h1<<16);
        ll[i] = (unsigned)l0 | ((unsigned)l1<<16);
    }
    *(uint4*)(hi + (size_t)idx*8) = make_uint4(hh[0],hh[1],hh[2],hh[3]);
    *(uint4*)(lo + (size_t)idx*8) = make_uint4(ll[0],ll[1],ll[2],ll[3]);
}

// ---------------- Wr1 [1048][2048] -> padded [1056][2048] bf16 split -------
__global__ void __launch_bounds__(256) f2bf_split_pad_kernel(
    const float* __restrict__ src, unsigned short* __restrict__ hi,
    unsigned short* __restrict__ lo)
{
    int idx = blockIdx.x*256 + threadIdx.x;
    if (idx >= 1056*256) return;       // 8 elems each
    int row = (idx*8) >> 11;
    unsigned hh[4]={0,0,0,0}, ll[4]={0,0,0,0};
    if (row < 1048) {
        const float4* s = (const float4*)(src) + (size_t)idx*2;
        float4 v0 = s[0], v1 = s[1];
        float f[8] = {v0.x,v0.y,v0.z,v0.w,v1.x,v1.y,v1.z,v1.w};
        #pragma unroll
        for (int i=0;i<4;i++){
            unsigned short h0 = f2bf(f[i*2]), h1 = f2bf(f[i*2+1]);
            unsigned short l0 = f2bf(f[i*2]-bf2f(h0)), l1 = f2bf(f[i*2+1]-bf2f(h1));
            hh[i] = (unsigned)h0 | ((unsigned)h1<<16);
            ll[i] = (unsigned)l0 | ((unsigned)l1<<16);
        }
    }
    *(uint4*)(hi + (size_t)idx*8) = make_uint4(hh[0],hh[1],hh[2],hh[3]);
    *(uint4*)(lo + (size_t)idx*8) = make_uint4(ll[0],ll[1],ll[2],ll[3]);
}

// ---------------- tensor-core GEMM on preconverted bf16 hi/lo planes -------
// 256 threads, 8 warps (4x2), warp tile 32x64, CTA tile 128x128, ktile 64.
#define SMEM_GEMM ((2*128*72 + 2*64*136)*2)
template<int EPI>
__global__ void __launch_bounds__(256,2) tgemm_kernel(
    const unsigned short* __restrict__ Ahi, const unsigned short* __restrict__ Alo,
    const unsigned short* __restrict__ Bhi, const unsigned short* __restrict__ Blo,
    const float* __restrict__ bias, float* __restrict__ C,
    int M, int N, int K)
{
    extern __shared__ unsigned short sm[];
    unsigned short* Ah = sm;                   // 128 x 72
    unsigned short* Al = Ah + 128*72;
    unsigned short* Bh = Al + 128*72;          // 64 x 136
    unsigned short* Bl = Bh + 64*136;

    const int tid  = threadIdx.x;
    const int lane = tid & 31;
    const int warp = tid >> 5;
    const int warp_m = warp & 3;
    const int warp_n = warp >> 2;
    const int brow = blockIdx.y * 128;
    const int bcol = blockIdx.x * 128;

    float c[2][8][4];
    #pragma unroll
    for (int i=0;i<2;i++)
        #pragma unroll
        for (int j=0;j<8;j++)
            #pragma unroll
            for (int t=0;t<4;t++) c[i][j][t]=0.f;

    const unsigned sAh = (unsigned)__cvta_generic_to_shared(Ah);
    const unsigned sAl = (unsigned)__cvta_generic_to_shared(Al);
    const unsigned sBh = (unsigned)__cvta_generic_to_shared(Bh);
    const unsigned sBl = (unsigned)__cvta_generic_to_shared(Bl);

    const int a_row = tid >> 1;             // 0..127
    const int a_col0 = (tid & 1) * 32;
    const int b_row = tid >> 2;             // 0..63
    const int b_col0 = (tid & 3) * 32;

    const unsigned short* Ahg = Ahi + (size_t)(brow + a_row)*K + a_col0;
    const unsigned short* Alg = Alo + (size_t)(brow + a_row)*K + a_col0;
    const unsigned short* Bhg = Bhi + (size_t)b_row*N + bcol + b_col0;
    const unsigned short* Blg = Blo + (size_t)b_row*N + bcol + b_col0;

    for (int kt = 0; kt < K; kt += 64) {
        #pragma unroll
        for (int c4=0;c4<4;c4++){
            int col = a_col0 + c4*8;
            *(uint4*)&Ah[a_row*72 + col] = *(const uint4*)(Ahg + kt + c4*8);
            *(uint4*)&Al[a_row*72 + col] = *(const uint4*)(Alg + kt + c4*8);
        }
        #pragma unroll
        for (int c4=0;c4<4;c4++){
            int col = b_col0 + c4*8;
            *(uint4*)&Bh[b_row*136 + col] = *(const uint4*)(Bhg + (size_t)kt*N + c4*8);
            *(uint4*)&Bl[b_row*136 + col] = *(const uint4*)(Blg + (size_t)kt*N + c4*8);
        }
        __syncthreads();

        #pragma unroll
        for (int ks = 0; ks < 4; ks++) {
            unsigned ah[2][4], al[2][4];
            #pragma unroll
            for (int mt = 0; mt < 2; mt++) {
                int ar = warp_m*32 + mt*16 + (lane & 15);
                int ac = ((lane >> 4) << 3) + ks*16;
                unsigned off = (unsigned)(ar*72 + ac)*2u;
                LDSM_X4(ah[mt][0],ah[mt][1],ah[mt][2],ah[mt][3], sAh + off);
                LDSM_X4(al[mt][0],al[mt][1],al[mt][2],al[mt][3], sAl + off);
            }
            #pragma unroll
            for (int np = 0; np < 4; np++) {
                unsigned bh[4], bl[4];
                int bk = (lane & 7) + (((lane >> 3) & 1) << 3) + ks*16;
                int bn = warp_n*64 + np*16 + ((lane >> 4) << 3);
                unsigned off = (unsigned)(bk*136 + bn)*2u;
                LDSM_X4T(bh[0],bh[1],bh[2],bh[3], sBh + off);
                LDSM_X4T(bl[0],bl[1],bl[2],bl[3], sBl + off);
                #pragma unroll
                for (int mt = 0; mt < 2; mt++) {
                    #pragma unroll
                    for (int jj = 0; jj < 2; jj++) {
                        int j = np*2 + jj, o = jj*2;
                        MMA_BF16(c[mt][j], ah[mt][0],ah[mt][1],ah[mt][2],ah[mt][3],
                                 bh[o], bh[o+1]);
                        MMA_BF16(c[mt][j], ah[mt][0],ah[mt][1],ah[mt][2],ah[mt][3],
                                 bl[o], bl[o+1]);
                        MMA_BF16(c[mt][j], al[mt][0],al[mt][1],al[mt][2],al[mt][3],
                                 bh[o], bh[o+1]);
                    }
                }
            }
        }
        __syncthreads();
    }

    #pragma unroll
    for (int mt = 0; mt < 2; mt++) {
        int r0 = brow + warp_m*32 + mt*16 + (lane >> 2);
        #pragma unroll
        for (int j = 0; j < 8; j++) {
            int col = bcol + warp_n*64 + j*8 + (lane & 3)*2;
            float2 v0 = make_float2(c[mt][j][0], c[mt][j][1]);
            float2 v1 = make_float2(c[mt][j][2], c[mt][j][3]);
            if (EPI == 1) {
                float b0 = bias[col], b1 = bias[col+1];
                v0.x += b0; v0.y += b1; v1.x += b0; v1.y += b1;
                v0.x = 0.5f*v0.x*(1.0f+erff(v0.x*0.70710678118654752f));
                v0.y = 0.5f*v0.y*(1.0f+erff(v0.y*0.70710678118654752f));
                v1.x = 0.5f*v1.x*(1.0f+erff(v1.x*0.70710678118654752f));
                v1.y = 0.5f*v1.y*(1.0f+erff(v1.y*0.70710678118654752f));
            }
            *(float2*)&C[(size_t)r0*N + col]     = v0;
            *(float2*)&C[(size_t)(r0+8)*N + col] = v1;
        }
    }
}

// ---------------- beta + id-gate projections ----------------
__global__ void __launch_bounds__(256) proj_beta_id_kernel(
    const float* __restrict__ x, const float* __restrict__ Wb,
    const float* __restrict__ Wid, const float* __restrict__ bid,
    float* __restrict__ beta, float* __restrict__ sid)
{
    int n = blockIdx.x;
    __shared__ float xs[1024];
    int tid = threadIdx.x;
    *(float4*)&xs[tid*4] = *(const float4*)(x + (size_t)n*1024 + tid*4);
    __syncthreads();
    int w = tid >> 5, lane = tid & 31;
    float s = 0.f;
    if (w < 4) { for (int d=lane; d<1024; d+=32) s += xs[d]*Wb[(size_t)d*4 + w]; }
    else       { int h=w-4; for (int d=lane; d<1024; d+=32) s += xs[d]*Wid[(size_t)d*4 + h]; }
    #pragma unroll
    for (int o=16;o;o>>=1) s += __shfl_xor_sync(0xffffffffu,s,o);
    if (lane==0) {
        if (w<4) beta[(size_t)n*4+w] = sigm(s);
        else     sid[(size_t)n*4+(w-4)] = sigm(s + bid[w-4]);
    }
}

// ---------------- causal depthwise conv (k=4) + silu ----------------
__global__ void __launch_bounds__(256) conv_silu_kernel(
    const float* __restrict__ in, const float* __restrict__ cw, float* __restrict__ out)
{
    int idx = blockIdx.x*256 + threadIdx.x;
    int c = idx & 1023;
    int n = idx >> 10;
    int l = n & (LSEQ-1);
    float4 wv = *(const float4*)(cw + (size_t)c*4);
    float wj[4] = {wv.x, wv.y, wv.z, wv.w};
    float acc = 0.f;
    #pragma unroll
    for (int j=0;j<4;j++){
        int t = l - 3 + j;
        if (t >= 0) acc += in[(size_t)(n-3+j)*1024 + c] * wj[j];
    }
    out[idx] = acc / (1.0f + expf(-acc));
}

// ---------------- per-chunk prep: l2norm, T, u, w, attn ----------------
__global__ void __launch_bounds__(256) chunk_prep_kernel(
    float* __restrict__ q, float* __restrict__ k, const float* __restrict__ v,
    const float* __restrict__ beta, float* __restrict__ u, float* __restrict__ w,
    float* __restrict__ attn)
{
    extern __shared__ float sh[];
    float* qs = sh;
    float* ks = qs + 32*260;
    float* vs = ks + 32*260;
    float* T  = vs + 32*260;
    float* bet = T + 32*33;
    int ci = blockIdx.x;
    int c = ci & 127;
    int h = (ci >> 7) & 3;
    int b = ci >> 9;
    int tid = threadIdx.x;
    size_t base = ((size_t)(b*LSEQ + c*32))*1024 + (size_t)h*256;
    for (int i=tid; i<2048; i+=256) {
        int r = i>>6; int d4 = (i&63)<<2;
        size_t off = base + (size_t)r*1024 + d4;
        *(float4*)&qs[r*260+d4] = *(const float4*)(q + off);
        *(float4*)&ks[r*260+d4] = *(const float4*)(k + off);
        *(float4*)&vs[r*260+d4] = *(const float4*)(v + off);
    }
    if (tid < 32) bet[tid] = beta[(size_t)(b*LSEQ + c*32 + tid)*4 + h];
    __syncthreads();
    {
        int wi = tid>>5, lane = tid&31;
        for (int r = wi*4; r < wi*4+4; r++) {
            float sq=0.f, sk2=0.f;
            for (int dd=lane; dd<256; dd+=32){
                float a=qs[r*260+dd]; sq+=a*a;
                float bb=ks[r*260+dd]; sk2+=bb*bb;
            }
            #pragma unroll
            for (int o=16;o;o>>=1){
                sq+=__shfl_xor_sync(0xffffffffu,sq,o);
                sk2+=__shfl_xor_sync(0xffffffffu,sk2,o);
            }
            float rq = rsqrtf(sq+1e-6f), rk = rsqrtf(sk2+1e-6f);
            for (int dd=lane; dd<256; dd+=32){ qs[r*260+dd]*=rq; ks[r*260+dd]*=rk; }
        }
    }
    __syncthreads();
    size_t abase = (size_t)ci*1024;
    for (int pp=tid; pp<1024; pp+=256) {
        int i = pp>>5, j = pp&31;
        float dkk=0.f, dqq=0.f;
        for (int dd=0; dd<256; dd++){
            float kj = ks[j*260+dd];
            dkk += ks[i*260+dd]*kj;
            dqq += qs[i*260+dd]*kj;
        }
        T[i*33+j] = (j<i)? (-bet[i]*dkk) : 0.f;
        attn[abase+pp] = (j<=i)? dqq : 0.f;
    }
    __syncthreads();
    if (tid<32) {
        int lane = tid;
        for (int i=1;i<32;i++){
            float rowv = T[i*33+lane];
            float add = 0.f;
            for (int j=0;j<i;j++) add += __shfl_sync(0xffffffffu, rowv, j)*T[j*33+lane];
            T[i*33+lane] = rowv + add;
            __syncwarp();
        }
        T[lane*33+lane] += 1.0f;
    }
    __syncthreads();
    for (int pp=tid; pp<8192; pp+=256){
        int r = pp>>8, dd = pp&255;
        float su=0.f, sw=0.f;
        #pragma unroll
        for (int j=0;j<32;j++){
            float tj = T[r*33+j]*bet[j];
            su += tj*vs[j*260+dd];
            sw += tj*ks[j*260+dd];
        }
        size_t off = base + (size_t)r*1024 + dd;
        u[off]=su; w[off]=sw;
        q[off]=qs[r*260+dd]; k[off]=ks[r*260+dd];
    }
}

// ---------------- sequential chunk scan, dv-sliced (16 slices of 16) -------
__global__ void __launch_bounds__(512) scan_kernel(
    const float* __restrict__ q, const float* __restrict__ k,
    const float* __restrict__ u, const float* __restrict__ w,
    const float* __restrict__ attn, float* __restrict__ outp)
{
    extern __shared__ float sh[];
    float* S  = sh;              // 256*16
    float* qs = S + 4096;        // 32*260
    float* ks = qs + 8320;
    float* ws = ks + 8320;
    float* as = ws + 8320;       // 32*32
    float* u2 = as + 1024;       // 32*16
    int bid = blockIdx.x;
    int sl = bid & 15;
    int bh = bid >> 4;
    int h = bh & 3, b = bh >> 2;
    int tid = threadIdx.x;
    for (int i=tid;i<4096;i+=512) S[i]=0.f;
    const int iRow = tid >> 4;
    const int q1 = tid & 15;
    const int dd0 = tid >> 2;
    const int c4 = (tid & 3) * 4;
    size_t abh = (size_t)bh * 128 * 1024;
    for (int c=0;c<128;c++){
        size_t base = ((size_t)(b*LSEQ + c*32))*1024 + (size_t)h*256;
        __syncthreads();
        for (int i=tid;i<2048;i+=512){
            int r=i>>6; int d4=(i&63)<<2;
            size_t off = base + (size_t)r*1024 + d4;
            *(float4*)&qs[r*260+d4] = *(const float4*)(q+off);
            *(float4*)&ks[r*260+d4] = *(const float4*)(k+off);
            *(float4*)&ws[r*260+d4] = *(const float4*)(w+off);
        }
        if (tid < 256)
            *(float4*)&as[tid*4] = *(const float4*)(attn + abh + (size_t)c*1024 + tid*4);
        __syncthreads();
        float au = u[base + (size_t)iRow*1024 + sl*16 + q1];
        float ao = 0.f;
        #pragma unroll 8
        for (int dd=0; dd<256; dd++){
            float Sv = S[dd*16+q1];
            au -= ws[iRow*260+dd]*Sv;
            ao += qs[iRow*260+dd]*Sv;
        }
        u2[iRow*16+q1] = au;
        __syncthreads();
        #pragma unroll
        for (int j=0;j<32;j++) ao += as[iRow*32+j]*u2[j*16+q1];
        outp[base + (size_t)iRow*1024 + sl*16 + q1] = ao;
        #pragma unroll
        for (int s2=0; s2<2; s2++){
            int dd = dd0 + s2*128;
            float4 Sv = *(float4*)&S[dd*16+c4];
            #pragma unroll 8
            for (int j=0;j<32;j++){
                float kv = ks[j*260+dd];
                float4 uv = *(float4*)&u2[j*16+c4];
                Sv.x += kv*uv.x; Sv.y += kv*uv.y; Sv.z += kv*uv.z; Sv.w += kv*uv.w;
            }
            *(float4*)&S[dd*16+c4] = Sv;
        }
    }
}

// ---------------- FIR short/long + stats + router input --------------------
__global__ void __launch_bounds__(256) fir_stats_kernel(
    const float* __restrict__ v, const float* __restrict__ dlt,
    const float* __restrict__ x, const float* __restrict__ firS,
    const float* __restrict__ firL,
    float* __restrict__ fs, float* __restrict__ fl, float* __restrict__ rin)
{
    int n = blockIdx.x;
    int l = n & (LSEQ-1);
    int d = threadIdx.x;
    __shared__ float red[8];
    {
        const float4* xs = (const float4*)(x + (size_t)n*1024);
        float4* rp = (float4*)(rin + (size_t)n*1056);
        rp[d] = xs[d];
    }
    if (d < 8) rin[(size_t)n*1056 + 1048 + d] = 0.f;
    for (int h=0; h<4; h++) {
        int cidx = h*256 + d;
        float accS = 0.f;
        #pragma unroll
        for (int j=0;j<3;j++){
            int t = l-2+j;
            if (t>=0) accS += v[(size_t)(n-2+j)*1024 + cidx]*firS[(size_t)cidx*3+j];
        }
        float accL = 0.f;
        #pragma unroll
        for (int j=0;j<31;j++){
            int t = l-30+j;
            if (t>=0) accL += v[(size_t)(n-30+j)*1024 + cidx]*firL[(size_t)cidx*31+j];
        }
        float dv = dlt[(size_t)n*1024 + cidx];
        fs[(size_t)n*1024+cidx]=accS;
        fl[(size_t)n*1024+cidx]=accL;
        float s1 = blockReduceSum(accS, red);
        float s2 = blockReduceSum(accS*accS, red);
        float s3 = blockReduceSum(accL, red);
        float s4 = blockReduceSum(accL*accL, red);
        float s5 = blockReduceSum(dv, red);
        float s6 = blockReduceSum(dv*dv, red);
        if (threadIdx.x==0) {
            float* rp = rin + (size_t)n*1056 + 1024;
            float m1 = s1*(1.f/256.f), m3 = s3*(1.f/256.f), m5 = s5*(1.f/256.f);
            rp[h]    = m1;
            rp[4+h]  = sqrtf(fmaxf(s2*(1.f/256.f) - m1*m1, 0.f));
            rp[8+h]  = m3;
            rp[12+h] = sqrtf(fmaxf(s4*(1.f/256.f) - m3*m3, 0.f));
            rp[16+h] = m5;
            rp[20+h] = sqrtf(fmaxf(s6*(1.f/256.f) - m5*m5, 0.f));
        }
        __syncthreads();
    }
}

// ---------------- router logits + tempered softmax --------------------------
__global__ void __launch_bounds__(256) router_kernel(
    const float* __restrict__ hmid, const float* __restrict__ Wr2,
    const float* __restrict__ br2, const float* __restrict__ ltg,
    float* __restrict__ p)
{
    int n = blockIdx.x;
    __shared__ float hrow[2048];
    __shared__ float lg[12];
    int tid = threadIdx.x;
    for (int i=tid;i<512;i+=256)
        *(float4*)&hrow[i*4] = *(const float4*)(hmid + (size_t)n*2048 + i*4);
    __syncthreads();
    int w = tid>>5, lane = tid&31;
    for (int out = w; out < 12; out += 8) {
        float s=0.f;
        for (int kk=lane; kk<2048; kk+=32) s += hrow[kk]*Wr2[(size_t)kk*12+out];
        #pragma unroll
        for (int o=16;o;o>>=1) s += __shfl_xor_sync(0xffffffffu,s,o);
        if (lane==0) lg[out] = s + br2[out];
    }
    __syncthreads();
    if (tid < 4) {
        int h = tid;
        float tau = expf(ltg[h>>1]);
        float a = lg[h*3+0]/tau, bq = lg[h*3+1]/tau, cq = lg[h*3+2]/tau;
        float m = fmaxf(a, fmaxf(bq,cq));
        float ea=expf(a-m), eb=expf(bq-m), ec=expf(cq-m);
        float inv = 1.f/(ea+eb+ec);
        p[(size_t)n*12 + h*3+0] = ea*inv*0.925f + 0.025f;
        p[(size_t)n*12 + h*3+1] = eb*inv*0.925f + 0.025f;
        p[(size_t)n*12 + h*3+2] = ec*inv*0.925f + 0.025f;
    }
}

// ---------------- gated mix + id path + per-head RMS norm -------------------
__global__ void __launch_bounds__(256) mix_norm_kernel(
    const float* __restrict__ p, const float* __restrict__ fs,
    const float* __restrict__ fl, const float* __restrict__ dlt,
    const float* __restrict__ v, const float* __restrict__ sid,
    const float* __restrict__ alpha_id, const float* __restrict__ onw,
    float* __restrict__ omix)
{
    int n = blockIdx.x;
    int d = threadIdx.x;
    __shared__ float red[8];
    for (int h=0;h<4;h++){
        size_t idx = (size_t)n*1024 + h*256 + d;
        float p0 = p[(size_t)n*12+h*3+0];
        float p1 = p[(size_t)n*12+h*3+1];
        float p2 = p[(size_t)n*12+h*3+2];
        float ids = 0.06f + sigm(alpha_id[h]) * sid[(size_t)n*4+h];
        float o = p0*fs[idx] + p1*fl[idx] + p2*dlt[idx] + ids*v[idx];
        float ss = blockReduceSum(o*o, red);
        float r = rsqrtf(ss*(1.f/256.f) + 1e-5f);
        omix[idx] = o*r*onw[d];
    }
}

extern "C" void kernel_launch(void* const* d_in, const int* in_sizes, int n_in,
                              void* d_out, int out_size) {
    const float* x    = (const float*)d_in[0];
    const float* Wq   = (const float*)d_in[1];
    const float* Wk   = (const float*)d_in[2];
    const float* Wv   = (const float*)d_in[3];
    const float* Wb   = (const float*)d_in[4];
    const float* cq   = (const float*)d_in[5];
    const float* ck   = (const float*)d_in[6];
    const float* cv   = (const float*)d_in[7];
    const float* firS = (const float*)d_in[8];
    const float* firL = (const float*)d_in[9];
    const float* aid  = (const float*)d_in[10];
    const float* Wid  = (const float*)d_in[11];
    const float* bid  = (const float*)d_in[12];
    const float* Wr1  = (const float*)d_in[13];
    const float* br1  = (const float*)d_in[14];
    const float* Wr2  = (const float*)d_in[15];
    const float* br2  = (const float*)d_in[16];
    const float* ltg  = (const float*)d_in[17];
    const float* onw  = (const float*)d_in[19];
    const float* Wo   = (const float*)d_in[20];
    float* out = (float*)d_out;

    void* bufv = nullptr;
    cudaGetSymbolAddress(&bufv, g_buf);
    float* buf = (float*)bufv;
    void* bbufv = nullptr;
    cudaGetSymbolAddress(&bbufv, g_bf);
    unsigned short* bbuf = (unsigned short*)bbufv;

    float* qlin = buf + OFF_QL;
    float* klin = buf + OFF_KL;
    float* vlin = buf + OFF_VL;
    float* qb   = buf + OFF_Q;
    float* kb   = buf + OFF_K;
    float* vb   = buf + OFF_V;
    float* ub   = buf + OFF_U;
    float* wb   = buf + OFF_W;
    float* dlt  = buf + OFF_DELTA;
    float* fsb  = buf + OFF_FS;
    float* flb  = buf + OFF_FL;
    float* omix = buf + OFF_OMIX;
    float* rin  = buf + OFF_RIN;
    float* hmid = buf + OFF_HMID;
    float* attn = buf + OFF_ATTN;
    float* beta = buf + OFF_BETA;
    float* sidb = buf + OFF_SID;
    float* pb   = buf + OFF_P;

    unsigned short* xhi  = bbuf + BOFF_X_HI;
    unsigned short* xlo  = bbuf + BOFF_X_LO;
    unsigned short* omhi = bbuf + BOFF_OM_HI;
    unsigned short* omlo = bbuf + BOFF_OM_LO;
    unsigned short* rihi = bbuf + BOFF_RIN_HI;
    unsigned short* rilo = bbuf + BOFF_RIN_LO;
    unsigned short* wqhi = bbuf + BOFF_WQ_HI;
    unsigned short* wqlo = bbuf + BOFF_WQ_LO;
    unsigned short* wkhi = bbuf + BOFF_WK_HI;
    unsigned short* wklo = bbuf + BOFF_WK_LO;
    unsigned short* wvhi = bbuf + BOFF_WV_HI;
    unsigned short* wvlo = bbuf + BOFF_WV_LO;
    unsigned short* wohi = bbuf + BOFF_WO_HI;
    unsigned short* wolo = bbuf + BOFF_WO_LO;
    unsigned short* w1hi = bbuf + BOFF_W1_HI;
    unsigned short* w1lo = bbuf + BOFF_W1_LO;

    int smem_prep = (3*32*260 + 32*33 + 32) * 4;
    int smem_scan = (4096 + 3*8320 + 1024 + 512) * 4;
    cudaFuncSetAttribute(chunk_prep_kernel, cudaFuncAttributeMaxDynamicSharedMemorySize, smem_prep);
    cudaFuncSetAttribute(scan_kernel, cudaFuncAttributeMaxDynamicSharedMemorySize, smem_scan);
    cudaFuncSetAttribute(tgemm_kernel<0>, cudaFuncAttributeMaxDynamicSharedMemorySize, SMEM_GEMM);
    cudaFuncSetAttribute(tgemm_kernel<1>, cudaFuncAttributeMaxDynamicSharedMemorySize, SMEM_GEMM);

    // ---- convert weights + x ----
    f2bf_split_kernel<<<4096, 256>>>(x, xhi, xlo, 8192*1024/8);
    f2bf_split_kernel<<<512, 256>>>(Wq, wqhi, wqlo, 1024*1024/8);
    f2bf_split_kernel<<<512, 256>>>(Wk, wkhi, wklo, 1024*1024/8);
    f2bf_split_kernel<<<512, 256>>>(Wv, wvhi, wvlo, 1024*1024/8);
    f2bf_split_kernel<<<512, 256>>>(Wo, wohi, wolo, 1024*1024/8);
    f2bf_split_pad_kernel<<<1056, 256>>>(Wr1, w1hi, w1lo);

    dim3 g1(8, 64), blk(256);
    tgemm_kernel<0><<<g1, blk, SMEM_GEMM>>>(xhi, xlo, wqhi, wqlo, nullptr, qlin, NTOK, 1024, 1024);
    tgemm_kernel<0><<<g1, blk, SMEM_GEMM>>>(xhi, xlo, wkhi, wklo, nullptr, klin, NTOK, 1024, 1024);
    tgemm_kernel<0><<<g1, blk, SMEM_GEMM>>>(xhi, xlo, wvhi, wvlo, nullptr, vlin, NTOK, 1024, 1024);
    proj_beta_id_kernel<<<NTOK, 256>>>(x, Wb, Wid, bid, beta, sidb);
    conv_silu_kernel<<<NTOK*4, 256>>>(qlin, cq, qb);
    conv_silu_kernel<<<NTOK*4, 256>>>(klin, ck, kb);
    conv_silu_kernel<<<NTOK*4, 256>>>(vlin, cv, vb);
    chunk_prep_kernel<<<1024, 256, smem_prep>>>(qb, kb, vb, beta, ub, wb, attn);
    scan_kernel<<<128, 512, smem_scan>>>(qb, kb, ub, wb, attn, dlt);
    fir_stats_kernel<<<NTOK, 256>>>(vb, dlt, x, firS, firL, fsb, flb, rin);
    f2bf_split_kernel<<<(8192*1056/8 + 255)/256, 256>>>(rin, rihi, rilo, 8192*1056/8);
    dim3 g2(16, 64);
    tgemm_kernel<1><<<g2, blk, SMEM_GEMM>>>(rihi, rilo, w1hi, w1lo, br1, hmid, NTOK, 2048, 1056);
    router_kernel<<<NTOK, 256>>>(hmid, Wr2, br2, ltg, pb);
    mix_norm_kernel<<<NTOK, 256>>>(pb, fsb, flb, dlt, vb, sidb, aid, onw, omix);
    f2bf_split_kernel<<<4096, 256>>>(omix, omhi, omlo, 8192*1024/8);
    tgemm_kernel<0><<<g1, blk, SMEM_GEMM>>>(omhi, omlo, wohi, wolo, nullptr, out, NTOK, 1024, 1024);
}

// round 6
// speedup vs baseline: 1.8073x; 1.0661x over previous
#include <cuda_runtime.h>
#include <cuda_bf16.h>
#include <math.h>

#define LSEQ 4096
#define NTOK 8192

// ---------------- float scratch offsets ----------------
#define OFF_QL    ((size_t)0)            // 8192 x 3072 fused qkv lin
#define OFF_Q     ((size_t)25165824)
#define OFF_K     ((size_t)33554432)
#define OFF_V     ((size_t)41943040)
#define OFF_U     ((size_t)50331648)
#define OFF_W     ((size_t)58720256)
#define OFF_DELTA ((size_t)67108864)
#define OFF_FS    ((size_t)75497472)
#define OFF_FL    ((size_t)83886080)
#define OFF_HMID  ((size_t)92274688)     // 8192 x 2048
#define OFF_ATTN  ((size_t)109051904)    // 1024 x 1024
#define OFF_BETA  ((size_t)110100480)
#define OFF_SID   ((size_t)110133248)
#define OFF_P     ((size_t)110166016)
#define BUF_TOTAL ((size_t)110264320)

__device__ float g_buf[BUF_TOTAL];

// ---------------- bf16 plane offsets (ushort units) ----------------
#define BOFF_X_HI    ((size_t)0)
#define BOFF_X_LO    ((size_t)8388608)
#define BOFF_OM_HI   ((size_t)16777216)
#define BOFF_OM_LO   ((size_t)25165824)
#define BOFF_RIN_HI  ((size_t)33554432)
#define BOFF_RIN_LO  ((size_t)42205184)
#define BOFF_WQKV_HI ((size_t)50855936)
#define BOFF_WQKV_LO ((size_t)54001664)
#define BOFF_WO_HI   ((size_t)57147392)
#define BOFF_WO_LO   ((size_t)58195968)
#define BOFF_W1_HI   ((size_t)59244544)
#define BOFF_W1_LO   ((size_t)61407232)
#define BBUF_TOTAL   ((size_t)63569920)

__device__ unsigned short g_bf[BBUF_TOTAL];

__device__ __forceinline__ float sigm(float x){ return 1.0f/(1.0f+expf(-x)); }

__device__ __forceinline__ unsigned short f2bf(float f){
    __nv_bfloat16 h = __float2bfloat16(f);
    return *(unsigned short*)&h;
}
__device__ __forceinline__ float bf2f(unsigned short u){
    __nv_bfloat16 h = *(__nv_bfloat16*)&u;
    return __bfloat162float(h);
}

__device__ __forceinline__ float blockReduceSum(float val, float* red) {
    int lane = threadIdx.x & 31, w = threadIdx.x >> 5;
    #pragma unroll
    for (int o=16;o;o>>=1) val += __shfl_xor_sync(0xffffffffu, val, o);
    if (lane==0) red[w]=val;
    __syncthreads();
    if (w==0) {
        float v2 = (lane<8)? red[lane] : 0.f;
        #pragma unroll
        for (int o=4;o;o>>=1) v2 += __shfl_xor_sync(0xffffffffu, v2, o);
        if (lane==0) red[0]=v2;
    }
    __syncthreads();
    float r = red[0];
    __syncthreads();
    return r;
}

#define LDSM_X4(R0,R1,R2,R3,ADDR) \
    asm volatile("ldmatrix.sync.aligned.m8n8.x4.shared.b16 {%0,%1,%2,%3}, [%4];" \
        : "=r"(R0),"=r"(R1),"=r"(R2),"=r"(R3) : "r"(ADDR))
#define LDSM_X4T(R0,R1,R2,R3,ADDR) \
    asm volatile("ldmatrix.sync.aligned.m8n8.x4.trans.shared.b16 {%0,%1,%2,%3}, [%4];" \
        : "=r"(R0),"=r"(R1),"=r"(R2),"=r"(R3) : "r"(ADDR))
#define MMA_BF16(C,A0,A1,A2,A3,B0,B1) \
    asm volatile("mma.sync.aligned.m16n8k16.row.col.f32.bf16.bf16.f32 " \
        "{%0,%1,%2,%3},{%4,%5,%6,%7},{%8,%9},{%0,%1,%2,%3};" \
        : "+f"(C[0]),"+f"(C[1]),"+f"(C[2]),"+f"(C[3]) \
        : "r"(A0),"r"(A1),"r"(A2),"r"(A3),"r"(B0),"r"(B1))

// ---------------- fp32 -> bf16 hi/lo split (8 elems/thread) ----------------
__global__ void __launch_bounds__(256) f2bf_split_kernel(
    const float* __restrict__ src, unsigned short* __restrict__ hi,
    unsigned short* __restrict__ lo, int n8)
{
    int idx = blockIdx.x*256 + threadIdx.x;
    if (idx >= n8) return;
    const float4* s = (const float4*)(src) + (size_t)idx*2;
    float4 v0 = s[0], v1 = s[1];
    float f[8] = {v0.x,v0.y,v0.z,v0.w,v1.x,v1.y,v1.z,v1.w};
    unsigned hh[4], ll[4];
    #pragma unroll
    for (int i=0;i<4;i++){
        unsigned short h0 = f2bf(f[i*2]), h1 = f2bf(f[i*2+1]);
        unsigned short l0 = f2bf(f[i*2]-bf2f(h0)), l1 = f2bf(f[i*2+1]-bf2f(h1));
        hh[i] = (unsigned)h0 | ((unsigned)h1<<16);
        ll[i] = (unsigned)l0 | ((unsigned)l1<<16);
    }
    *(uint4*)(hi + (size_t)idx*8) = make_uint4(hh[0],hh[1],hh[2],hh[3]);
    *(uint4*)(lo + (size_t)idx*8) = make_uint4(ll[0],ll[1],ll[2],ll[3]);
}

// ---------------- pack Wq|Wk|Wv -> [1024][3072] bf16 hi/lo ----------------
__global__ void __launch_bounds__(256) f2bf_pack_qkv_kernel(
    const float* __restrict__ Wq, const float* __restrict__ Wk,
    const float* __restrict__ Wv,
    unsigned short* __restrict__ hi, unsigned short* __restrict__ lo)
{
    int idx = blockIdx.x*256 + threadIdx.x;
    if (idx >= 1024*3072/8) return;
    int e0 = idx*8;
    int row = e0 / 3072;
    int col = e0 % 3072;
    int s = col >> 10;
    const float* src = (s==0)? Wq : (s==1)? Wk : Wv;
    const float4* sp = (const float4*)(src + (size_t)row*1024 + (col & 1023));
    float4 v0 = sp[0], v1 = sp[1];
    float f[8] = {v0.x,v0.y,v0.z,v0.w,v1.x,v1.y,v1.z,v1.w};
    unsigned hh[4], ll[4];
    #pragma unroll
    for (int i=0;i<4;i++){
        unsigned short h0 = f2bf(f[i*2]), h1 = f2bf(f[i*2+1]);
        unsigned short l0 = f2bf(f[i*2]-bf2f(h0)), l1 = f2bf(f[i*2+1]-bf2f(h1));
        hh[i] = (unsigned)h0 | ((unsigned)h1<<16);
        ll[i] = (unsigned)l0 | ((unsigned)l1<<16);
    }
    *(uint4*)(hi + (size_t)idx*8) = make_uint4(hh[0],hh[1],hh[2],hh[3]);
    *(uint4*)(lo + (size_t)idx*8) = make_uint4(ll[0],ll[1],ll[2],ll[3]);
}

// ---------------- Wr1 [1048][2048] -> padded [1056][2048] bf16 split -------
__global__ void __launch_bounds__(256) f2bf_split_pad_kernel(
    const float* __restrict__ src, unsigned short* __restrict__ hi,
    unsigned short* __restrict__ lo)
{
    int idx = blockIdx.x*256 + threadIdx.x;
    if (idx >= 1056*256) return;
    int row = (idx*8) >> 11;
    unsigned hh[4]={0,0,0,0}, ll[4]={0,0,0,0};
    if (row < 1048) {
        const float4* s = (const float4*)(src) + (size_t)idx*2;
        float4 v0 = s[0], v1 = s[1];
        float f[8] = {v0.x,v0.y,v0.z,v0.w,v1.x,v1.y,v1.z,v1.w};
        #pragma unroll
        for (int i=0;i<4;i++){
            unsigned short h0 = f2bf(f[i*2]), h1 = f2bf(f[i*2+1]);
            unsigned short l0 = f2bf(f[i*2]-bf2f(h0)), l1 = f2bf(f[i*2+1]-bf2f(h1));
            hh[i] = (unsigned)h0 | ((unsigned)h1<<16);
            ll[i] = (unsigned)l0 | ((unsigned)l1<<16);
        }
    }
    *(uint4*)(hi + (size_t)idx*8) = make_uint4(hh[0],hh[1],hh[2],hh[3]);
    *(uint4*)(lo + (size_t)idx*8) = make_uint4(ll[0],ll[1],ll[2],ll[3]);
}

// ---------------- tensor-core GEMM on preconverted bf16 hi/lo planes -------
#define SMEM_GEMM ((2*128*72 + 2*64*136)*2)
template<int EPI>
__global__ void __launch_bounds__(256,2) tgemm_kernel(
    const unsigned short* __restrict__ Ahi, const unsigned short* __restrict__ Alo,
    const unsigned short* __restrict__ Bhi, const unsigned short* __restrict__ Blo,
    const float* __restrict__ bias, float* __restrict__ C,
    int M, int N, int K)
{
    extern __shared__ unsigned short sm[];
    unsigned short* Ah = sm;
    unsigned short* Al = Ah + 128*72;
    unsigned short* Bh = Al + 128*72;
    unsigned short* Bl = Bh + 64*136;

    const int tid  = threadIdx.x;
    const int lane = tid & 31;
    const int warp = tid >> 5;
    const int warp_m = warp & 3;
    const int warp_n = warp >> 2;
    const int brow = blockIdx.y * 128;
    const int bcol = blockIdx.x * 128;

    float c[2][8][4];
    #pragma unroll
    for (int i=0;i<2;i++)
        #pragma unroll
        for (int j=0;j<8;j++)
            #pragma unroll
            for (int t=0;t<4;t++) c[i][j][t]=0.f;

    const unsigned sAh = (unsigned)__cvta_generic_to_shared(Ah);
    const unsigned sAl = (unsigned)__cvta_generic_to_shared(Al);
    const unsigned sBh = (unsigned)__cvta_generic_to_shared(Bh);
    const unsigned sBl = (unsigned)__cvta_generic_to_shared(Bl);

    const int a_row = tid >> 1;
    const int a_col0 = (tid & 1) * 32;
    const int b_row = tid >> 2;
    const int b_col0 = (tid & 3) * 32;

    const unsigned short* Ahg = Ahi + (size_t)(brow + a_row)*K + a_col0;
    const unsigned short* Alg = Alo + (size_t)(brow + a_row)*K + a_col0;
    const unsigned short* Bhg = Bhi + (size_t)b_row*N + bcol + b_col0;
    const unsigned short* Blg = Blo + (size_t)b_row*N + bcol + b_col0;

    for (int kt = 0; kt < K; kt += 64) {
        #pragma unroll
        for (int c4=0;c4<4;c4++){
            int col = a_col0 + c4*8;
            *(uint4*)&Ah[a_row*72 + col] = *(const uint4*)(Ahg + kt + c4*8);
            *(uint4*)&Al[a_row*72 + col] = *(const uint4*)(Alg + kt + c4*8);
        }
        #pragma unroll
        for (int c4=0;c4<4;c4++){
            int col = b_col0 + c4*8;
            *(uint4*)&Bh[b_row*136 + col] = *(const uint4*)(Bhg + (size_t)kt*N + c4*8);
            *(uint4*)&Bl[b_row*136 + col] = *(const uint4*)(Blg + (size_t)kt*N + c4*8);
        }
        __syncthreads();

        #pragma unroll
        for (int ks = 0; ks < 4; ks++) {
            unsigned ah[2][4], al[2][4];
            #pragma unroll
            for (int mt = 0; mt < 2; mt++) {
                int ar = warp_m*32 + mt*16 + (lane & 15);
                int ac = ((lane >> 4) << 3) + ks*16;
                unsigned off = (unsigned)(ar*72 + ac)*2u;
                LDSM_X4(ah[mt][0],ah[mt][1],ah[mt][2],ah[mt][3], sAh + off);
                LDSM_X4(al[mt][0],al[mt][1],al[mt][2],al[mt][3], sAl + off);
            }
            #pragma unroll
            for (int np = 0; np < 4; np++) {
                unsigned bh[4], bl[4];
                int bk = (lane & 7) + (((lane >> 3) & 1) << 3) + ks*16;
                int bn = warp_n*64 + np*16 + ((lane >> 4) << 3);
                unsigned off = (unsigned)(bk*136 + bn)*2u;
                LDSM_X4T(bh[0],bh[1],bh[2],bh[3], sBh + off);
                LDSM_X4T(bl[0],bl[1],bl[2],bl[3], sBl + off);
                #pragma unroll
                for (int mt = 0; mt < 2; mt++) {
                    #pragma unroll
                    for (int jj = 0; jj < 2; jj++) {
                        int j = np*2 + jj, o = jj*2;
                        MMA_BF16(c[mt][j], ah[mt][0],ah[mt][1],ah[mt][2],ah[mt][3],
                                 bh[o], bh[o+1]);
                        MMA_BF16(c[mt][j], ah[mt][0],ah[mt][1],ah[mt][2],ah[mt][3],
                                 bl[o], bl[o+1]);
                        MMA_BF16(c[mt][j], al[mt][0],al[mt][1],al[mt][2],al[mt][3],
                                 bh[o], bh[o+1]);
                    }
                }
            }
        }
        __syncthreads();
    }

    #pragma unroll
    for (int mt = 0; mt < 2; mt++) {
        int r0 = brow + warp_m*32 + mt*16 + (lane >> 2);
        #pragma unroll
        for (int j = 0; j < 8; j++) {
            int col = bcol + warp_n*64 + j*8 + (lane & 3)*2;
            float2 v0 = make_float2(c[mt][j][0], c[mt][j][1]);
            float2 v1 = make_float2(c[mt][j][2], c[mt][j][3]);
            if (EPI == 1) {
                float b0 = bias[col], b1 = bias[col+1];
                v0.x += b0; v0.y += b1; v1.x += b0; v1.y += b1;
                v0.x = 0.5f*v0.x*(1.0f+erff(v0.x*0.70710678118654752f));
                v0.y = 0.5f*v0.y*(1.0f+erff(v0.y*0.70710678118654752f));
                v1.x = 0.5f*v1.x*(1.0f+erff(v1.x*0.70710678118654752f));
                v1.y = 0.5f*v1.y*(1.0f+erff(v1.y*0.70710678118654752f));
            }
            *(float2*)&C[(size_t)r0*N + col]     = v0;
            *(float2*)&C[(size_t)(r0+8)*N + col] = v1;
        }
    }
}

// ---------------- beta + id-gate projections ----------------
__global__ void __launch_bounds__(256) proj_beta_id_kernel(
    const float* __restrict__ x, const float* __restrict__ Wb,
    const float* __restrict__ Wid, const float* __restrict__ bid,
    float* __restrict__ beta, float* __restrict__ sid)
{
    int n = blockIdx.x;
    __shared__ float xs[1024];
    int tid = threadIdx.x;
    *(float4*)&xs[tid*4] = *(const float4*)(x + (size_t)n*1024 + tid*4);
    __syncthreads();
    int w = tid >> 5, lane = tid & 31;
    float s = 0.f;
    if (w < 4) { for (int d=lane; d<1024; d+=32) s += xs[d]*Wb[(size_t)d*4 + w]; }
    else       { int h=w-4; for (int d=lane; d<1024; d+=32) s += xs[d]*Wid[(size_t)d*4 + h]; }
    #pragma unroll
    for (int o=16;o;o>>=1) s += __shfl_xor_sync(0xffffffffu,s,o);
    if (lane==0) {
        if (w<4) beta[(size_t)n*4+w] = sigm(s);
        else     sid[(size_t)n*4+(w-4)] = sigm(s + bid[w-4]);
    }
}

// ---------------- fused causal depthwise conv (k=4) + silu, 3 streams -------
__global__ void __launch_bounds__(256) conv_silu_kernel(
    const float* __restrict__ in, const float* __restrict__ cq,
    const float* __restrict__ ck, const float* __restrict__ cv,
    float* __restrict__ qb, float* __restrict__ kb, float* __restrict__ vb)
{
    long long gidx = (long long)blockIdx.x*256 + threadIdx.x;
    int s = (int)(gidx >> 23);          // 8192*1024 = 2^23 per stream
    int idx = (int)(gidx & ((1<<23)-1));
    int c = idx & 1023;
    int n = idx >> 10;
    int l = n & (LSEQ-1);
    const float* cw = (s==0)? cq : (s==1)? ck : cv;
    float* out = (s==0)? qb : (s==1)? kb : vb;
    float4 wv = *(const float4*)(cw + (size_t)c*4);
    float wj[4] = {wv.x, wv.y, wv.z, wv.w};
    float acc = 0.f;
    #pragma unroll
    for (int j=0;j<4;j++){
        int t = l - 3 + j;
        if (t >= 0) acc += in[(size_t)(n-3+j)*3072 + s*1024 + c] * wj[j];
    }
    out[idx] = acc / (1.0f + expf(-acc));
}

// ---------------- per-chunk prep: l2norm, T, u, w, attn ----------------
__global__ void __launch_bounds__(256) chunk_prep_kernel(
    float* __restrict__ q, float* __restrict__ k, const float* __restrict__ v,
    const float* __restrict__ beta, float* __restrict__ u, float* __restrict__ w,
    float* __restrict__ attn)
{
    extern __shared__ float sh[];
    float* qs = sh;
    float* ks = qs + 32*260;
    float* vs = ks + 32*260;
    float* T  = vs + 32*260;
    float* bet = T + 32*33;
    int ci = blockIdx.x;
    int c = ci & 127;
    int h = (ci >> 7) & 3;
    int b = ci >> 9;
    int tid = threadIdx.x;
    size_t base = ((size_t)(b*LSEQ + c*32))*1024 + (size_t)h*256;
    for (int i=tid; i<2048; i+=256) {
        int r = i>>6; int d4 = (i&63)<<2;
        size_t off = base + (size_t)r*1024 + d4;
        *(float4*)&qs[r*260+d4] = *(const float4*)(q + off);
        *(float4*)&ks[r*260+d4] = *(const float4*)(k + off);
        *(float4*)&vs[r*260+d4] = *(const float4*)(v + off);
    }
    if (tid < 32) bet[tid] = beta[(size_t)(b*LSEQ + c*32 + tid)*4 + h];
    __syncthreads();
    {
        int wi = tid>>5, lane = tid&31;
        for (int r = wi*4; r < wi*4+4; r++) {
            float sq=0.f, sk2=0.f;
            for (int dd=lane; dd<256; dd+=32){
                float a=qs[r*260+dd]; sq+=a*a;
                float bb=ks[r*260+dd]; sk2+=bb*bb;
            }
            #pragma unroll
            for (int o=16;o;o>>=1){
                sq+=__shfl_xor_sync(0xffffffffu,sq,o);
                sk2+=__shfl_xor_sync(0xffffffffu,sk2,o);
            }
            float rq = rsqrtf(sq+1e-6f), rk = rsqrtf(sk2+1e-6f);
            for (int dd=lane; dd<256; dd+=32){ qs[r*260+dd]*=rq; ks[r*260+dd]*=rk; }
        }
    }
    __syncthreads();
    size_t abase = (size_t)ci*1024;
    for (int pp=tid; pp<1024; pp+=256) {
        int i = pp>>5, j = pp&31;
        float dkk=0.f, dqq=0.f;
        for (int dd=0; dd<256; dd++){
            float kj = ks[j*260+dd];
            dkk += ks[i*260+dd]*kj;
            dqq += qs[i*260+dd]*kj;
        }
        T[i*33+j] = (j<i)? (-bet[i]*dkk) : 0.f;
        attn[abase+pp] = (j<=i)? dqq : 0.f;
    }
    __syncthreads();
    if (tid<32) {
        int lane = tid;
        for (int i=1;i<32;i++){
            float rowv = T[i*33+lane];
            float add = 0.f;
            for (int j=0;j<i;j++) add += __shfl_sync(0xffffffffu, rowv, j)*T[j*33+lane];
            T[i*33+lane] = rowv + add;
            __syncwarp();
        }
        T[lane*33+lane] += 1.0f;
    }
    __syncthreads();
    for (int pp=tid; pp<8192; pp+=256){
        int r = pp>>8, dd = pp&255;
        float su=0.f, sw=0.f;
        #pragma unroll
        for (int j=0;j<32;j++){
            float tj = T[r*33+j]*bet[j];
            su += tj*vs[j*260+dd];
            sw += tj*ks[j*260+dd];
        }
        size_t off = base + (size_t)r*1024 + dd;
        u[off]=su; w[off]=sw;
        q[off]=qs[r*260+dd]; k[off]=ks[r*260+dd];
    }
}

// ---------------- sequential chunk scan, dv-sliced (16 slices of 16) -------
__global__ void __launch_bounds__(512) scan_kernel(
    const float* __restrict__ q, const float* __restrict__ k,
    const float* __restrict__ u, const float* __restrict__ w,
    const float* __restrict__ attn, float* __restrict__ outp)
{
    extern __shared__ float sh[];
    float* S  = sh;
    float* qs = S + 4096;
    float* ks = qs + 8320;
    float* ws = ks + 8320;
    float* as = ws + 8320;
    float* u2 = as + 1024;
    int bid = blockIdx.x;
    int sl = bid & 15;
    int bh = bid >> 4;
    int h = bh & 3, b = bh >> 2;
    int tid = threadIdx.x;
    for (int i=tid;i<4096;i+=512) S[i]=0.f;
    const int iRow = tid >> 4;
    const int q1 = tid & 15;
    const int dd0 = tid >> 2;
    const int c4 = (tid & 3) * 4;
    size_t abh = (size_t)bh * 128 * 1024;
    for (int c=0;c<128;c++){
        size_t base = ((size_t)(b*LSEQ + c*32))*1024 + (size_t)h*256;
        __syncthreads();
        for (int i=tid;i<2048;i+=512){
            int r=i>>6; int d4=(i&63)<<2;
            size_t off = base + (size_t)r*1024 + d4;
            *(float4*)&qs[r*260+d4] = *(const float4*)(q+off);
            *(float4*)&ks[r*260+d4] = *(const float4*)(k+off);
            *(float4*)&ws[r*260+d4] = *(const float4*)(w+off);
        }
        if (tid < 256)
            *(float4*)&as[tid*4] = *(const float4*)(attn + abh + (size_t)c*1024 + tid*4);
        __syncthreads();
        float au = u[base + (size_t)iRow*1024 + sl*16 + q1];
        float ao = 0.f;
        #pragma unroll 8
        for (int dd=0; dd<256; dd++){
            float Sv = S[dd*16+q1];
            au -= ws[iRow*260+dd]*Sv;
            ao += qs[iRow*260+dd]*Sv;
        }
        u2[iRow*16+q1] = au;
        __syncthreads();
        #pragma unroll
        for (int j=0;j<32;j++) ao += as[iRow*32+j]*u2[j*16+q1];
        outp[base + (size_t)iRow*1024 + sl*16 + q1] = ao;
        #pragma unroll
        for (int s2=0; s2<2; s2++){
            int dd = dd0 + s2*128;
            float4 Sv = *(float4*)&S[dd*16+c4];
            #pragma unroll 8
            for (int j=0;j<32;j++){
                float kv = ks[j*260+dd];
                float4 uv = *(float4*)&u2[j*16+c4];
                Sv.x += kv*uv.x; Sv.y += kv*uv.y; Sv.z += kv*uv.z; Sv.w += kv*uv.w;
            }
            *(float4*)&S[dd*16+c4] = Sv;
        }
    }
}

// ---------------- FIR + stats + router input (smem-tiled, bf16 out) --------
// grid: (NTOK/32, 4). 256 threads. dyn smem: 62*256*4 = 63488 B.
__global__ void __launch_bounds__(256) fir_stats_kernel(
    const float* __restrict__ v, const float* __restrict__ dlt,
    const unsigned short* __restrict__ xhi, const unsigned short* __restrict__ xlo,
    const float* __restrict__ firS, const float* __restrict__ firL,
    float* __restrict__ fs, float* __restrict__ fl,
    unsigned short* __restrict__ rihi, unsigned short* __restrict__ rilo)
{
    extern __shared__ float vsm[];           // [62][256]
    __shared__ float red[8][6];
    const int h  = blockIdx.y;
    const int t0 = blockIdx.x * 32;
    const int l0 = t0 & (LSEQ-1);
    const int tid = threadIdx.x;
    const int d = tid;
    const int cidx = h*256 + d;
    const int lane = tid & 31, wrp = tid >> 5;

    // x-part copy + pad (head-0 blocks only)
    if (h == 0) {
        for (int i = tid; i < 32*128; i += 256) {
            int tt = i >> 7, c8 = (i & 127) << 3;
            size_t dst = (size_t)(t0+tt)*1056 + c8;
            size_t src = (size_t)(t0+tt)*1024 + c8;
            *(uint4*)(rihi + dst) = *(const uint4*)(xhi + src);
            *(uint4*)(rilo + dst) = *(const uint4*)(xlo + src);
        }
        if (tid < 32) {
            size_t dst = (size_t)(t0+tid)*1056 + 1048;
            *(uint4*)(rihi + dst) = make_uint4(0,0,0,0);
            *(uint4*)(rilo + dst) = make_uint4(0,0,0,0);
        }
    }

    // stage 62 v rows into smem
    for (int i = tid; i < 62*64; i += 256) {
        int r = i >> 6; int c4 = (i & 63) << 2;
        float4 val = make_float4(0.f,0.f,0.f,0.f);
        if (l0 - 30 + r >= 0)
            val = *(const float4*)(v + (size_t)(t0-30+r)*1024 + h*256 + c4);
        *(float4*)&vsm[r*256 + c4] = val;
    }
    __syncthreads();

    float fS[3], fL[31];
    #pragma unroll
    for (int j=0;j<3;j++)  fS[j] = firS[(size_t)cidx*3+j];
    #pragma unroll
    for (int j=0;j<31;j++) fL[j] = firL[(size_t)cidx*31+j];

    for (int tt = 0; tt < 32; tt++) {
        int row = tt + 30;
        int n = t0 + tt;
        float accS = 0.f;
        #pragma unroll
        for (int j=0;j<3;j++) accS += vsm[(row-2+j)*256 + d]*fS[j];
        float accL = 0.f;
        #pragma unroll
        for (int j=0;j<31;j++) accL += vsm[(row-30+j)*256 + d]*fL[j];
        float dv = dlt[(size_t)n*1024 + cidx];
        fs[(size_t)n*1024 + cidx] = accS;
        fl[(size_t)n*1024 + cidx] = accL;

        float vals[6] = {accS, accS*accS, accL, accL*accL, dv, dv*dv};
        #pragma unroll
        for (int k2=0;k2<6;k2++){
            float s = vals[k2];
            #pragma unroll
            for (int o=16;o;o>>=1) s += __shfl_xor_sync(0xffffffffu, s, o);
            if (lane==0) red[wrp][k2] = s;
        }
        __syncthreads();
        if (tid == 0) {
            float s[6];
            #pragma unroll
            for (int k2=0;k2<6;k2++){
                float a = 0.f;
                #pragma unroll
                for (int ww=0;ww<8;ww++) a += red[ww][k2];
                s[k2] = a;
            }
            float m1 = s[0]*(1.f/256.f), m3 = s[2]*(1.f/256.f), m5 = s[4]*(1.f/256.f);
            float o[6];
            o[0]=m1;
            o[1]=sqrtf(fmaxf(s[1]*(1.f/256.f)-m1*m1,0.f));
            o[2]=m3;
            o[3]=sqrtf(fmaxf(s[3]*(1.f/256.f)-m3*m3,0.f));
            o[4]=m5;
            o[5]=sqrtf(fmaxf(s[5]*(1.f/256.f)-m5*m5,0.f));
            size_t rb = (size_t)n*1056 + 1024 + h;
            #pragma unroll
            for (int k2=0;k2<6;k2++){
                unsigned short hh = f2bf(o[k2]);
                rihi[rb + k2*4] = hh;
                rilo[rb + k2*4] = f2bf(o[k2]-bf2f(hh));
            }
        }
        __syncthreads();
    }
}

// ---------------- router logits + tempered softmax --------------------------
__global__ void __launch_bounds__(256) router_kernel(
    const float* __restrict__ hmid, const float* __restrict__ Wr2,
    const float* __restrict__ br2, const float* __restrict__ ltg,
    float* __restrict__ p)
{
    int n = blockIdx.x;
    __shared__ float hrow[2048];
    __shared__ float lg[12];
    int tid = threadIdx.x;
    for (int i=tid;i<512;i+=256)
        *(float4*)&hrow[i*4] = *(const float4*)(hmid + (size_t)n*2048 + i*4);
    __syncthreads();
    int w = tid>>5, lane = tid&31;
    for (int out = w; out < 12; out += 8) {
        float s=0.f;
        for (int kk=lane; kk<2048; kk+=32) s += hrow[kk]*Wr2[(size_t)kk*12+out];
        #pragma unroll
        for (int o=16;o;o>>=1) s += __shfl_xor_sync(0xffffffffu,s,o);
        if (lane==0) lg[out] = s + br2[out];
    }
    __syncthreads();
    if (tid < 4) {
        int h = tid;
        float tau = expf(ltg[h>>1]);
        float a = lg[h*3+0]/tau, bq = lg[h*3+1]/tau, cq = lg[h*3+2]/tau;
        float m = fmaxf(a, fmaxf(bq,cq));
        float ea=expf(a-m), eb=expf(bq-m), ec=expf(cq-m);
        float inv = 1.f/(ea+eb+ec);
        p[(size_t)n*12 + h*3+0] = ea*inv*0.925f + 0.025f;
        p[(size_t)n*12 + h*3+1] = eb*inv*0.925f + 0.025f;
        p[(size_t)n*12 + h*3+2] = ec*inv*0.925f + 0.025f;
    }
}

// ---------------- gated mix + id + RMS norm -> bf16 hi/lo -------------------
__global__ void __launch_bounds__(256) mix_norm_kernel(
    const float* __restrict__ p, const float* __restrict__ fs,
    const float* __restrict__ fl, const float* __restrict__ dlt,
    const float* __restrict__ v, const float* __restrict__ sid,
    const float* __restrict__ alpha_id, const float* __restrict__ onw,
    unsigned short* __restrict__ omhi, unsigned short* __restrict__ omlo)
{
    int n = blockIdx.x;
    int d = threadIdx.x;
    __shared__ float red[8];
    for (int h=0;h<4;h++){
        size_t idx = (size_t)n*1024 + h*256 + d;
        float p0 = p[(size_t)n*12+h*3+0];
        float p1 = p[(size_t)n*12+h*3+1];
        float p2 = p[(size_t)n*12+h*3+2];
        float ids = 0.06f + sigm(alpha_id[h]) * sid[(size_t)n*4+h];
        float o = p0*fs[idx] + p1*fl[idx] + p2*dlt[idx] + ids*v[idx];
        float ss = blockReduceSum(o*o, red);
        float r = rsqrtf(ss*(1.f/256.f) + 1e-5f);
        float val = o*r*onw[d];
        unsigned short hh = f2bf(val);
        omhi[idx] = hh;
        omlo[idx] = f2bf(val - bf2f(hh));
    }
}

extern "C" void kernel_launch(void* const* d_in, const int* in_sizes, int n_in,
                              void* d_out, int out_size) {
    const float* x    = (const float*)d_in[0];
    const float* Wq   = (const float*)d_in[1];
    const float* Wk   = (const float*)d_in[2];
    const float* Wv   = (const float*)d_in[3];
    const float* Wb   = (const float*)d_in[4];
    const float* cq   = (const float*)d_in[5];
    const float* ck   = (const float*)d_in[6];
    const float* cv   = (const float*)d_in[7];
    const float* firS = (const float*)d_in[8];
    const float* firL = (const float*)d_in[9];
    const float* aid  = (const float*)d_in[10];
    const float* Wid  = (const float*)d_in[11];
    const float* bid  = (const float*)d_in[12];
    const float* Wr1  = (const float*)d_in[13];
    const float* br1  = (const float*)d_in[14];
    const float* Wr2  = (const float*)d_in[15];
    const float* br2  = (const float*)d_in[16];
    const float* ltg  = (const float*)d_in[17];
    const float* onw  = (const float*)d_in[19];
    const float* Wo   = (const float*)d_in[20];
    float* out = (float*)d_out;

    void* bufv = nullptr;
    cudaGetSymbolAddress(&bufv, g_buf);
    float* buf = (float*)bufv;
    void* bbufv = nullptr;
    cudaGetSymbolAddress(&bbufv, g_bf);
    unsigned short* bbuf = (unsigned short*)bbufv;

    float* qkvlin = buf + OFF_QL;
    float* qb   = buf + OFF_Q;
    float* kb   = buf + OFF_K;
    float* vb   = buf + OFF_V;
    float* ub   = buf + OFF_U;
    float* wb   = buf + OFF_W;
    float* dlt  = buf + OFF_DELTA;
    float* fsb  = buf + OFF_FS;
    float* flb  = buf + OFF_FL;
    float* hmid = buf + OFF_HMID;
    float* attn = buf + OFF_ATTN;
    float* beta = buf + OFF_BETA;
    float* sidb = buf + OFF_SID;
    float* pb   = buf + OFF_P;

    unsigned short* xhi  = bbuf + BOFF_X_HI;
    unsigned short* xlo  = bbuf + BOFF_X_LO;
    unsigned short* omhi = bbuf + BOFF_OM_HI;
    unsigned short* omlo = bbuf + BOFF_OM_LO;
    unsigned short* rihi = bbuf + BOFF_RIN_HI;
    unsigned short* rilo = bbuf + BOFF_RIN_LO;
    unsigned short* wqkvhi = bbuf + BOFF_WQKV_HI;
    unsigned short* wqkvlo = bbuf + BOFF_WQKV_LO;
    unsigned short* wohi = bbuf + BOFF_WO_HI;
    unsigned short* wolo = bbuf + BOFF_WO_LO;
    unsigned short* w1hi = bbuf + BOFF_W1_HI;
    unsigned short* w1lo = bbuf + BOFF_W1_LO;

    int smem_prep = (3*32*260 + 32*33 + 32) * 4;
    int smem_scan = (4096 + 3*8320 + 1024 + 512) * 4;
    int smem_fir  = 62*256*4;
    cudaFuncSetAttribute(chunk_prep_kernel, cudaFuncAttributeMaxDynamicSharedMemorySize, smem_prep);
    cudaFuncSetAttribute(scan_kernel, cudaFuncAttributeMaxDynamicSharedMemorySize, smem_scan);
    cudaFuncSetAttribute(fir_stats_kernel, cudaFuncAttributeMaxDynamicSharedMemorySize, smem_fir);
    cudaFuncSetAttribute(tgemm_kernel<0>, cudaFuncAttributeMaxDynamicSharedMemorySize, SMEM_GEMM);
    cudaFuncSetAttribute(tgemm_kernel<1>, cudaFuncAttributeMaxDynamicSharedMemorySize, SMEM_GEMM);

    f2bf_split_kernel<<<4096, 256>>>(x, xhi, xlo, 8192*1024/8);
    f2bf_pack_qkv_kernel<<<1536, 256>>>(Wq, Wk, Wv, wqkvhi, wqkvlo);
    f2bf_split_kernel<<<512, 256>>>(Wo, wohi, wolo, 1024*1024/8);
    f2bf_split_pad_kernel<<<1056, 256>>>(Wr1, w1hi, w1lo);

    dim3 blk(256);
    dim3 gqkv(24, 64);
    tgemm_kernel<0><<<gqkv, blk, SMEM_GEMM>>>(xhi, xlo, wqkvhi, wqkvlo, nullptr, qkvlin, NTOK, 3072, 1024);
    proj_beta_id_kernel<<<NTOK, 256>>>(x, Wb, Wid, bid, beta, sidb);
    conv_silu_kernel<<<3*NTOK*4, 256>>>(qkvlin, cq, ck, cv, qb, kb, vb);
    chunk_prep_kernel<<<1024, 256, smem_prep>>>(qb, kb, vb, beta, ub, wb, attn);
    scan_kernel<<<128, 512, smem_scan>>>(qb, kb, ub, wb, attn, dlt);
    dim3 gfir(NTOK/32, 4);
    fir_stats_kernel<<<gfir, 256, smem_fir>>>(vb, dlt, xhi, xlo, firS, firL, fsb, flb, rihi, rilo);
    dim3 g2(16, 64);
    tgemm_kernel<1><<<g2, blk, SMEM_GEMM>>>(rihi, rilo, w1hi, w1lo, br1, hmid, NTOK, 2048, 1056);
    router_kernel<<<NTOK, 256>>>(hmid, Wr2, br2, ltg, pb);
    mix_norm_kernel<<<NTOK, 256>>>(pb, fsb, flb, dlt, vb, sidb, aid, onw, omhi, omlo);
    dim3 g1(8, 64);
    tgemm_kernel<0><<<g1, blk, SMEM_GEMM>>>(omhi, omlo, wohi, wolo, nullptr, out, NTOK, 1024, 1024);
}

// round 7
// speedup vs baseline: 1.9374x; 1.0719x over previous
#include <cuda_runtime.h>
#include <cuda_bf16.h>
#include <math.h>

#define LSEQ 4096
#define NTOK 8192

// ---------------- float scratch offsets ----------------
#define OFF_QL    ((size_t)0)            // 8192 x 3072 fused qkv lin
#define OFF_Q     ((size_t)25165824)
#define OFF_K     ((size_t)33554432)
#define OFF_V     ((size_t)41943040)
#define OFF_U     ((size_t)50331648)
#define OFF_W     ((size_t)58720256)
#define OFF_DELTA ((size_t)67108864)
#define OFF_FS    ((size_t)75497472)
#define OFF_FL    ((size_t)83886080)
#define OFF_HMID  ((size_t)92274688)     // 8192 x 2048
#define OFF_ATTN  ((size_t)109051904)    // 1024 x 1024
#define OFF_BETA  ((size_t)110100480)
#define OFF_SID   ((size_t)110133248)
#define OFF_P     ((size_t)110166016)
#define BUF_TOTAL ((size_t)110264320)

__device__ float g_buf[BUF_TOTAL];

// ---------------- bf16 plane offsets (ushort units) ----------------
#define BOFF_X_HI    ((size_t)0)
#define BOFF_X_LO    ((size_t)8388608)
#define BOFF_OM_HI   ((size_t)16777216)
#define BOFF_OM_LO   ((size_t)25165824)
#define BOFF_RIN_HI  ((size_t)33554432)
#define BOFF_RIN_LO  ((size_t)42205184)
#define BOFF_WQKV_HI ((size_t)50855936)
#define BOFF_WQKV_LO ((size_t)54001664)
#define BOFF_WO_HI   ((size_t)57147392)
#define BOFF_WO_LO   ((size_t)58195968)
#define BOFF_W1_HI   ((size_t)59244544)
#define BOFF_W1_LO   ((size_t)61407232)
#define BBUF_TOTAL   ((size_t)63569920)

__device__ unsigned short g_bf[BBUF_TOTAL];

__device__ __forceinline__ float sigm(float x){ return 1.0f/(1.0f+expf(-x)); }

__device__ __forceinline__ unsigned short f2bf(float f){
    __nv_bfloat16 h = __float2bfloat16(f);
    return *(unsigned short*)&h;
}
__device__ __forceinline__ float bf2f(unsigned short u){
    __nv_bfloat16 h = *(__nv_bfloat16*)&u;
    return __bfloat162float(h);
}

__device__ __forceinline__ float blockReduceSum(float val, float* red) {
    int lane = threadIdx.x & 31, w = threadIdx.x >> 5;
    #pragma unroll
    for (int o=16;o;o>>=1) val += __shfl_xor_sync(0xffffffffu, val, o);
    if (lane==0) red[w]=val;
    __syncthreads();
    if (w==0) {
        float v2 = (lane<8)? red[lane] : 0.f;
        #pragma unroll
        for (int o=4;o;o>>=1) v2 += __shfl_xor_sync(0xffffffffu, v2, o);
        if (lane==0) red[0]=v2;
    }
    __syncthreads();
    float r = red[0];
    __syncthreads();
    return r;
}

#define LDSM_X4(R0,R1,R2,R3,ADDR) \
    asm volatile("ldmatrix.sync.aligned.m8n8.x4.shared.b16 {%0,%1,%2,%3}, [%4];" \
        : "=r"(R0),"=r"(R1),"=r"(R2),"=r"(R3) : "r"(ADDR))
#define LDSM_X4T(R0,R1,R2,R3,ADDR) \
    asm volatile("ldmatrix.sync.aligned.m8n8.x4.trans.shared.b16 {%0,%1,%2,%3}, [%4];" \
        : "=r"(R0),"=r"(R1),"=r"(R2),"=r"(R3) : "r"(ADDR))
#define MMA_BF16(C,A0,A1,A2,A3,B0,B1) \
    asm volatile("mma.sync.aligned.m16n8k16.row.col.f32.bf16.bf16.f32 " \
        "{%0,%1,%2,%3},{%4,%5,%6,%7},{%8,%9},{%0,%1,%2,%3};" \
        : "+f"(C[0]),"+f"(C[1]),"+f"(C[2]),"+f"(C[3]) \
        : "r"(A0),"r"(A1),"r"(A2),"r"(A3),"r"(B0),"r"(B1))
#define CP16(DST,SRC) \
    asm volatile("cp.async.cg.shared.global [%0], [%1], 16;\n" :: "r"(DST), "l"(SRC))

// GEMM pipeline layout constants (ushort elems / byte offsets)
#define AL_OFFB  (128*40*2)
#define B_OFFB   (2*128*40*2)
#define BL_OFFB  (32*136*2)
#define STAGE_B  (2*128*40*2 + 2*32*136*2)   // 37888 bytes
#define SMEM_GEMM (2*STAGE_B)                // 75776 bytes

// ---------------- fp32 -> bf16 hi/lo split (8 elems/thread) ----------------
__global__ void __launch_bounds__(256) f2bf_split_kernel(
    const float* __restrict__ src, unsigned short* __restrict__ hi,
    unsigned short* __restrict__ lo, int n8)
{
    int idx = blockIdx.x*256 + threadIdx.x;
    if (idx >= n8) return;
    const float4* s = (const float4*)(src) + (size_t)idx*2;
    float4 v0 = s[0], v1 = s[1];
    float f[8] = {v0.x,v0.y,v0.z,v0.w,v1.x,v1.y,v1.z,v1.w};
    unsigned hh[4], ll[4];
    #pragma unroll
    for (int i=0;i<4;i++){
        unsigned short h0 = f2bf(f[i*2]), h1 = f2bf(f[i*2+1]);
        unsigned short l0 = f2bf(f[i*2]-bf2f(h0)), l1 = f2bf(f[i*2+1]-bf2f(h1));
        hh[i] = (unsigned)h0 | ((unsigned)h1<<16);
        ll[i] = (unsigned)l0 | ((unsigned)l1<<16);
    }
    *(uint4*)(hi + (size_t)idx*8) = make_uint4(hh[0],hh[1],hh[2],hh[3]);
    *(uint4*)(lo + (size_t)idx*8) = make_uint4(ll[0],ll[1],ll[2],ll[3]);
}

// ---------------- pack Wq|Wk|Wv -> [1024][3072] bf16 hi/lo ----------------
__global__ void __launch_bounds__(256) f2bf_pack_qkv_kernel(
    const float* __restrict__ Wq, const float* __restrict__ Wk,
    const float* __restrict__ Wv,
    unsigned short* __restrict__ hi, unsigned short* __restrict__ lo)
{
    int idx = blockIdx.x*256 + threadIdx.x;
    if (idx >= 1024*3072/8) return;
    int e0 = idx*8;
    int row = e0 / 3072;
    int col = e0 % 3072;
    int s = col >> 10;
    const float* src = (s==0)? Wq : (s==1)? Wk : Wv;
    const float4* sp = (const float4*)(src + (size_t)row*1024 + (col & 1023));
    float4 v0 = sp[0], v1 = sp[1];
    float f[8] = {v0.x,v0.y,v0.z,v0.w,v1.x,v1.y,v1.z,v1.w};
    unsigned hh[4], ll[4];
    #pragma unroll
    for (int i=0;i<4;i++){
        unsigned short h0 = f2bf(f[i*2]), h1 = f2bf(f[i*2+1]);
        unsigned short l0 = f2bf(f[i*2]-bf2f(h0)), l1 = f2bf(f[i*2+1]-bf2f(h1));
        hh[i] = (unsigned)h0 | ((unsigned)h1<<16);
        ll[i] = (unsigned)l0 | ((unsigned)l1<<16);
    }
    *(uint4*)(hi + (size_t)idx*8) = make_uint4(hh[0],hh[1],hh[2],hh[3]);
    *(uint4*)(lo + (size_t)idx*8) = make_uint4(ll[0],ll[1],ll[2],ll[3]);
}

// ---------------- Wr1 [1048][2048] -> padded [1056][2048] bf16 split -------
__global__ void __launch_bounds__(256) f2bf_split_pad_kernel(
    const float* __restrict__ src, unsigned short* __restrict__ hi,
    unsigned short* __restrict__ lo)
{
    int idx = blockIdx.x*256 + threadIdx.x;
    if (idx >= 1056*256) return;
    int row = (idx*8) >> 11;
    unsigned hh[4]={0,0,0,0}, ll[4]={0,0,0,0};
    if (row < 1048) {
        const float4* s = (const float4*)(src) + (size_t)idx*2;
        float4 v0 = s[0], v1 = s[1];
        float f[8] = {v0.x,v0.y,v0.z,v0.w,v1.x,v1.y,v1.z,v1.w};
        #pragma unroll
        for (int i=0;i<4;i++){
            unsigned short h0 = f2bf(f[i*2]), h1 = f2bf(f[i*2+1]);
            unsigned short l0 = f2bf(f[i*2]-bf2f(h0)), l1 = f2bf(f[i*2+1]-bf2f(h1));
            hh[i] = (unsigned)h0 | ((unsigned)h1<<16);
            ll[i] = (unsigned)l0 | ((unsigned)l1<<16);
        }
    }
    *(uint4*)(hi + (size_t)idx*8) = make_uint4(hh[0],hh[1],hh[2],hh[3]);
    *(uint4*)(lo + (size_t)idx*8) = make_uint4(ll[0],ll[1],ll[2],ll[3]);
}

// ---------------- tensor-core GEMM, cp.async 2-stage pipeline --------------
// 256 threads, 8 warps (4x2), warp tile 32x64, CTA 128x128, K-tile 32.
template<int EPI>
__global__ void __launch_bounds__(256,2) tgemm_kernel(
    const unsigned short* __restrict__ Ahi, const unsigned short* __restrict__ Alo,
    const unsigned short* __restrict__ Bhi, const unsigned short* __restrict__ Blo,
    const float* __restrict__ bias, float* __restrict__ C,
    int M, int N, int K)
{
    extern __shared__ unsigned short sm[];
    const int tid  = threadIdx.x;
    const int lane = tid & 31;
    const int warp = tid >> 5;
    const int warp_m = warp & 3;
    const int warp_n = warp >> 2;
    const int brow = blockIdx.y * 128;
    const int bcol = blockIdx.x * 128;

    float c[2][8][4];
    #pragma unroll
    for (int i=0;i<2;i++)
        #pragma unroll
        for (int j=0;j<8;j++)
            #pragma unroll
            for (int t=0;t<4;t++) c[i][j][t]=0.f;

    const unsigned sb = (unsigned)__cvta_generic_to_shared(sm);

    // cp.async fill indices
    const int ar = tid >> 1;               // 0..127
    const int ac = (tid & 1) * 16;         // ushort col 0 or 16
    const int br = tid >> 3;               // 0..31
    const int bc = (tid & 7) * 16;         // ushort col 0..112

    const unsigned short* Ahg = Ahi + (size_t)(brow + ar)*K + ac;
    const unsigned short* Alg = Alo + (size_t)(brow + ar)*K + ac;
    const unsigned short* Bhg = Bhi + (size_t)br*N + bcol + bc;
    const unsigned short* Blg = Blo + (size_t)br*N + bcol + bc;

    const unsigned a_dst = sb + (unsigned)(ar*40 + ac)*2u;
    const unsigned b_dst = sb + B_OFFB + (unsigned)(br*136 + bc)*2u;

    #define ISSUE_STAGE(KT, BUF) do {                                   \
        unsigned a0 = a_dst + (BUF)*STAGE_B;                             \
        CP16(a0,            Ahg + (KT));                                 \
        CP16(a0 + 16u,      Ahg + (KT) + 8);                             \
        CP16(a0 + AL_OFFB,       Alg + (KT));                            \
        CP16(a0 + AL_OFFB + 16u, Alg + (KT) + 8);                        \
        unsigned b0 = b_dst + (BUF)*STAGE_B;                             \
        const unsigned short* bhp = Bhg + (size_t)(KT)*N;                \
        const unsigned short* blp = Blg + (size_t)(KT)*N;                \
        CP16(b0,            bhp);                                        \
        CP16(b0 + 16u,      bhp + 8);                                    \
        CP16(b0 + BL_OFFB,       blp);                                   \
        CP16(b0 + BL_OFFB + 16u, blp + 8);                               \
        asm volatile("cp.async.commit_group;\n" ::);                     \
    } while(0)

    const int T = K >> 5;
    ISSUE_STAGE(0, 0);

    for (int t = 0; t < T; t++) {
        if (t + 1 < T) {
            ISSUE_STAGE((t+1)*32, (t+1)&1);
            asm volatile("cp.async.wait_group 1;\n" ::);
        } else {
            asm volatile("cp.async.wait_group 0;\n" ::);
        }
        __syncthreads();

        const unsigned s0 = sb + (unsigned)(t&1)*STAGE_B;
        #pragma unroll
        for (int ks = 0; ks < 2; ks++) {
            unsigned ah[2][4], al[2][4];
            #pragma unroll
            for (int mt = 0; mt < 2; mt++) {
                int ar2 = warp_m*32 + mt*16 + (lane & 15);
                int ac2 = ((lane >> 4) << 3) + ks*16;
                unsigned off = s0 + (unsigned)(ar2*40 + ac2)*2u;
                LDSM_X4(ah[mt][0],ah[mt][1],ah[mt][2],ah[mt][3], off);
                LDSM_X4(al[mt][0],al[mt][1],al[mt][2],al[mt][3], off + AL_OFFB);
            }
            #pragma unroll
            for (int np = 0; np < 4; np++) {
                unsigned bh[4], bl[4];
                int bk = (lane & 7) + (((lane >> 3) & 1) << 3) + ks*16;
                int bn = warp_n*64 + np*16 + ((lane >> 4) << 3);
                unsigned off = s0 + B_OFFB + (unsigned)(bk*136 + bn)*2u;
                LDSM_X4T(bh[0],bh[1],bh[2],bh[3], off);
                LDSM_X4T(bl[0],bl[1],bl[2],bl[3], off + BL_OFFB);
                #pragma unroll
                for (int mt = 0; mt < 2; mt++) {
                    #pragma unroll
                    for (int jj = 0; jj < 2; jj++) {
                        int j = np*2 + jj, o = jj*2;
                        MMA_BF16(c[mt][j], ah[mt][0],ah[mt][1],ah[mt][2],ah[mt][3],
                                 bh[o], bh[o+1]);
                        MMA_BF16(c[mt][j], ah[mt][0],ah[mt][1],ah[mt][2],ah[mt][3],
                                 bl[o], bl[o+1]);
                        MMA_BF16(c[mt][j], al[mt][0],al[mt][1],al[mt][2],al[mt][3],
                                 bh[o], bh[o+1]);
                    }
                }
            }
        }
        __syncthreads();
    }
    #undef ISSUE_STAGE

    #pragma unroll
    for (int mt = 0; mt < 2; mt++) {
        int r0 = brow + warp_m*32 + mt*16 + (lane >> 2);
        #pragma unroll
        for (int j = 0; j < 8; j++) {
            int col = bcol + warp_n*64 + j*8 + (lane & 3)*2;
            float2 v0 = make_float2(c[mt][j][0], c[mt][j][1]);
            float2 v1 = make_float2(c[mt][j][2], c[mt][j][3]);
            if (EPI == 1) {
                float b0 = bias[col], b1 = bias[col+1];
                v0.x += b0; v0.y += b1; v1.x += b0; v1.y += b1;
                v0.x = 0.5f*v0.x*(1.0f+erff(v0.x*0.70710678118654752f));
                v0.y = 0.5f*v0.y*(1.0f+erff(v0.y*0.70710678118654752f));
                v1.x = 0.5f*v1.x*(1.0f+erff(v1.x*0.70710678118654752f));
                v1.y = 0.5f*v1.y*(1.0f+erff(v1.y*0.70710678118654752f));
            }
            *(float2*)&C[(size_t)r0*N + col]     = v0;
            *(float2*)&C[(size_t)(r0+8)*N + col] = v1;
        }
    }
}

// ---------------- beta + id-gate projections ----------------
__global__ void __launch_bounds__(256) proj_beta_id_kernel(
    const float* __restrict__ x, const float* __restrict__ Wb,
    const float* __restrict__ Wid, const float* __restrict__ bid,
    float* __restrict__ beta, float* __restrict__ sid)
{
    int n = blockIdx.x;
    __shared__ float xs[1024];
    int tid = threadIdx.x;
    *(float4*)&xs[tid*4] = *(const float4*)(x + (size_t)n*1024 + tid*4);
    __syncthreads();
    int w = tid >> 5, lane = tid & 31;
    float s = 0.f;
    if (w < 4) { for (int d=lane; d<1024; d+=32) s += xs[d]*Wb[(size_t)d*4 + w]; }
    else       { int h=w-4; for (int d=lane; d<1024; d+=32) s += xs[d]*Wid[(size_t)d*4 + h]; }
    #pragma unroll
    for (int o=16;o;o>>=1) s += __shfl_xor_sync(0xffffffffu,s,o);
    if (lane==0) {
        if (w<4) beta[(size_t)n*4+w] = sigm(s);
        else     sid[(size_t)n*4+(w-4)] = sigm(s + bid[w-4]);
    }
}

// ---------------- fused causal depthwise conv (k=4) + silu, 3 streams -------
__global__ void __launch_bounds__(256) conv_silu_kernel(
    const float* __restrict__ in, const float* __restrict__ cq,
    const float* __restrict__ ck, const float* __restrict__ cv,
    float* __restrict__ qb, float* __restrict__ kb, float* __restrict__ vb)
{
    long long gidx = (long long)blockIdx.x*256 + threadIdx.x;
    int s = (int)(gidx >> 23);
    int idx = (int)(gidx & ((1<<23)-1));
    int c = idx & 1023;
    int n = idx >> 10;
    int l = n & (LSEQ-1);
    const float* cw = (s==0)? cq : (s==1)? ck : cv;
    float* out = (s==0)? qb : (s==1)? kb : vb;
    float4 wv = *(const float4*)(cw + (size_t)c*4);
    float wj[4] = {wv.x, wv.y, wv.z, wv.w};
    float acc = 0.f;
    #pragma unroll
    for (int j=0;j<4;j++){
        int t = l - 3 + j;
        if (t >= 0) acc += in[(size_t)(n-3+j)*3072 + s*1024 + c] * wj[j];
    }
    out[idx] = acc / (1.0f + expf(-acc));
}

// ---------------- per-chunk prep: l2norm, T, u, w, attn ----------------
__global__ void __launch_bounds__(256) chunk_prep_kernel(
    float* __restrict__ q, float* __restrict__ k, const float* __restrict__ v,
    const float* __restrict__ beta, float* __restrict__ u, float* __restrict__ w,
    float* __restrict__ attn)
{
    extern __shared__ float sh[];
    float* qs = sh;
    float* ks = qs + 32*260;
    float* vs = ks + 32*260;
    float* T  = vs + 32*260;
    float* bet = T + 32*33;
    int ci = blockIdx.x;
    int c = ci & 127;
    int h = (ci >> 7) & 3;
    int b = ci >> 9;
    int tid = threadIdx.x;
    size_t base = ((size_t)(b*LSEQ + c*32))*1024 + (size_t)h*256;
    for (int i=tid; i<2048; i+=256) {
        int r = i>>6; int d4 = (i&63)<<2;
        size_t off = base + (size_t)r*1024 + d4;
        *(float4*)&qs[r*260+d4] = *(const float4*)(q + off);
        *(float4*)&ks[r*260+d4] = *(const float4*)(k + off);
        *(float4*)&vs[r*260+d4] = *(const float4*)(v + off);
    }
    if (tid < 32) bet[tid] = beta[(size_t)(b*LSEQ + c*32 + tid)*4 + h];
    __syncthreads();
    {
        int wi = tid>>5, lane = tid&31;
        for (int r = wi*4; r < wi*4+4; r++) {
            float sq=0.f, sk2=0.f;
            for (int dd=lane; dd<256; dd+=32){
                float a=qs[r*260+dd]; sq+=a*a;
                float bb=ks[r*260+dd]; sk2+=bb*bb;
            }
            #pragma unroll
            for (int o=16;o;o>>=1){
                sq+=__shfl_xor_sync(0xffffffffu,sq,o);
                sk2+=__shfl_xor_sync(0xffffffffu,sk2,o);
            }
            float rq = rsqrtf(sq+1e-6f), rk = rsqrtf(sk2+1e-6f);
            for (int dd=lane; dd<256; dd+=32){ qs[r*260+dd]*=rq; ks[r*260+dd]*=rk; }
        }
    }
    __syncthreads();
    size_t abase = (size_t)ci*1024;
    for (int pp=tid; pp<1024; pp+=256) {
        int i = pp>>5, j = pp&31;
        float dkk=0.f, dqq=0.f;
        for (int dd=0; dd<256; dd++){
            float kj = ks[j*260+dd];
            dkk += ks[i*260+dd]*kj;
            dqq += qs[i*260+dd]*kj;
        }
        T[i*33+j] = (j<i)? (-bet[i]*dkk) : 0.f;
        attn[abase+pp] = (j<=i)? dqq : 0.f;
    }
    __syncthreads();
    if (tid<32) {
        int lane = tid;
        for (int i=1;i<32;i++){
            float rowv = T[i*33+lane];
            float add = 0.f;
            for (int j=0;j<i;j++) add += __shfl_sync(0xffffffffu, rowv, j)*T[j*33+lane];
            T[i*33+lane] = rowv + add;
            __syncwarp();
        }
        T[lane*33+lane] += 1.0f;
    }
    __syncthreads();
    for (int pp=tid; pp<8192; pp+=256){
        int r = pp>>8, dd = pp&255;
        float su=0.f, sw=0.f;
        #pragma unroll
        for (int j=0;j<32;j++){
            float tj = T[r*33+j]*bet[j];
            su += tj*vs[j*260+dd];
            sw += tj*ks[j*260+dd];
        }
        size_t off = base + (size_t)r*1024 + dd;
        u[off]=su; w[off]=sw;
        q[off]=qs[r*260+dd]; k[off]=ks[r*260+dd];
    }
}

// ---------------- sequential chunk scan, dv-sliced (16 slices of 16) -------
__global__ void __launch_bounds__(512) scan_kernel(
    const float* __restrict__ q, const float* __restrict__ k,
    const float* __restrict__ u, const float* __restrict__ w,
    const float* __restrict__ attn, float* __restrict__ outp)
{
    extern __shared__ float sh[];
    float* S  = sh;
    float* qs = S + 4096;
    float* ks = qs + 8320;
    float* ws = ks + 8320;
    float* as = ws + 8320;
    float* u2 = as + 1024;
    int bid = blockIdx.x;
    int sl = bid & 15;
    int bh = bid >> 4;
    int h = bh & 3, b = bh >> 2;
    int tid = threadIdx.x;
    for (int i=tid;i<4096;i+=512) S[i]=0.f;
    const int iRow = tid >> 4;
    const int q1 = tid & 15;
    const int dd0 = tid >> 2;
    const int c4 = (tid & 3) * 4;
    size_t abh = (size_t)bh * 128 * 1024;
    for (int c=0;c<128;c++){
        size_t base = ((size_t)(b*LSEQ + c*32))*1024 + (size_t)h*256;
        __syncthreads();
        for (int i=tid;i<2048;i+=512){
            int r=i>>6; int d4=(i&63)<<2;
            size_t off = base + (size_t)r*1024 + d4;
            *(float4*)&qs[r*260+d4] = *(const float4*)(q+off);
            *(float4*)&ks[r*260+d4] = *(const float4*)(k+off);
            *(float4*)&ws[r*260+d4] = *(const float4*)(w+off);
        }
        if (tid < 256)
            *(float4*)&as[tid*4] = *(const float4*)(attn + abh + (size_t)c*1024 + tid*4);
        __syncthreads();
        float au = u[base + (size_t)iRow*1024 + sl*16 + q1];
        float ao = 0.f;
        #pragma unroll 8
        for (int dd=0; dd<256; dd++){
            float Sv = S[dd*16+q1];
            au -= ws[iRow*260+dd]*Sv;
            ao += qs[iRow*260+dd]*Sv;
        }
        u2[iRow*16+q1] = au;
        __syncthreads();
        #pragma unroll
        for (int j=0;j<32;j++) ao += as[iRow*32+j]*u2[j*16+q1];
        outp[base + (size_t)iRow*1024 + sl*16 + q1] = ao;
        #pragma unroll
        for (int s2=0; s2<2; s2++){
            int dd = dd0 + s2*128;
            float4 Sv = *(float4*)&S[dd*16+c4];
            #pragma unroll 8
            for (int j=0;j<32;j++){
                float kv = ks[j*260+dd];
                float4 uv = *(float4*)&u2[j*16+c4];
                Sv.x += kv*uv.x; Sv.y += kv*uv.y; Sv.z += kv*uv.z; Sv.w += kv*uv.w;
            }
            *(float4*)&S[dd*16+c4] = Sv;
        }
    }
}

// ---------------- FIR + stats + router input (smem-tiled, bf16 out) --------
__global__ void __launch_bounds__(256) fir_stats_kernel(
    const float* __restrict__ v, const float* __restrict__ dlt,
    const unsigned short* __restrict__ xhi, const unsigned short* __restrict__ xlo,
    const float* __restrict__ firS, const float* __restrict__ firL,
    float* __restrict__ fs, float* __restrict__ fl,
    unsigned short* __restrict__ rihi, unsigned short* __restrict__ rilo)
{
    extern __shared__ float vsm[];
    __shared__ float red[8][6];
    const int h  = blockIdx.y;
    const int t0 = blockIdx.x * 32;
    const int l0 = t0 & (LSEQ-1);
    const int tid = threadIdx.x;
    const int d = tid;
    const int cidx = h*256 + d;
    const int lane = tid & 31, wrp = tid >> 5;

    if (h == 0) {
        for (int i = tid; i < 32*128; i += 256) {
            int tt = i >> 7, c8 = (i & 127) << 3;
            size_t dst = (size_t)(t0+tt)*1056 + c8;
            size_t src = (size_t)(t0+tt)*1024 + c8;
            *(uint4*)(rihi + dst) = *(const uint4*)(xhi + src);
            *(uint4*)(rilo + dst) = *(const uint4*)(xlo + src);
        }
        if (tid < 32) {
            size_t dst = (size_t)(t0+tid)*1056 + 1048;
            *(uint4*)(rihi + dst) = make_uint4(0,0,0,0);
            *(uint4*)(rilo + dst) = make_uint4(0,0,0,0);
        }
    }

    for (int i = tid; i < 62*64; i += 256) {
        int r = i >> 6; int c4 = (i & 63) << 2;
        float4 val = make_float4(0.f,0.f,0.f,0.f);
        if (l0 - 30 + r >= 0)
            val = *(const float4*)(v + (size_t)(t0-30+r)*1024 + h*256 + c4);
        *(float4*)&vsm[r*256 + c4] = val;
    }
    __syncthreads();

    float fS[3], fL[31];
    #pragma unroll
    for (int j=0;j<3;j++)  fS[j] = firS[(size_t)cidx*3+j];
    #pragma unroll
    for (int j=0;j<31;j++) fL[j] = firL[(size_t)cidx*31+j];

    for (int tt = 0; tt < 32; tt++) {
        int row = tt + 30;
        int n = t0 + tt;
        float accS = 0.f;
        #pragma unroll
        for (int j=0;j<3;j++) accS += vsm[(row-2+j)*256 + d]*fS[j];
        float accL = 0.f;
        #pragma unroll
        for (int j=0;j<31;j++) accL += vsm[(row-30+j)*256 + d]*fL[j];
        float dv = dlt[(size_t)n*1024 + cidx];
        fs[(size_t)n*1024 + cidx] = accS;
        fl[(size_t)n*1024 + cidx] = accL;

        float vals[6] = {accS, accS*accS, accL, accL*accL, dv, dv*dv};
        #pragma unroll
        for (int k2=0;k2<6;k2++){
            float s = vals[k2];
            #pragma unroll
            for (int o=16;o;o>>=1) s += __shfl_xor_sync(0xffffffffu, s, o);
            if (lane==0) red[wrp][k2] = s;
        }
        __syncthreads();
        if (tid == 0) {
            float s[6];
            #pragma unroll
            for (int k2=0;k2<6;k2++){
                float a = 0.f;
                #pragma unroll
                for (int ww=0;ww<8;ww++) a += red[ww][k2];
                s[k2] = a;
            }
            float m1 = s[0]*(1.f/256.f), m3 = s[2]*(1.f/256.f), m5 = s[4]*(1.f/256.f);
            float o[6];
            o[0]=m1;
            o[1]=sqrtf(fmaxf(s[1]*(1.f/256.f)-m1*m1,0.f));
            o[2]=m3;
            o[3]=sqrtf(fmaxf(s[3]*(1.f/256.f)-m3*m3,0.f));
            o[4]=m5;
            o[5]=sqrtf(fmaxf(s[5]*(1.f/256.f)-m5*m5,0.f));
            size_t rb = (size_t)n*1056 + 1024 + h;
            #pragma unroll
            for (int k2=0;k2<6;k2++){
                unsigned short hh = f2bf(o[k2]);
                rihi[rb + k2*4] = hh;
                rilo[rb + k2*4] = f2bf(o[k2]-bf2f(hh));
            }
        }
        __syncthreads();
    }
}

// ---------------- router logits + tempered softmax --------------------------
__global__ void __launch_bounds__(256) router_kernel(
    const float* __restrict__ hmid, const float* __restrict__ Wr2,
    const float* __restrict__ br2, const float* __restrict__ ltg,
    float* __restrict__ p)
{
    int n = blockIdx.x;
    __shared__ float hrow[2048];
    __shared__ float lg[12];
    int tid = threadIdx.x;
    for (int i=tid;i<512;i+=256)
        *(float4*)&hrow[i*4] = *(const float4*)(hmid + (size_t)n*2048 + i*4);
    __syncthreads();
    int w = tid>>5, lane = tid&31;
    for (int out = w; out < 12; out += 8) {
        float s=0.f;
        for (int kk=lane; kk<2048; kk+=32) s += hrow[kk]*Wr2[(size_t)kk*12+out];
        #pragma unroll
        for (int o=16;o;o>>=1) s += __shfl_xor_sync(0xffffffffu,s,o);
        if (lane==0) lg[out] = s + br2[out];
    }
    __syncthreads();
    if (tid < 4) {
        int h = tid;
        float tau = expf(ltg[h>>1]);
        float a = lg[h*3+0]/tau, bq = lg[h*3+1]/tau, cq = lg[h*3+2]/tau;
        float m = fmaxf(a, fmaxf(bq,cq));
        float ea=expf(a-m), eb=expf(bq-m), ec=expf(cq-m);
        float inv = 1.f/(ea+eb+ec);
        p[(size_t)n*12 + h*3+0] = ea*inv*0.925f + 0.025f;
        p[(size_t)n*12 + h*3+1] = eb*inv*0.925f + 0.025f;
        p[(size_t)n*12 + h*3+2] = ec*inv*0.925f + 0.025f;
    }
}

// ---------------- gated mix + id + RMS norm -> bf16 hi/lo -------------------
__global__ void __launch_bounds__(256) mix_norm_kernel(
    const float* __restrict__ p, const float* __restrict__ fs,
    const float* __restrict__ fl, const float* __restrict__ dlt,
    const float* __restrict__ v, const float* __restrict__ sid,
    const float* __restrict__ alpha_id, const float* __restrict__ onw,
    unsigned short* __restrict__ omhi, unsigned short* __restrict__ omlo)
{
    int n = blockIdx.x;
    int d = threadIdx.x;
    __shared__ float red[8];
    for (int h=0;h<4;h++){
        size_t idx = (size_t)n*1024 + h*256 + d;
        float p0 = p[(size_t)n*12+h*3+0];
        float p1 = p[(size_t)n*12+h*3+1];
        float p2 = p[(size_t)n*12+h*3+2];
        float ids = 0.06f + sigm(alpha_id[h]) * sid[(size_t)n*4+h];
        float o = p0*fs[idx] + p1*fl[idx] + p2*dlt[idx] + ids*v[idx];
        float ss = blockReduceSum(o*o, red);
        float r = rsqrtf(ss*(1.f/256.f) + 1e-5f);
        float val = o*r*onw[d];
        unsigned short hh = f2bf(val);
        omhi[idx] = hh;
        omlo[idx] = f2bf(val - bf2f(hh));
    }
}

extern "C" void kernel_launch(void* const* d_in, const int* in_sizes, int n_in,
                              void* d_out, int out_size) {
    const float* x    = (const float*)d_in[0];
    const float* Wq   = (const float*)d_in[1];
    const float* Wk   = (const float*)d_in[2];
    const float* Wv   = (const float*)d_in[3];
    const float* Wb   = (const float*)d_in[4];
    const float* cq   = (const float*)d_in[5];
    const float* ck   = (const float*)d_in[6];
    const float* cv   = (const float*)d_in[7];
    const float* firS = (const float*)d_in[8];
    const float* firL = (const float*)d_in[9];
    const float* aid  = (const float*)d_in[10];
    const float* Wid  = (const float*)d_in[11];
    const float* bid  = (const float*)d_in[12];
    const float* Wr1  = (const float*)d_in[13];
    const float* br1  = (const float*)d_in[14];
    const float* Wr2  = (const float*)d_in[15];
    const float* br2  = (const float*)d_in[16];
    const float* ltg  = (const float*)d_in[17];
    const float* onw  = (const float*)d_in[19];
    const float* Wo   = (const float*)d_in[20];
    float* out = (float*)d_out;

    void* bufv = nullptr;
    cudaGetSymbolAddress(&bufv, g_buf);
    float* buf = (float*)bufv;
    void* bbufv = nullptr;
    cudaGetSymbolAddress(&bbufv, g_bf);
    unsigned short* bbuf = (unsigned short*)bbufv;

    float* qkvlin = buf + OFF_QL;
    float* qb   = buf + OFF_Q;
    float* kb   = buf + OFF_K;
    float* vb   = buf + OFF_V;
    float* ub   = buf + OFF_U;
    float* wb   = buf + OFF_W;
    float* dlt  = buf + OFF_DELTA;
    float* fsb  = buf + OFF_FS;
    float* flb  = buf + OFF_FL;
    float* hmid = buf + OFF_HMID;
    float* attn = buf + OFF_ATTN;
    float* beta = buf + OFF_BETA;
    float* sidb = buf + OFF_SID;
    float* pb   = buf + OFF_P;

    unsigned short* xhi  = bbuf + BOFF_X_HI;
    unsigned short* xlo  = bbuf + BOFF_X_LO;
    unsigned short* omhi = bbuf + BOFF_OM_HI;
    unsigned short* omlo = bbuf + BOFF_OM_LO;
    unsigned short* rihi = bbuf + BOFF_RIN_HI;
    unsigned short* rilo = bbuf + BOFF_RIN_LO;
    unsigned short* wqkvhi = bbuf + BOFF_WQKV_HI;
    unsigned short* wqkvlo = bbuf + BOFF_WQKV_LO;
    unsigned short* wohi = bbuf + BOFF_WO_HI;
    unsigned short* wolo = bbuf + BOFF_WO_LO;
    unsigned short* w1hi = bbuf + BOFF_W1_HI;
    unsigned short* w1lo = bbuf + BOFF_W1_LO;

    int smem_prep = (3*32*260 + 32*33 + 32) * 4;
    int smem_scan = (4096 + 3*8320 + 1024 + 512) * 4;
    int smem_fir  = 62*256*4;
    cudaFuncSetAttribute(chunk_prep_kernel, cudaFuncAttributeMaxDynamicSharedMemorySize, smem_prep);
    cudaFuncSetAttribute(scan_kernel, cudaFuncAttributeMaxDynamicSharedMemorySize, smem_scan);
    cudaFuncSetAttribute(fir_stats_kernel, cudaFuncAttributeMaxDynamicSharedMemorySize, smem_fir);
    cudaFuncSetAttribute(tgemm_kernel<0>, cudaFuncAttributeMaxDynamicSharedMemorySize, SMEM_GEMM);
    cudaFuncSetAttribute(tgemm_kernel<1>, cudaFuncAttributeMaxDynamicSharedMemorySize, SMEM_GEMM);

    f2bf_split_kernel<<<4096, 256>>>(x, xhi, xlo, 8192*1024/8);
    f2bf_pack_qkv_kernel<<<1536, 256>>>(Wq, Wk, Wv, wqkvhi, wqkvlo);
    f2bf_split_kernel<<<512, 256>>>(Wo, wohi, wolo, 1024*1024/8);
    f2bf_split_pad_kernel<<<1056, 256>>>(Wr1, w1hi, w1lo);

    dim3 blk(256);
    dim3 gqkv(24, 64);
    tgemm_kernel<0><<<gqkv, blk, SMEM_GEMM>>>(xhi, xlo, wqkvhi, wqkvlo, nullptr, qkvlin, NTOK, 3072, 1024);
    proj_beta_id_kernel<<<NTOK, 256>>>(x, Wb, Wid, bid, beta, sidb);
    conv_silu_kernel<<<3*NTOK*4, 256>>>(qkvlin, cq, ck, cv, qb, kb, vb);
    chunk_prep_kernel<<<1024, 256, smem_prep>>>(qb, kb, vb, beta, ub, wb, attn);
    scan_kernel<<<128, 512, smem_scan>>>(qb, kb, ub, wb, attn, dlt);
    dim3 gfir(NTOK/32, 4);
    fir_stats_kernel<<<gfir, 256, smem_fir>>>(vb, dlt, xhi, xlo, firS, firL, fsb, flb, rihi, rilo);
    dim3 g2(16, 64);
    tgemm_kernel<1><<<g2, blk, SMEM_GEMM>>>(rihi, rilo, w1hi, w1lo, br1, hmid, NTOK, 2048, 1056);
    router_kernel<<<NTOK, 256>>>(hmid, Wr2, br2, ltg, pb);
    mix_norm_kernel<<<NTOK, 256>>>(pb, fsb, flb, dlt, vb, sidb, aid, onw, omhi, omlo);
    dim3 g1(8, 64);
    tgemm_kernel<0><<<g1, blk, SMEM_GEMM>>>(omhi, omlo, wohi, wolo, nullptr, out, NTOK, 1024, 1024);
}

// round 9
// speedup vs baseline: 2.0104x; 1.0377x over previous
#include <cuda_runtime.h>
#include <cuda_bf16.h>
#include <math.h>

#define LSEQ 4096
#define NTOK 8192

// ---------------- float scratch offsets ----------------
#define OFF_QL     ((size_t)0)            // 8192 x 3200 fused qkv+beta+id lin
#define OFF_Q      ((size_t)26214400)
#define OFF_K      ((size_t)34603008)
#define OFF_V      ((size_t)42991616)
#define OFF_U      ((size_t)51380224)
#define OFF_W      ((size_t)59768832)
#define OFF_DELTA  ((size_t)68157440)
#define OFF_FS     ((size_t)76546048)
#define OFF_FL     ((size_t)84934656)
#define OFF_LOGITS ((size_t)93323264)     // 8192 x 12
#define OFF_ATTN   ((size_t)93421568)     // 1024 x 1024
#define OFF_BETA   ((size_t)94470144)
#define OFF_SID    ((size_t)94502912)
#define OFF_P      ((size_t)94535680)
#define BUF_TOTAL  ((size_t)94633984)

__device__ float g_buf[BUF_TOTAL];

// ---------------- bf16 plane offsets (ushort units) ----------------
#define BOFF_X_HI     ((size_t)0)
#define BOFF_X_LO     ((size_t)8388608)
#define BOFF_OM_HI    ((size_t)16777216)
#define BOFF_OM_LO    ((size_t)25165824)
#define BOFF_ST_HI    ((size_t)33554432)   // 8192 x 64 stats
#define BOFF_ST_LO    ((size_t)34078720)
#define BOFF_WQKV_HI  ((size_t)34603008)   // 1024 x 3200
#define BOFF_WQKV_LO  ((size_t)37879808)
#define BOFF_WO_HI    ((size_t)41156608)
#define BOFF_WO_LO    ((size_t)42205184)
#define BOFF_W1_HI    ((size_t)43253760)   // 1088 x 2048
#define BOFF_W1_LO    ((size_t)45481984)
#define BBUF_TOTAL    ((size_t)47710208)

__device__ unsigned short g_bf[BBUF_TOTAL];

__device__ __forceinline__ float sigm(float x){ return 1.0f/(1.0f+expf(-x)); }

__device__ __forceinline__ unsigned short f2bf(float f){
    __nv_bfloat16 h = __float2bfloat16(f);
    return *(unsigned short*)&h;
}
__device__ __forceinline__ float bf2f(unsigned short u){
    __nv_bfloat16 h = *(__nv_bfloat16*)&u;
    return __bfloat162float(h);
}

__device__ __forceinline__ float blockReduceSum(float val, float* red) {
    int lane = threadIdx.x & 31, w = threadIdx.x >> 5;
    #pragma unroll
    for (int o=16;o;o>>=1) val += __shfl_xor_sync(0xffffffffu, val, o);
    if (lane==0) red[w]=val;
    __syncthreads();
    if (w==0) {
        float v2 = (lane<8)? red[lane] : 0.f;
        #pragma unroll
        for (int o=4;o;o>>=1) v2 += __shfl_xor_sync(0xffffffffu, v2, o);
        if (lane==0) red[0]=v2;
    }
    __syncthreads();
    float r = red[0];
    __syncthreads();
    return r;
}

#define LDSM_X4(R0,R1,R2,R3,ADDR) \
    asm volatile("ldmatrix.sync.aligned.m8n8.x4.shared.b16 {%0,%1,%2,%3}, [%4];" \
        : "=r"(R0),"=r"(R1),"=r"(R2),"=r"(R3) : "r"(ADDR))
#define LDSM_X4T(R0,R1,R2,R3,ADDR) \
    asm volatile("ldmatrix.sync.aligned.m8n8.x4.trans.shared.b16 {%0,%1,%2,%3}, [%4];" \
        : "=r"(R0),"=r"(R1),"=r"(R2),"=r"(R3) : "r"(ADDR))
#define MMA_BF16(C,A0,A1,A2,A3,B0,B1) \
    asm volatile("mma.sync.aligned.m16n8k16.row.col.f32.bf16.bf16.f32 " \
        "{%0,%1,%2,%3},{%4,%5,%6,%7},{%8,%9},{%0,%1,%2,%3};" \
        : "+f"(C[0]),"+f"(C[1]),"+f"(C[2]),"+f"(C[3]) \
        : "r"(A0),"r"(A1),"r"(A2),"r"(A3),"r"(B0),"r"(B1))
#define CP16(DST,SRC) \
    asm volatile("cp.async.cg.shared.global [%0], [%1], 16;\n" :: "r"(DST), "l"(SRC))

// GEMM pipeline layout constants
#define AL_OFFB  (128*40*2)
#define B_OFFB   (2*128*40*2)
#define BL_OFFB  (32*136*2)
#define STAGE_B  (2*128*40*2 + 2*32*136*2)   // 37888 bytes
#define SMEM_GEMM (2*STAGE_B)                // 75776 bytes

// ---------------- zero kernel ----------------
__global__ void __launch_bounds__(256) zero_kernel(float* dst, int n4)
{
    int idx = blockIdx.x*256 + threadIdx.x;
    if (idx < n4) *(float4*)(dst + (size_t)idx*4) = make_float4(0.f,0.f,0.f,0.f);
}

// ---------------- fp32 -> bf16 hi/lo split (8 elems/thread) ----------------
__global__ void __launch_bounds__(256) f2bf_split_kernel(
    const float* __restrict__ src, unsigned short* __restrict__ hi,
    unsigned short* __restrict__ lo, int n8)
{
    int idx = blockIdx.x*256 + threadIdx.x;
    if (idx >= n8) return;
    const float4* s = (const float4*)(src) + (size_t)idx*2;
    float4 v0 = s[0], v1 = s[1];
    float f[8] = {v0.x,v0.y,v0.z,v0.w,v1.x,v1.y,v1.z,v1.w};
    unsigned hh[4], ll[4];
    #pragma unroll
    for (int i=0;i<4;i++){
        unsigned short h0 = f2bf(f[i*2]), h1 = f2bf(f[i*2+1]);
        unsigned short l0 = f2bf(f[i*2]-bf2f(h0)), l1 = f2bf(f[i*2+1]-bf2f(h1));
        hh[i] = (unsigned)h0 | ((unsigned)h1<<16);
        ll[i] = (unsigned)l0 | ((unsigned)l1<<16);
    }
    *(uint4*)(hi + (size_t)idx*8) = make_uint4(hh[0],hh[1],hh[2],hh[3]);
    *(uint4*)(lo + (size_t)idx*8) = make_uint4(ll[0],ll[1],ll[2],ll[3]);
}

// ------- pack Wq|Wk|Wv|Wb|Wid|0pad -> [1024][3200] bf16 hi/lo --------------
__global__ void __launch_bounds__(256) f2bf_pack_qkv_kernel(
    const float* __restrict__ Wq, const float* __restrict__ Wk,
    const float* __restrict__ Wv, const float* __restrict__ Wb,
    const float* __restrict__ Wid,
    unsigned short* __restrict__ hi, unsigned short* __restrict__ lo)
{
    int idx = blockIdx.x*256 + threadIdx.x;
    if (idx >= 1024*3200/8) return;
    int e0 = idx*8;
    int row = e0 / 3200;
    int col = e0 % 3200;
    float f[8];
    if (col < 3072) {
        int s = col >> 10;
        const float* src = (s==0)? Wq : (s==1)? Wk : Wv;
        const float4* sp = (const float4*)(src + (size_t)row*1024 + (col & 1023));
        float4 a = sp[0], b = sp[1];
        f[0]=a.x; f[1]=a.y; f[2]=a.z; f[3]=a.w; f[4]=b.x; f[5]=b.y; f[6]=b.z; f[7]=b.w;
    } else if (col == 3072) {
        #pragma unroll
        for (int i=0;i<4;i++){ f[i] = Wb[(size_t)row*4+i]; f[4+i] = Wid[(size_t)row*4+i]; }
    } else {
        #pragma unroll
        for (int i=0;i<8;i++) f[i] = 0.f;
    }
    unsigned hh[4], ll[4];
    #pragma unroll
    for (int i=0;i<4;i++){
        unsigned short h0 = f2bf(f[i*2]), h1 = f2bf(f[i*2+1]);
        unsigned short l0 = f2bf(f[i*2]-bf2f(h0)), l1 = f2bf(f[i*2+1]-bf2f(h1));
        hh[i] = (unsigned)h0 | ((unsigned)h1<<16);
        ll[i] = (unsigned)l0 | ((unsigned)l1<<16);
    }
    *(uint4*)(hi + (size_t)idx*8) = make_uint4(hh[0],hh[1],hh[2],hh[3]);
    *(uint4*)(lo + (size_t)idx*8) = make_uint4(ll[0],ll[1],ll[2],ll[3]);
}

// ---------------- Wr1 [1048][2048] -> padded [1088][2048] bf16 split -------
__global__ void __launch_bounds__(256) f2bf_split_pad_kernel(
    const float* __restrict__ src, unsigned short* __restrict__ hi,
    unsigned short* __restrict__ lo)
{
    int idx = blockIdx.x*256 + threadIdx.x;
    if (idx >= 1088*256) return;
    int row = (idx*8) >> 11;
    unsigned hh[4]={0,0,0,0}, ll[4]={0,0,0,0};
    if (row < 1048) {
        const float4* s = (const float4*)(src) + (size_t)idx*2;
        float4 v0 = s[0], v1 = s[1];
        float f[8] = {v0.x,v0.y,v0.z,v0.w,v1.x,v1.y,v1.z,v1.w};
        #pragma unroll
        for (int i=0;i<4;i++){
            unsigned short h0 = f2bf(f[i*2]), h1 = f2bf(f[i*2+1]);
            unsigned short l0 = f2bf(f[i*2]-bf2f(h0)), l1 = f2bf(f[i*2+1]-bf2f(h1));
            hh[i] = (unsigned)h0 | ((unsigned)h1<<16);
            ll[i] = (unsigned)l0 | ((unsigned)l1<<16);
        }
    }
    *(uint4*)(hi + (size_t)idx*8) = make_uint4(hh[0],hh[1],hh[2],hh[3]);
    *(uint4*)(lo + (size_t)idx*8) = make_uint4(ll[0],ll[1],ll[2],ll[3]);
}

// ---------------- tensor-core GEMM, cp.async 2-stage pipeline (EPI none) ----
__global__ void __launch_bounds__(256,2) tgemm_kernel(
    const unsigned short* __restrict__ Ahi, const unsigned short* __restrict__ Alo,
    const unsigned short* __restrict__ Bhi, const unsigned short* __restrict__ Blo,
    float* __restrict__ C, int M, int N, int K)
{
    extern __shared__ unsigned short sm[];
    const int tid  = threadIdx.x;
    const int lane = tid & 31;
    const int warp = tid >> 5;
    const int warp_m = warp & 3;
    const int warp_n = warp >> 2;
    const int brow = blockIdx.y * 128;
    const int bcol = blockIdx.x * 128;

    float c[2][8][4];
    #pragma unroll
    for (int i=0;i<2;i++)
        #pragma unroll
        for (int j=0;j<8;j++)
            #pragma unroll
            for (int t=0;t<4;t++) c[i][j][t]=0.f;

    const unsigned sb = (unsigned)__cvta_generic_to_shared(sm);
    const int ar = tid >> 1;
    const int ac = (tid & 1) * 16;
    const int br = tid >> 3;
    const int bc = (tid & 7) * 16;

    const unsigned short* Ahg = Ahi + (size_t)(brow + ar)*K + ac;
    const unsigned short* Alg = Alo + (size_t)(brow + ar)*K + ac;
    const unsigned short* Bhg = Bhi + (size_t)br*N + bcol + bc;
    const unsigned short* Blg = Blo + (size_t)br*N + bcol + bc;

    const unsigned a_dst = sb + (unsigned)(ar*40 + ac)*2u;
    const unsigned b_dst = sb + B_OFFB + (unsigned)(br*136 + bc)*2u;

    #define ISSUE_STAGE(KT, BUF) do {                                   \
        unsigned a0 = a_dst + (BUF)*STAGE_B;                             \
        CP16(a0,            Ahg + (KT));                                 \
        CP16(a0 + 16u,      Ahg + (KT) + 8);                             \
        CP16(a0 + AL_OFFB,       Alg + (KT));                            \
        CP16(a0 + AL_OFFB + 16u, Alg + (KT) + 8);                        \
        unsigned b0 = b_dst + (BUF)*STAGE_B;                             \
        const unsigned short* bhp = Bhg + (size_t)(KT)*N;                \
        const unsigned short* blp = Blg + (size_t)(KT)*N;                \
        CP16(b0,            bhp);                                        \
        CP16(b0 + 16u,      bhp + 8);                                    \
        CP16(b0 + BL_OFFB,       blp);                                   \
        CP16(b0 + BL_OFFB + 16u, blp + 8);                               \
        asm volatile("cp.async.commit_group;\n" ::);                     \
    } while(0)

    const int T = K >> 5;
    ISSUE_STAGE(0, 0);

    for (int t = 0; t < T; t++) {
        if (t + 1 < T) {
            ISSUE_STAGE((t+1)*32, (t+1)&1);
            asm volatile("cp.async.wait_group 1;\n" ::);
        } else {
            asm volatile("cp.async.wait_group 0;\n" ::);
        }
        __syncthreads();

        const unsigned s0 = sb + (unsigned)(t&1)*STAGE_B;
        #pragma unroll
        for (int ks = 0; ks < 2; ks++) {
            unsigned ah[2][4], al[2][4];
            #pragma unroll
            for (int mt = 0; mt < 2; mt++) {
                int ar2 = warp_m*32 + mt*16 + (lane & 15);
                int ac2 = ((lane >> 4) << 3) + ks*16;
                unsigned off = s0 + (unsigned)(ar2*40 + ac2)*2u;
                LDSM_X4(ah[mt][0],ah[mt][1],ah[mt][2],ah[mt][3], off);
                LDSM_X4(al[mt][0],al[mt][1],al[mt][2],al[mt][3], off + AL_OFFB);
            }
            #pragma unroll
            for (int np = 0; np < 4; np++) {
                unsigned bh[4], bl[4];
                int bk = (lane & 7) + (((lane >> 3) & 1) << 3) + ks*16;
                int bn = warp_n*64 + np*16 + ((lane >> 4) << 3);
                unsigned off = s0 + B_OFFB + (unsigned)(bk*136 + bn)*2u;
                LDSM_X4T(bh[0],bh[1],bh[2],bh[3], off);
                LDSM_X4T(bl[0],bl[1],bl[2],bl[3], off + BL_OFFB);
                #pragma unroll
                for (int mt = 0; mt < 2; mt++) {
                    #pragma unroll
                    for (int jj = 0; jj < 2; jj++) {
                        int j = np*2 + jj, o = jj*2;
                        MMA_BF16(c[mt][j], ah[mt][0],ah[mt][1],ah[mt][2],ah[mt][3],
                                 bh[o], bh[o+1]);
                        MMA_BF16(c[mt][j], ah[mt][0],ah[mt][1],ah[mt][2],ah[mt][3],
                                 bl[o], bl[o+1]);
                        MMA_BF16(c[mt][j], al[mt][0],al[mt][1],al[mt][2],al[mt][3],
                                 bh[o], bh[o+1]);
                    }
                }
            }
        }
        __syncthreads();
    }
    #undef ISSUE_STAGE

    #pragma unroll
    for (int mt = 0; mt < 2; mt++) {
        int r0 = brow + warp_m*32 + mt*16 + (lane >> 2);
        #pragma unroll
        for (int j = 0; j < 8; j++) {
            int col = bcol + warp_n*64 + j*8 + (lane & 3)*2;
            *(float2*)&C[(size_t)r0*N + col]     = make_float2(c[mt][j][0], c[mt][j][1]);
            *(float2*)&C[(size_t)(r0+8)*N + col] = make_float2(c[mt][j][2], c[mt][j][3]);
        }
    }
}

// --------- Wr1 GEMM fused with gelu + router logits (atomicAdd) ------------
// A: x planes [8192][1024] ++ stats planes [8192][64]  (K = 1088)
// B: w1 planes [1088][2048].  No C output; logits[n][12] += gelu(.)·Wr2
__global__ void __launch_bounds__(256,2) tgemm_router_kernel(
    const unsigned short* __restrict__ Axhi, const unsigned short* __restrict__ Axlo,
    const unsigned short* __restrict__ Sthi, const unsigned short* __restrict__ Stlo,
    const unsigned short* __restrict__ Bhi, const unsigned short* __restrict__ Blo,
    const float* __restrict__ bias, const float* __restrict__ Wr2,
    float* __restrict__ logits)
{
    extern __shared__ unsigned short sm[];
    const int tid  = threadIdx.x;
    const int lane = tid & 31;
    const int warp = tid >> 5;
    const int warp_m = warp & 3;
    const int warp_n = warp >> 2;
    const int brow = blockIdx.y * 128;
    const int bcol = blockIdx.x * 128;
    const int N = 2048;

    float c[2][8][4];
    #pragma unroll
    for (int i=0;i<2;i++)
        #pragma unroll
        for (int j=0;j<8;j++)
            #pragma unroll
            for (int t=0;t<4;t++) c[i][j][t]=0.f;

    const unsigned sb = (unsigned)__cvta_generic_to_shared(sm);
    const int ar = tid >> 1;
    const int ac = (tid & 1) * 16;
    const int br = tid >> 3;
    const int bc = (tid & 7) * 16;

    const unsigned short* Bhg = Bhi + (size_t)br*N + bcol + bc;
    const unsigned short* Blg = Blo + (size_t)br*N + bcol + bc;

    const unsigned a_dst = sb + (unsigned)(ar*40 + ac)*2u;
    const unsigned b_dst = sb + B_OFFB + (unsigned)(br*136 + bc)*2u;

    #define TCR_ISSUE(KT, BUF) do {                                          \
        unsigned a0 = a_dst + (BUF)*STAGE_B;                                  \
        const unsigned short* ah_src; const unsigned short* al_src;           \
        if ((KT) < 1024) {                                                    \
            ah_src = Axhi + (size_t)(brow+ar)*1024 + (KT) + ac;               \
            al_src = Axlo + (size_t)(brow+ar)*1024 + (KT) + ac;               \
        } else {                                                              \
            ah_src = Sthi + (size_t)(brow+ar)*64 + ((KT)-1024) + ac;          \
            al_src = Stlo + (size_t)(brow+ar)*64 + ((KT)-1024) + ac;          \
        }                                                                     \
        CP16(a0,            ah_src);                                          \
        CP16(a0 + 16u,      ah_src + 8);                                      \
        CP16(a0 + AL_OFFB,       al_src);                                     \
        CP16(a0 + AL_OFFB + 16u, al_src + 8);                                 \
        unsigned b0 = b_dst + (BUF)*STAGE_B;                                  \
        const unsigned short* bhp = Bhg + (size_t)(KT)*N;                     \
        const unsigned short* blp = Blg + (size_t)(KT)*N;                     \
        CP16(b0,            bhp);                                             \
        CP16(b0 + 16u,      bhp + 8);                                         \
        CP16(b0 + BL_OFFB,       blp);                                        \
        CP16(b0 + BL_OFFB + 16u, blp + 8);                                    \
        asm volatile("cp.async.commit_group;\n" ::);                          \
    } while(0)

    const int T = 34;     // K = 1088
    TCR_ISSUE(0, 0);

    for (int t = 0; t < T; t++) {
        if (t + 1 < T) {
            TCR_ISSUE((t+1)*32, (t+1)&1);
            asm volatile("cp.async.wait_group 1;\n" ::);
        } else {
            asm volatile("cp.async.wait_group 0;\n" ::);
        }
        __syncthreads();

        const unsigned s0 = sb + (unsigned)(t&1)*STAGE_B;
        #pragma unroll
        for (int ks = 0; ks < 2; ks++) {
            unsigned ah[2][4], al[2][4];
            #pragma unroll
            for (int mt = 0; mt < 2; mt++) {
                int ar2 = warp_m*32 + mt*16 + (lane & 15);
                int ac2 = ((lane >> 4) << 3) + ks*16;
                unsigned off = s0 + (unsigned)(ar2*40 + ac2)*2u;
                LDSM_X4(ah[mt][0],ah[mt][1],ah[mt][2],ah[mt][3], off);
                LDSM_X4(al[mt][0],al[mt][1],al[mt][2],al[mt][3], off + AL_OFFB);
            }
            #pragma unroll
            for (int np = 0; np < 4; np++) {
                unsigned bh[4], bl[4];
                int bk = (lane & 7) + (((lane >> 3) & 1) << 3) + ks*16;
                int bn = warp_n*64 + np*16 + ((lane >> 4) << 3);
                unsigned off = s0 + B_OFFB + (unsigned)(bk*136 + bn)*2u;
                LDSM_X4T(bh[0],bh[1],bh[2],bh[3], off);
                LDSM_X4T(bl[0],bl[1],bl[2],bl[3], off + BL_OFFB);
                #pragma unroll
                for (int mt = 0; mt < 2; mt++) {
                    #pragma unroll
                    for (int jj = 0; jj < 2; jj++) {
                        int j = np*2 + jj, o = jj*2;
                        MMA_BF16(c[mt][j], ah[mt][0],ah[mt][1],ah[mt][2],ah[mt][3],
                                 bh[o], bh[o+1]);
                        MMA_BF16(c[mt][j], ah[mt][0],ah[mt][1],ah[mt][2],ah[mt][3],
                                 bl[o], bl[o+1]);
                        MMA_BF16(c[mt][j], al[mt][0],al[mt][1],al[mt][2],al[mt][3],
                                 bh[o], bh[o+1]);
                    }
                }
            }
        }
        __syncthreads();
    }
    #undef TCR_ISSUE

    // ---- fused epilogue: bias + exact gelu + router partial logits ----
    float* w2s = (float*)sm;      // 128 cols x 12 outs = 1536 floats
    for (int i = tid; i < 1536; i += 256)
        w2s[i] = Wr2[(size_t)(bcol + i/12)*12 + (i%12)];
    __syncthreads();

    #pragma unroll
    for (int mt = 0; mt < 2; mt++) {
        #pragma unroll
        for (int rr = 0; rr < 2; rr++) {
            int row = brow + warp_m*32 + mt*16 + (lane >> 2) + rr*8;
            float lsum[12];
            #pragma unroll
            for (int o2=0;o2<12;o2++) lsum[o2]=0.f;
            #pragma unroll
            for (int j = 0; j < 8; j++) {
                int cl = warp_n*64 + j*8 + (lane & 3)*2;
                float v0 = c[mt][j][rr*2+0] + bias[bcol+cl];
                float v1 = c[mt][j][rr*2+1] + bias[bcol+cl+1];
                v0 = 0.5f*v0*(1.0f+erff(v0*0.70710678118654752f));
                v1 = 0.5f*v1*(1.0f+erff(v1*0.70710678118654752f));
                #pragma unroll
                for (int o2=0;o2<12;o2++)
                    lsum[o2] += v0*w2s[cl*12+o2] + v1*w2s[(cl+1)*12+o2];
            }
            #pragma unroll
            for (int o2=0;o2<12;o2++){
                lsum[o2] += __shfl_xor_sync(0xffffffffu, lsum[o2], 1);
                lsum[o2] += __shfl_xor_sync(0xffffffffu, lsum[o2], 2);
            }
            if ((lane & 3) == 0) {
                #pragma unroll
                for (int o2=0;o2<12;o2++)
                    atomicAdd(&logits[(size_t)row*12 + o2], lsum[o2]);
            }
        }
    }
}

// ---------------- beta + id-gate from qkvlin cols 3072..3079 ----------------
__global__ void __launch_bounds__(256) beta_sid_kernel(
    const float* __restrict__ qkvlin, const float* __restrict__ bid,
    float* __restrict__ beta, float* __restrict__ sid)
{
    int idx = blockIdx.x*256 + threadIdx.x;     // 32768 = 8192*4
    if (idx >= NTOK*4) return;
    int n = idx >> 2, h = idx & 3;
    const float* row = qkvlin + (size_t)n*3200;
    beta[idx] = sigm(row[3072 + h]);
    sid[idx]  = sigm(row[3076 + h] + bid[h]);
}

// ---------------- fused causal depthwise conv (k=4) + silu, 3 streams -------
__global__ void __launch_bounds__(256) conv_silu_kernel(
    const float* __restrict__ in, const float* __restrict__ cq,
    const float* __restrict__ ck, const float* __restrict__ cv,
    float* __restrict__ qb, float* __restrict__ kb, float* __restrict__ vb)
{
    long long gidx = (long long)blockIdx.x*256 + threadIdx.x;
    int s = (int)(gidx >> 23);
    int idx = (int)(gidx & ((1<<23)-1));
    int c = idx & 1023;
    int n = idx >> 10;
    int l = n & (LSEQ-1);
    const float* cw = (s==0)? cq : (s==1)? ck : cv;
    float* out = (s==0)? qb : (s==1)? kb : vb;
    float4 wv = *(const float4*)(cw + (size_t)c*4);
    float wj[4] = {wv.x, wv.y, wv.z, wv.w};
    float acc = 0.f;
    #pragma unroll
    for (int j=0;j<4;j++){
        int t = l - 3 + j;
        if (t >= 0) acc += in[(size_t)(n-3+j)*3200 + s*1024 + c] * wj[j];
    }
    out[idx] = acc / (1.0f + expf(-acc));
}

// ---------------- per-chunk prep: l2norm, T, u, w, attn ----------------
__global__ void __launch_bounds__(256) chunk_prep_kernel(
    float* __restrict__ q, float* __restrict__ k, const float* __restrict__ v,
    const float* __restrict__ beta, float* __restrict__ u, float* __restrict__ w,
    float* __restrict__ attn)
{
    extern __shared__ float sh[];
    float* qs = sh;
    float* ks = qs + 32*260;
    float* vs = ks + 32*260;
    float* T  = vs + 32*260;
    float* bet = T + 32*33;
    int ci = blockIdx.x;
    int c = ci & 127;
    int h = (ci >> 7) & 3;
    int b = ci >> 9;
    int tid = threadIdx.x;
    size_t base = ((size_t)(b*LSEQ + c*32))*1024 + (size_t)h*256;
    for (int i=tid; i<2048; i+=256) {
        int r = i>>6; int d4 = (i&63)<<2;
        size_t off = base + (size_t)r*1024 + d4;
        *(float4*)&qs[r*260+d4] = *(const float4*)(q + off);
        *(float4*)&ks[r*260+d4] = *(const float4*)(k + off);
        *(float4*)&vs[r*260+d4] = *(const float4*)(v + off);
    }
    if (tid < 32) bet[tid] = beta[(size_t)(b*LSEQ + c*32 + tid)*4 + h];
    __syncthreads();
    {
        int wi = tid>>5, lane = tid&31;
        for (int r = wi*4; r < wi*4+4; r++) {
            float sq=0.f, sk2=0.f;
            for (int dd=lane; dd<256; dd+=32){
                float a=qs[r*260+dd]; sq+=a*a;
                float bb=ks[r*260+dd]; sk2+=bb*bb;
            }
            #pragma unroll
            for (int o=16;o;o>>=1){
                sq+=__shfl_xor_sync(0xffffffffu,sq,o);
                sk2+=__shfl_xor_sync(0xffffffffu,sk2,o);
            }
            float rq = rsqrtf(sq+1e-6f), rk = rsqrtf(sk2+1e-6f);
            for (int dd=lane; dd<256; dd+=32){ qs[r*260+dd]*=rq; ks[r*260+dd]*=rk; }
        }
    }
    __syncthreads();
    size_t abase = (size_t)ci*1024;
    for (int pp=tid; pp<1024; pp+=256) {
        int i = pp>>5, j = pp&31;
        float dkk=0.f, dqq=0.f;
        for (int dd=0; dd<256; dd++){
            float kj = ks[j*260+dd];
            dkk += ks[i*260+dd]*kj;
            dqq += qs[i*260+dd]*kj;
        }
        T[i*33+j] = (j<i)? (-bet[i]*dkk) : 0.f;
        attn[abase+pp] = (j<=i)? dqq : 0.f;
    }
    __syncthreads();
    if (tid<32) {
        int lane = tid;
        for (int i=1;i<32;i++){
            float rowv = T[i*33+lane];
            float add = 0.f;
            for (int j=0;j<i;j++) add += __shfl_sync(0xffffffffu, rowv, j)*T[j*33+lane];
            T[i*33+lane] = rowv + add;
            __syncwarp();
        }
        T[lane*33+lane] += 1.0f;
    }
    __syncthreads();
    for (int pp=tid; pp<8192; pp+=256){
        int r = pp>>8, dd = pp&255;
        float su=0.f, sw=0.f;
        #pragma unroll
        for (int j=0;j<32;j++){
            float tj = T[r*33+j]*bet[j];
            su += tj*vs[j*260+dd];
            sw += tj*ks[j*260+dd];
        }
        size_t off = base + (size_t)r*1024 + dd;
        u[off]=su; w[off]=sw;
        q[off]=qs[r*260+dd]; k[off]=ks[r*260+dd];
    }
}

// ---------------- sequential chunk scan, dv-sliced (16 slices of 16) -------
__global__ void __launch_bounds__(512) scan_kernel(
    const float* __restrict__ q, const float* __restrict__ k,
    const float* __restrict__ u, const float* __restrict__ w,
    const float* __restrict__ attn, float* __restrict__ outp)
{
    extern __shared__ float sh[];
    float* S  = sh;
    float* qs = S + 4096;
    float* ks = qs + 8320;
    float* ws = ks + 8320;
    float* as = ws + 8320;
    float* u2 = as + 1024;
    int bid = blockIdx.x;
    int sl = bid & 15;
    int bh = bid >> 4;
    int h = bh & 3, b = bh >> 2;
    int tid = threadIdx.x;
    for (int i=tid;i<4096;i+=512) S[i]=0.f;
    const int iRow = tid >> 4;
    const int q1 = tid & 15;
    const int dd0 = tid >> 2;
    const int c4 = (tid & 3) * 4;
    size_t abh = (size_t)bh * 128 * 1024;
    for (int c=0;c<128;c++){
        size_t base = ((size_t)(b*LSEQ + c*32))*1024 + (size_t)h*256;
        __syncthreads();
        for (int i=tid;i<2048;i+=512){
            int r=i>>6; int d4=(i&63)<<2;
            size_t off = base + (size_t)r*1024 + d4;
            *(float4*)&qs[r*260+d4] = *(const float4*)(q+off);
            *(float4*)&ks[r*260+d4] = *(const float4*)(k+off);
            *(float4*)&ws[r*260+d4] = *(const float4*)(w+off);
        }
        if (tid < 256)
            *(float4*)&as[tid*4] = *(const float4*)(attn + abh + (size_t)c*1024 + tid*4);
        __syncthreads();
        float au = u[base + (size_t)iRow*1024 + sl*16 + q1];
        float ao = 0.f;
        #pragma unroll 8
        for (int dd=0; dd<256; dd++){
            float Sv = S[dd*16+q1];
            au -= ws[iRow*260+dd]*Sv;
            ao += qs[iRow*260+dd]*Sv;
        }
        u2[iRow*16+q1] = au;
        __syncthreads();
        #pragma unroll
        for (int j=0;j<32;j++) ao += as[iRow*32+j]*u2[j*16+q1];
        outp[base + (size_t)iRow*1024 + sl*16 + q1] = ao;
        #pragma unroll
        for (int s2=0; s2<2; s2++){
            int dd = dd0 + s2*128;
            float4 Sv = *(float4*)&S[dd*16+c4];
            #pragma unroll 8
            for (int j=0;j<32;j++){
                float kv = ks[j*260+dd];
                float4 uv = *(float4*)&u2[j*16+c4];
                Sv.x += kv*uv.x; Sv.y += kv*uv.y; Sv.z += kv*uv.z; Sv.w += kv*uv.w;
            }
            *(float4*)&S[dd*16+c4] = Sv;
        }
    }
}

// ---------------- FIR + stats (smem-tiled, bf16 stats plane out) -----------
__global__ void __launch_bounds__(256) fir_stats_kernel(
    const float* __restrict__ v, const float* __restrict__ dlt,
    const float* __restrict__ firS, const float* __restrict__ firL,
    float* __restrict__ fs, float* __restrict__ fl,
    unsigned short* __restrict__ sthi, unsigned short* __restrict__ stlo)
{
    extern __shared__ float vsm[];
    __shared__ float red[8][6];
    const int h  = blockIdx.y;
    const int t0 = blockIdx.x * 32;
    const int l0 = t0 & (LSEQ-1);
    const int tid = threadIdx.x;
    const int d = tid;
    const int cidx = h*256 + d;
    const int lane = tid & 31, wrp = tid >> 5;

    // zero stats pad cols 24..63 (head-0 blocks)
    if (h == 0 && tid < 32) {
        size_t dst = (size_t)(t0+tid)*64 + 24;
        #pragma unroll
        for (int j=0;j<5;j++){
            *(uint4*)(sthi + dst + j*8) = make_uint4(0,0,0,0);
            *(uint4*)(stlo + dst + j*8) = make_uint4(0,0,0,0);
        }
    }

    for (int i = tid; i < 62*64; i += 256) {
        int r = i >> 6; int c4 = (i & 63) << 2;
        float4 val = make_float4(0.f,0.f,0.f,0.f);
        if (l0 - 30 + r >= 0)
            val = *(const float4*)(v + (size_t)(t0-30+r)*1024 + h*256 + c4);
        *(float4*)&vsm[r*256 + c4] = val;
    }
    __syncthreads();

    float fS[3], fL[31];
    #pragma unroll
    for (int j=0;j<3;j++)  fS[j] = firS[(size_t)cidx*3+j];
    #pragma unroll
    for (int j=0;j<31;j++) fL[j] = firL[(size_t)cidx*31+j];

    for (int tt = 0; tt < 32; tt++) {
        int row = tt + 30;
        int n = t0 + tt;
        float accS = 0.f;
        #pragma unroll
        for (int j=0;j<3;j++) accS += vsm[(row-2+j)*256 + d]*fS[j];
        float accL = 0.f;
        #pragma unroll
        for (int j=0;j<31;j++) accL += vsm[(row-30+j)*256 + d]*fL[j];
        float dv = dlt[(size_t)n*1024 + cidx];
        fs[(size_t)n*1024 + cidx] = accS;
        fl[(size_t)n*1024 + cidx] = accL;

        float vals[6] = {accS, accS*accS, accL, accL*accL, dv, dv*dv};
        #pragma unroll
        for (int k2=0;k2<6;k2++){
            float s = vals[k2];
            #pragma unroll
            for (int o=16;o;o>>=1) s += __shfl_xor_sync(0xffffffffu, s, o);
            if (lane==0) red[wrp][k2] = s;
        }
        __syncthreads();
        if (tid == 0) {
            float s[6];
            #pragma unroll
            for (int k2=0;k2<6;k2++){
                float a = 0.f;
                #pragma unroll
                for (int ww=0;ww<8;ww++) a += red[ww][k2];
                s[k2] = a;
            }
            float m1 = s[0]*(1.f/256.f), m3 = s[2]*(1.f/256.f), m5 = s[4]*(1.f/256.f);
            float o[6];
            o[0]=m1;
            o[1]=sqrtf(fmaxf(s[1]*(1.f/256.f)-m1*m1,0.f));
            o[2]=m3;
            o[3]=sqrtf(fmaxf(s[3]*(1.f/256.f)-m3*m3,0.f));
            o[4]=m5;
            o[5]=sqrtf(fmaxf(s[5]*(1.f/256.f)-m5*m5,0.f));
            size_t rb = (size_t)n*64 + h;
            #pragma unroll
            for (int k2=0;k2<6;k2++){
                unsigned short hh = f2bf(o[k2]);
                sthi[rb + k2*4] = hh;
                stlo[rb + k2*4] = f2bf(o[k2]-bf2f(hh));
            }
        }
        __syncthreads();
    }
}

// ---------------- softmax over router logits ----------------
__global__ void __launch_bounds__(256) softmax_router_kernel(
    const float* __restrict__ logits, const float* __restrict__ br2,
    const float* __restrict__ ltg, float* __restrict__ p)
{
    int n = blockIdx.x*256 + threadIdx.x;
    if (n >= NTOK) return;
    float lg[12];
    #pragma unroll
    for (int i=0;i<12;i++) lg[i] = logits[(size_t)n*12+i] + br2[i];
    #pragma unroll
    for (int h=0;h<4;h++){
        float tau = expf(ltg[h>>1]);
        float a = lg[h*3+0]/tau, bq = lg[h*3+1]/tau, cq = lg[h*3+2]/tau;
        float m = fmaxf(a, fmaxf(bq,cq));
        float ea=expf(a-m), eb=expf(bq-m), ec=expf(cq-m);
        float inv = 1.f/(ea+eb+ec);
        p[(size_t)n*12 + h*3+0] = ea*inv*0.925f + 0.025f;
        p[(size_t)n*12 + h*3+1] = eb*inv*0.925f + 0.025f;
        p[(size_t)n*12 + h*3+2] = ec*inv*0.925f + 0.025f;
    }
}

// ---------------- gated mix + id + RMS norm -> bf16 hi/lo -------------------
__global__ void __launch_bounds__(256) mix_norm_kernel(
    const float* __restrict__ p, const float* __restrict__ fs,
    const float* __restrict__ fl, const float* __restrict__ dlt,
    const float* __restrict__ v, const float* __restrict__ sid,
    const float* __restrict__ alpha_id, const float* __restrict__ onw,
    unsigned short* __restrict__ omhi, unsigned short* __restrict__ omlo)
{
    int n = blockIdx.x;
    int d = threadIdx.x;
    __shared__ float red[8];
    for (int h=0;h<4;h++){
        size_t idx = (size_t)n*1024 + h*256 + d;
        float p0 = p[(size_t)n*12+h*3+0];
        float p1 = p[(size_t)n*12+h*3+1];
        float p2 = p[(size_t)n*12+h*3+2];
        float ids = 0.06f + sigm(alpha_id[h]) * sid[(size_t)n*4+h];
        float o = p0*fs[idx] + p1*fl[idx] + p2*dlt[idx] + ids*v[idx];
        float ss = blockReduceSum(o*o, red);
        float r = rsqrtf(ss*(1.f/256.f) + 1e-5f);
        float val = o*r*onw[d];
        unsigned short hh = f2bf(val);
        omhi[idx] = hh;
        omlo[idx] = f2bf(val - bf2f(hh));
    }
}

extern "C" void kernel_launch(void* const* d_in, const int* in_sizes, int n_in,
                              void* d_out, int out_size) {
    const float* x    = (const float*)d_in[0];
    const float* Wq   = (const float*)d_in[1];
    const float* Wk   = (const float*)d_in[2];
    const float* Wv   = (const float*)d_in[3];
    const float* Wb   = (const float*)d_in[4];
    const float* cq   = (const float*)d_in[5];
    const float* ck   = (const float*)d_in[6];
    const float* cv   = (const float*)d_in[7];
    const float* firS = (const float*)d_in[8];
    const float* firL = (const float*)d_in[9];
    const float* aid  = (const float*)d_in[10];
    const float* Wid  = (const float*)d_in[11];
    const float* bid  = (const float*)d_in[12];
    const float* Wr1  = (const float*)d_in[13];
    const float* br1  = (const float*)d_in[14];
    const float* Wr2  = (const float*)d_in[15];
    const float* br2  = (const float*)d_in[16];
    const float* ltg  = (const float*)d_in[17];
    const float* onw  = (const float*)d_in[19];
    const float* Wo   = (const float*)d_in[20];
    float* out = (float*)d_out;

    void* bufv = nullptr;
    cudaGetSymbolAddress(&bufv, g_buf);
    float* buf = (float*)bufv;
    void* bbufv = nullptr;
    cudaGetSymbolAddress(&bbufv, g_bf);
    unsigned short* bbuf = (unsigned short*)bbufv;

    float* qkvlin = buf + OFF_QL;
    float* qb   = buf + OFF_Q;
    float* kb   = buf + OFF_K;
    float* vb   = buf + OFF_V;
    float* ub   = buf + OFF_U;
    float* wb   = buf + OFF_W;
    float* dlt  = buf + OFF_DELTA;
    float* fsb  = buf + OFF_FS;
    float* flb  = buf + OFF_FL;
    float* lgts = buf + OFF_LOGITS;
    float* attn = buf + OFF_ATTN;
    float* beta = buf + OFF_BETA;
    float* sidb = buf + OFF_SID;
    float* pb   = buf + OFF_P;

    unsigned short* xhi  = bbuf + BOFF_X_HI;
    unsigned short* xlo  = bbuf + BOFF_X_LO;
    unsigned short* omhi = bbuf + BOFF_OM_HI;
    unsigned short* omlo = bbuf + BOFF_OM_LO;
    unsigned short* sthi = bbuf + BOFF_ST_HI;
    unsigned short* stlo = bbuf + BOFF_ST_LO;
    unsigned short* wqkvhi = bbuf + BOFF_WQKV_HI;
    unsigned short* wqkvlo = bbuf + BOFF_WQKV_LO;
    unsigned short* wohi = bbuf + BOFF_WO_HI;
    unsigned short* wolo = bbuf + BOFF_WO_LO;
    unsigned short* w1hi = bbuf + BOFF_W1_HI;
    unsigned short* w1lo = bbuf + BOFF_W1_LO;

    int smem_prep = (3*32*260 + 32*33 + 32) * 4;
    int smem_scan = (4096 + 3*8320 + 1024 + 512) * 4;
    int smem_fir  = 62*256*4;
    cudaFuncSetAttribute(chunk_prep_kernel, cudaFuncAttributeMaxDynamicSharedMemorySize, smem_prep);
    cudaFuncSetAttribute(scan_kernel, cudaFuncAttributeMaxDynamicSharedMemorySize, smem_scan);
    cudaFuncSetAttribute(fir_stats_kernel, cudaFuncAttributeMaxDynamicSharedMemorySize, smem_fir);
    cudaFuncSetAttribute(tgemm_kernel, cudaFuncAttributeMaxDynamicSharedMemorySize, SMEM_GEMM);
    cudaFuncSetAttribute(tgemm_router_kernel, cudaFuncAttributeMaxDynamicSharedMemorySize, SMEM_GEMM);

    // ---- init + conversions ----
    zero_kernel<<<96, 256>>>(lgts, NTOK*12/4);
    f2bf_split_kernel<<<4096, 256>>>(x, xhi, xlo, 8192*1024/8);
    f2bf_pack_qkv_kernel<<<1600, 256>>>(Wq, Wk, Wv, Wb, Wid, wqkvhi, wqkvlo);
    f2bf_split_kernel<<<512, 256>>>(Wo, wohi, wolo, 1024*1024/8);
    f2bf_split_pad_kernel<<<1088, 256>>>(Wr1, w1hi, w1lo);

    dim3 blk(256);
    dim3 gqkv(25, 64);
    tgemm_kernel<<<gqkv, blk, SMEM_GEMM>>>(xhi, xlo, wqkvhi, wqkvlo, qkvlin, NTOK, 3200, 1024);
    beta_sid_kernel<<<128, 256>>>(qkvlin, bid, beta, sidb);
    conv_silu_kernel<<<3*NTOK*4, 256>>>(qkvlin, cq, ck, cv, qb, kb, vb);
    chunk_prep_kernel<<<1024, 256, smem_prep>>>(qb, kb, vb, beta, ub, wb, attn);
    scan_kernel<<<128, 512, smem_scan>>>(qb, kb, ub, wb, attn, dlt);
    dim3 gfir(NTOK/32, 4);
    fir_stats_kernel<<<gfir, 256, smem_fir>>>(vb, dlt, firS, firL, fsb, flb, sthi, stlo);
    dim3 g2(16, 64);
    tgemm_router_kernel<<<g2, blk, SMEM_GEMM>>>(xhi, xlo, sthi, stlo, w1hi, w1lo, br1, Wr2, lgts);
    softmax_router_kernel<<<32, 256>>>(lgts, br2, ltg, pb);
    mix_norm_kernel<<<NTOK, 256>>>(pb, fsb, flb, dlt, vb, sidb, aid, onw, omhi, omlo);
    dim3 g1(8, 64);
    tgemm_kernel<<<g1, blk, SMEM_GEMM>>>(omhi, omlo, wohi, wolo, out, NTOK, 1024, 1024);
}

// round 10
// speedup vs baseline: 2.0268x; 1.0081x over previous
#include <cuda_runtime.h>
#include <cuda_bf16.h>
#include <math.h>

#define LSEQ 4096
#define NTOK 8192

// ---------------- float scratch offsets ----------------
#define OFF_QL     ((size_t)0)            // 8192 x 3200 fused qkv+beta+id lin
#define OFF_Q      ((size_t)26214400)
#define OFF_K      ((size_t)34603008)
#define OFF_V      ((size_t)42991616)
#define OFF_U      ((size_t)51380224)
#define OFF_W      ((size_t)59768832)
#define OFF_DELTA  ((size_t)68157440)
#define OFF_FS     ((size_t)76546048)
#define OFF_FL     ((size_t)84934656)
#define OFF_LOGITS ((size_t)93323264)     // 8192 x 12
#define OFF_ATTN   ((size_t)93421568)     // 1024 x 1024
#define OFF_BETA   ((size_t)94470144)
#define OFF_SID    ((size_t)94502912)
#define OFF_P      ((size_t)94535680)
#define BUF_TOTAL  ((size_t)94633984)

__device__ float g_buf[BUF_TOTAL];

// ---------------- bf16 plane offsets (ushort units) ----------------
#define BOFF_X_HI     ((size_t)0)
#define BOFF_X_LO     ((size_t)8388608)
#define BOFF_OM_HI    ((size_t)16777216)
#define BOFF_OM_LO    ((size_t)25165824)
#define BOFF_ST_HI    ((size_t)33554432)   // 8192 x 64 stats
#define BOFF_ST_LO    ((size_t)34078720)
#define BOFF_WQKV_HI  ((size_t)34603008)   // 1024 x 3200
#define BOFF_WQKV_LO  ((size_t)37879808)
#define BOFF_WO_HI    ((size_t)41156608)
#define BOFF_WO_LO    ((size_t)42205184)
#define BOFF_W1_HI    ((size_t)43253760)   // 1088 x 2048
#define BOFF_W1_LO    ((size_t)45481984)
#define BBUF_TOTAL    ((size_t)47710208)

__device__ unsigned short g_bf[BBUF_TOTAL];

__device__ __forceinline__ float sigm(float x){ return 1.0f/(1.0f+expf(-x)); }

__device__ __forceinline__ unsigned short f2bf(float f){
    __nv_bfloat16 h = __float2bfloat16(f);
    return *(unsigned short*)&h;
}
__device__ __forceinline__ float bf2f(unsigned short u){
    __nv_bfloat16 h = *(__nv_bfloat16*)&u;
    return __bfloat162float(h);
}

__device__ __forceinline__ float blockReduceSum(float val, float* red) {
    int lane = threadIdx.x & 31, w = threadIdx.x >> 5;
    #pragma unroll
    for (int o=16;o;o>>=1) val += __shfl_xor_sync(0xffffffffu, val, o);
    if (lane==0) red[w]=val;
    __syncthreads();
    if (w==0) {
        float v2 = (lane<8)? red[lane] : 0.f;
        #pragma unroll
        for (int o=4;o;o>>=1) v2 += __shfl_xor_sync(0xffffffffu, v2, o);
        if (lane==0) red[0]=v2;
    }
    __syncthreads();
    float r = red[0];
    __syncthreads();
    return r;
}

#define LDSM_X4(R0,R1,R2,R3,ADDR) \
    asm volatile("ldmatrix.sync.aligned.m8n8.x4.shared.b16 {%0,%1,%2,%3}, [%4];" \
        : "=r"(R0),"=r"(R1),"=r"(R2),"=r"(R3) : "r"(ADDR))
#define LDSM_X4T(R0,R1,R2,R3,ADDR) \
    asm volatile("ldmatrix.sync.aligned.m8n8.x4.trans.shared.b16 {%0,%1,%2,%3}, [%4];" \
        : "=r"(R0),"=r"(R1),"=r"(R2),"=r"(R3) : "r"(ADDR))
#define MMA_BF16(C,A0,A1,A2,A3,B0,B1) \
    asm volatile("mma.sync.aligned.m16n8k16.row.col.f32.bf16.bf16.f32 " \
        "{%0,%1,%2,%3},{%4,%5,%6,%7},{%8,%9},{%0,%1,%2,%3};" \
        : "+f"(C[0]),"+f"(C[1]),"+f"(C[2]),"+f"(C[3]) \
        : "r"(A0),"r"(A1),"r"(A2),"r"(A3),"r"(B0),"r"(B1))
#define CP16(DST,SRC) \
    asm volatile("cp.async.cg.shared.global [%0], [%1], 16;\n" :: "r"(DST), "l"(SRC))

// GEMM pipeline layout constants — 3-stage ring
#define AL_OFFB  (128*40*2)
#define B_OFFB   (2*128*40*2)
#define BL_OFFB  (32*136*2)
#define STAGE_B  (2*128*40*2 + 2*32*136*2)   // 37888 bytes
#define SMEM_GEMM (3*STAGE_B)                // 113664 bytes

// ---------------- zero kernel ----------------
__global__ void __launch_bounds__(256) zero_kernel(float* dst, int n4)
{
    int idx = blockIdx.x*256 + threadIdx.x;
    if (idx < n4) *(float4*)(dst + (size_t)idx*4) = make_float4(0.f,0.f,0.f,0.f);
}

// ---------------- fp32 -> bf16 hi/lo split (8 elems/thread) ----------------
__global__ void __launch_bounds__(256) f2bf_split_kernel(
    const float* __restrict__ src, unsigned short* __restrict__ hi,
    unsigned short* __restrict__ lo, int n8)
{
    int idx = blockIdx.x*256 + threadIdx.x;
    if (idx >= n8) return;
    const float4* s = (const float4*)(src) + (size_t)idx*2;
    float4 v0 = s[0], v1 = s[1];
    float f[8] = {v0.x,v0.y,v0.z,v0.w,v1.x,v1.y,v1.z,v1.w};
    unsigned hh[4], ll[4];
    #pragma unroll
    for (int i=0;i<4;i++){
        unsigned short h0 = f2bf(f[i*2]), h1 = f2bf(f[i*2+1]);
        unsigned short l0 = f2bf(f[i*2]-bf2f(h0)), l1 = f2bf(f[i*2+1]-bf2f(h1));
        hh[i] = (unsigned)h0 | ((unsigned)h1<<16);
        ll[i] = (unsigned)l0 | ((unsigned)l1<<16);
    }
    *(uint4*)(hi + (size_t)idx*8) = make_uint4(hh[0],hh[1],hh[2],hh[3]);
    *(uint4*)(lo + (size_t)idx*8) = make_uint4(ll[0],ll[1],ll[2],ll[3]);
}

// ------- pack Wq|Wk|Wv|Wb|Wid|0pad -> [1024][3200] bf16 hi/lo --------------
__global__ void __launch_bounds__(256) f2bf_pack_qkv_kernel(
    const float* __restrict__ Wq, const float* __restrict__ Wk,
    const float* __restrict__ Wv, const float* __restrict__ Wb,
    const float* __restrict__ Wid,
    unsigned short* __restrict__ hi, unsigned short* __restrict__ lo)
{
    int idx = blockIdx.x*256 + threadIdx.x;
    if (idx >= 1024*3200/8) return;
    int e0 = idx*8;
    int row = e0 / 3200;
    int col = e0 % 3200;
    float f[8];
    if (col < 3072) {
        int s = col >> 10;
        const float* src = (s==0)? Wq : (s==1)? Wk : Wv;
        const float4* sp = (const float4*)(src + (size_t)row*1024 + (col & 1023));
        float4 a = sp[0], b = sp[1];
        f[0]=a.x; f[1]=a.y; f[2]=a.z; f[3]=a.w; f[4]=b.x; f[5]=b.y; f[6]=b.z; f[7]=b.w;
    } else if (col == 3072) {
        #pragma unroll
        for (int i=0;i<4;i++){ f[i] = Wb[(size_t)row*4+i]; f[4+i] = Wid[(size_t)row*4+i]; }
    } else {
        #pragma unroll
        for (int i=0;i<8;i++) f[i] = 0.f;
    }
    unsigned hh[4], ll[4];
    #pragma unroll
    for (int i=0;i<4;i++){
        unsigned short h0 = f2bf(f[i*2]), h1 = f2bf(f[i*2+1]);
        unsigned short l0 = f2bf(f[i*2]-bf2f(h0)), l1 = f2bf(f[i*2+1]-bf2f(h1));
        hh[i] = (unsigned)h0 | ((unsigned)h1<<16);
        ll[i] = (unsigned)l0 | ((unsigned)l1<<16);
    }
    *(uint4*)(hi + (size_t)idx*8) = make_uint4(hh[0],hh[1],hh[2],hh[3]);
    *(uint4*)(lo + (size_t)idx*8) = make_uint4(ll[0],ll[1],ll[2],ll[3]);
}

// ---------------- Wr1 [1048][2048] -> padded [1088][2048] bf16 split -------
__global__ void __launch_bounds__(256) f2bf_split_pad_kernel(
    const float* __restrict__ src, unsigned short* __restrict__ hi,
    unsigned short* __restrict__ lo)
{
    int idx = blockIdx.x*256 + threadIdx.x;
    if (idx >= 1088*256) return;
    int row = (idx*8) >> 11;
    unsigned hh[4]={0,0,0,0}, ll[4]={0,0,0,0};
    if (row < 1048) {
        const float4* s = (const float4*)(src) + (size_t)idx*2;
        float4 v0 = s[0], v1 = s[1];
        float f[8] = {v0.x,v0.y,v0.z,v0.w,v1.x,v1.y,v1.z,v1.w};
        #pragma unroll
        for (int i=0;i<4;i++){
            unsigned short h0 = f2bf(f[i*2]), h1 = f2bf(f[i*2+1]);
            unsigned short l0 = f2bf(f[i*2]-bf2f(h0)), l1 = f2bf(f[i*2+1]-bf2f(h1));
            hh[i] = (unsigned)h0 | ((unsigned)h1<<16);
            ll[i] = (unsigned)l0 | ((unsigned)l1<<16);
        }
    }
    *(uint4*)(hi + (size_t)idx*8) = make_uint4(hh[0],hh[1],hh[2],hh[3]);
    *(uint4*)(lo + (size_t)idx*8) = make_uint4(ll[0],ll[1],ll[2],ll[3]);
}

// -------- tensor-core GEMM, cp.async 3-stage pipeline (no epilogue) --------
__global__ void __launch_bounds__(256,2) tgemm_kernel(
    const unsigned short* __restrict__ Ahi, const unsigned short* __restrict__ Alo,
    const unsigned short* __restrict__ Bhi, const unsigned short* __restrict__ Blo,
    float* __restrict__ C, int M, int N, int K)
{
    extern __shared__ unsigned short sm[];
    const int tid  = threadIdx.x;
    const int lane = tid & 31;
    const int warp = tid >> 5;
    const int warp_m = warp & 3;
    const int warp_n = warp >> 2;
    const int brow = blockIdx.y * 128;
    const int bcol = blockIdx.x * 128;

    float c[2][8][4];
    #pragma unroll
    for (int i=0;i<2;i++)
        #pragma unroll
        for (int j=0;j<8;j++)
            #pragma unroll
            for (int t=0;t<4;t++) c[i][j][t]=0.f;

    const unsigned sb = (unsigned)__cvta_generic_to_shared(sm);
    const int ar = tid >> 1;
    const int ac = (tid & 1) * 16;
    const int br = tid >> 3;
    const int bc = (tid & 7) * 16;

    const unsigned short* Ahg = Ahi + (size_t)(brow + ar)*K + ac;
    const unsigned short* Alg = Alo + (size_t)(brow + ar)*K + ac;
    const unsigned short* Bhg = Bhi + (size_t)br*N + bcol + bc;
    const unsigned short* Blg = Blo + (size_t)br*N + bcol + bc;

    const unsigned a_dst = sb + (unsigned)(ar*40 + ac)*2u;
    const unsigned b_dst = sb + B_OFFB + (unsigned)(br*136 + bc)*2u;

    #define ISSUE_STAGE(KT, BUF) do {                                   \
        unsigned a0 = a_dst + (BUF)*STAGE_B;                             \
        CP16(a0,            Ahg + (KT));                                 \
        CP16(a0 + 16u,      Ahg + (KT) + 8);                             \
        CP16(a0 + AL_OFFB,       Alg + (KT));                            \
        CP16(a0 + AL_OFFB + 16u, Alg + (KT) + 8);                        \
        unsigned b0 = b_dst + (BUF)*STAGE_B;                             \
        const unsigned short* bhp = Bhg + (size_t)(KT)*N;                \
        const unsigned short* blp = Blg + (size_t)(KT)*N;                \
        CP16(b0,            bhp);                                        \
        CP16(b0 + 16u,      bhp + 8);                                    \
        CP16(b0 + BL_OFFB,       blp);                                   \
        CP16(b0 + BL_OFFB + 16u, blp + 8);                               \
        asm volatile("cp.async.commit_group;\n" ::);                     \
    } while(0)

    const int T = K >> 5;
    ISSUE_STAGE(0, 0);
    ISSUE_STAGE(32, 1);

    int buf = 0;
    for (int t = 0; t < T; t++) {
        if (t + 1 < T) {
            asm volatile("cp.async.wait_group 1;\n" ::);
        } else {
            asm volatile("cp.async.wait_group 0;\n" ::);
        }
        __syncthreads();
        if (t + 2 < T) {
            int nb = buf + 2; if (nb >= 3) nb -= 3;
            ISSUE_STAGE((t+2)*32, nb);
        }

        const unsigned s0 = sb + (unsigned)buf*STAGE_B;
        #pragma unroll
        for (int ks = 0; ks < 2; ks++) {
            unsigned ah[2][4], al[2][4];
            #pragma unroll
            for (int mt = 0; mt < 2; mt++) {
                int ar2 = warp_m*32 + mt*16 + (lane & 15);
                int ac2 = ((lane >> 4) << 3) + ks*16;
                unsigned off = s0 + (unsigned)(ar2*40 + ac2)*2u;
                LDSM_X4(ah[mt][0],ah[mt][1],ah[mt][2],ah[mt][3], off);
                LDSM_X4(al[mt][0],al[mt][1],al[mt][2],al[mt][3], off + AL_OFFB);
            }
            #pragma unroll
            for (int np = 0; np < 4; np++) {
                unsigned bh[4], bl[4];
                int bk = (lane & 7) + (((lane >> 3) & 1) << 3) + ks*16;
                int bn = warp_n*64 + np*16 + ((lane >> 4) << 3);
                unsigned off = s0 + B_OFFB + (unsigned)(bk*136 + bn)*2u;
                LDSM_X4T(bh[0],bh[1],bh[2],bh[3], off);
                LDSM_X4T(bl[0],bl[1],bl[2],bl[3], off + BL_OFFB);
                #pragma unroll
                for (int mt = 0; mt < 2; mt++) {
                    #pragma unroll
                    for (int jj = 0; jj < 2; jj++) {
                        int j = np*2 + jj, o = jj*2;
                        MMA_BF16(c[mt][j], ah[mt][0],ah[mt][1],ah[mt][2],ah[mt][3],
                                 bh[o], bh[o+1]);
                        MMA_BF16(c[mt][j], ah[mt][0],ah[mt][1],ah[mt][2],ah[mt][3],
                                 bl[o], bl[o+1]);
                        MMA_BF16(c[mt][j], al[mt][0],al[mt][1],al[mt][2],al[mt][3],
                                 bh[o], bh[o+1]);
                    }
                }
            }
        }
        if (++buf >= 3) buf = 0;
    }
    #undef ISSUE_STAGE

    #pragma unroll
    for (int mt = 0; mt < 2; mt++) {
        int r0 = brow + warp_m*32 + mt*16 + (lane >> 2);
        #pragma unroll
        for (int j = 0; j < 8; j++) {
            int col = bcol + warp_n*64 + j*8 + (lane & 3)*2;
            *(float2*)&C[(size_t)r0*N + col]     = make_float2(c[mt][j][0], c[mt][j][1]);
            *(float2*)&C[(size_t)(r0+8)*N + col] = make_float2(c[mt][j][2], c[mt][j][3]);
        }
    }
}

// --------- Wr1 GEMM fused with gelu + router logits (atomicAdd), 3-stage ---
__global__ void __launch_bounds__(256,2) tgemm_router_kernel(
    const unsigned short* __restrict__ Axhi, const unsigned short* __restrict__ Axlo,
    const unsigned short* __restrict__ Sthi, const unsigned short* __restrict__ Stlo,
    const unsigned short* __restrict__ Bhi, const unsigned short* __restrict__ Blo,
    const float* __restrict__ bias, const float* __restrict__ Wr2,
    float* __restrict__ logits)
{
    extern __shared__ unsigned short sm[];
    const int tid  = threadIdx.x;
    const int lane = tid & 31;
    const int warp = tid >> 5;
    const int warp_m = warp & 3;
    const int warp_n = warp >> 2;
    const int brow = blockIdx.y * 128;
    const int bcol = blockIdx.x * 128;
    const int N = 2048;

    float c[2][8][4];
    #pragma unroll
    for (int i=0;i<2;i++)
        #pragma unroll
        for (int j=0;j<8;j++)
            #pragma unroll
            for (int t=0;t<4;t++) c[i][j][t]=0.f;

    const unsigned sb = (unsigned)__cvta_generic_to_shared(sm);
    const int ar = tid >> 1;
    const int ac = (tid & 1) * 16;
    const int br = tid >> 3;
    const int bc = (tid & 7) * 16;

    const unsigned short* Bhg = Bhi + (size_t)br*N + bcol + bc;
    const unsigned short* Blg = Blo + (size_t)br*N + bcol + bc;

    const unsigned a_dst = sb + (unsigned)(ar*40 + ac)*2u;
    const unsigned b_dst = sb + B_OFFB + (unsigned)(br*136 + bc)*2u;

    #define TCR_ISSUE(KT, BUF) do {                                          \
        unsigned a0 = a_dst + (BUF)*STAGE_B;                                  \
        const unsigned short* ah_src; const unsigned short* al_src;           \
        if ((KT) < 1024) {                                                    \
            ah_src = Axhi + (size_t)(brow+ar)*1024 + (KT) + ac;               \
            al_src = Axlo + (size_t)(brow+ar)*1024 + (KT) + ac;               \
        } else {                                                              \
            ah_src = Sthi + (size_t)(brow+ar)*64 + ((KT)-1024) + ac;          \
            al_src = Stlo + (size_t)(brow+ar)*64 + ((KT)-1024) + ac;          \
        }                                                                     \
        CP16(a0,            ah_src);                                          \
        CP16(a0 + 16u,      ah_src + 8);                                      \
        CP16(a0 + AL_OFFB,       al_src);                                     \
        CP16(a0 + AL_OFFB + 16u, al_src + 8);                                 \
        unsigned b0 = b_dst + (BUF)*STAGE_B;                                  \
        const unsigned short* bhp = Bhg + (size_t)(KT)*N;                     \
        const unsigned short* blp = Blg + (size_t)(KT)*N;                     \
        CP16(b0,            bhp);                                             \
        CP16(b0 + 16u,      bhp + 8);                                         \
        CP16(b0 + BL_OFFB,       blp);                                        \
        CP16(b0 + BL_OFFB + 16u, blp + 8);                                    \
        asm volatile("cp.async.commit_group;\n" ::);                          \
    } while(0)

    const int T = 34;     // K = 1088
    TCR_ISSUE(0, 0);
    TCR_ISSUE(32, 1);

    int buf = 0;
    for (int t = 0; t < T; t++) {
        if (t + 1 < T) {
            asm volatile("cp.async.wait_group 1;\n" ::);
        } else {
            asm volatile("cp.async.wait_group 0;\n" ::);
        }
        __syncthreads();
        if (t + 2 < T) {
            int nb = buf + 2; if (nb >= 3) nb -= 3;
            TCR_ISSUE((t+2)*32, nb);
        }

        const unsigned s0 = sb + (unsigned)buf*STAGE_B;
        #pragma unroll
        for (int ks = 0; ks < 2; ks++) {
            unsigned ah[2][4], al[2][4];
            #pragma unroll
            for (int mt = 0; mt < 2; mt++) {
                int ar2 = warp_m*32 + mt*16 + (lane & 15);
                int ac2 = ((lane >> 4) << 3) + ks*16;
                unsigned off = s0 + (unsigned)(ar2*40 + ac2)*2u;
                LDSM_X4(ah[mt][0],ah[mt][1],ah[mt][2],ah[mt][3], off);
                LDSM_X4(al[mt][0],al[mt][1],al[mt][2],al[mt][3], off + AL_OFFB);
            }
            #pragma unroll
            for (int np = 0; np < 4; np++) {
                unsigned bh[4], bl[4];
                int bk = (lane & 7) + (((lane >> 3) & 1) << 3) + ks*16;
                int bn = warp_n*64 + np*16 + ((lane >> 4) << 3);
                unsigned off = s0 + B_OFFB + (unsigned)(bk*136 + bn)*2u;
                LDSM_X4T(bh[0],bh[1],bh[2],bh[3], off);
                LDSM_X4T(bl[0],bl[1],bl[2],bl[3], off + BL_OFFB);
                #pragma unroll
                for (int mt = 0; mt < 2; mt++) {
                    #pragma unroll
                    for (int jj = 0; jj < 2; jj++) {
                        int j = np*2 + jj, o = jj*2;
                        MMA_BF16(c[mt][j], ah[mt][0],ah[mt][1],ah[mt][2],ah[mt][3],
                                 bh[o], bh[o+1]);
                        MMA_BF16(c[mt][j], ah[mt][0],ah[mt][1],ah[mt][2],ah[mt][3],
                                 bl[o], bl[o+1]);
                        MMA_BF16(c[mt][j], al[mt][0],al[mt][1],al[mt][2],al[mt][3],
                                 bh[o], bh[o+1]);
                    }
                }
            }
        }
        if (++buf >= 3) buf = 0;
    }
    #undef TCR_ISSUE

    __syncthreads();
    // ---- fused epilogue: bias + exact gelu + router partial logits ----
    float* w2s = (float*)sm;      // 128 cols x 12 outs = 1536 floats
    for (int i = tid; i < 1536; i += 256)
        w2s[i] = Wr2[(size_t)(bcol + i/12)*12 + (i%12)];
    __syncthreads();

    #pragma unroll
    for (int mt = 0; mt < 2; mt++) {
        #pragma unroll
        for (int rr = 0; rr < 2; rr++) {
            int row = brow + warp_m*32 + mt*16 + (lane >> 2) + rr*8;
            float lsum[12];
            #pragma unroll
            for (int o2=0;o2<12;o2++) lsum[o2]=0.f;
            #pragma unroll
            for (int j = 0; j < 8; j++) {
                int cl = warp_n*64 + j*8 + (lane & 3)*2;
                float v0 = c[mt][j][rr*2+0] + bias[bcol+cl];
                float v1 = c[mt][j][rr*2+1] + bias[bcol+cl+1];
                v0 = 0.5f*v0*(1.0f+erff(v0*0.70710678118654752f));
                v1 = 0.5f*v1*(1.0f+erff(v1*0.70710678118654752f));
                #pragma unroll
                for (int o2=0;o2<12;o2++)
                    lsum[o2] += v0*w2s[cl*12+o2] + v1*w2s[(cl+1)*12+o2];
            }
            #pragma unroll
            for (int o2=0;o2<12;o2++){
                lsum[o2] += __shfl_xor_sync(0xffffffffu, lsum[o2], 1);
                lsum[o2] += __shfl_xor_sync(0xffffffffu, lsum[o2], 2);
            }
            if ((lane & 3) == 0) {
                #pragma unroll
                for (int o2=0;o2<12;o2++)
                    atomicAdd(&logits[(size_t)row*12 + o2], lsum[o2]);
            }
        }
    }
}

// ---------------- beta + id-gate from qkvlin cols 3072..3079 ----------------
__global__ void __launch_bounds__(256) beta_sid_kernel(
    const float* __restrict__ qkvlin, const float* __restrict__ bid,
    float* __restrict__ beta, float* __restrict__ sid)
{
    int idx = blockIdx.x*256 + threadIdx.x;
    if (idx >= NTOK*4) return;
    int n = idx >> 2, h = idx & 3;
    const float* row = qkvlin + (size_t)n*3200;
    beta[idx] = sigm(row[3072 + h]);
    sid[idx]  = sigm(row[3076 + h] + bid[h]);
}

// ---------------- fused causal depthwise conv (k=4) + silu, 3 streams -------
__global__ void __launch_bounds__(256) conv_silu_kernel(
    const float* __restrict__ in, const float* __restrict__ cq,
    const float* __restrict__ ck, const float* __restrict__ cv,
    float* __restrict__ qb, float* __restrict__ kb, float* __restrict__ vb)
{
    long long gidx = (long long)blockIdx.x*256 + threadIdx.x;
    int s = (int)(gidx >> 23);
    int idx = (int)(gidx & ((1<<23)-1));
    int c = idx & 1023;
    int n = idx >> 10;
    int l = n & (LSEQ-1);
    const float* cw = (s==0)? cq : (s==1)? ck : cv;
    float* out = (s==0)? qb : (s==1)? kb : vb;
    float4 wv = *(const float4*)(cw + (size_t)c*4);
    float wj[4] = {wv.x, wv.y, wv.z, wv.w};
    float acc = 0.f;
    #pragma unroll
    for (int j=0;j<4;j++){
        int t = l - 3 + j;
        if (t >= 0) acc += in[(size_t)(n-3+j)*3200 + s*1024 + c] * wj[j];
    }
    out[idx] = acc / (1.0f + expf(-acc));
}

// ---------------- per-chunk prep: l2norm, T, u, w, attn ----------------
__global__ void __launch_bounds__(256) chunk_prep_kernel(
    float* __restrict__ q, float* __restrict__ k, const float* __restrict__ v,
    const float* __restrict__ beta, float* __restrict__ u, float* __restrict__ w,
    float* __restrict__ attn)
{
    extern __shared__ float sh[];
    float* qs = sh;
    float* ks = qs + 32*260;
    float* vs = ks + 32*260;
    float* T  = vs + 32*260;
    float* bet = T + 32*33;
    int ci = blockIdx.x;
    int c = ci & 127;
    int h = (ci >> 7) & 3;
    int b = ci >> 9;
    int tid = threadIdx.x;
    size_t base = ((size_t)(b*LSEQ + c*32))*1024 + (size_t)h*256;
    for (int i=tid; i<2048; i+=256) {
        int r = i>>6; int d4 = (i&63)<<2;
        size_t off = base + (size_t)r*1024 + d4;
        *(float4*)&qs[r*260+d4] = *(const float4*)(q + off);
        *(float4*)&ks[r*260+d4] = *(const float4*)(k + off);
        *(float4*)&vs[r*260+d4] = *(const float4*)(v + off);
    }
    if (tid < 32) bet[tid] = beta[(size_t)(b*LSEQ + c*32 + tid)*4 + h];
    __syncthreads();
    {
        int wi = tid>>5, lane = tid&31;
        for (int r = wi*4; r < wi*4+4; r++) {
            float sq=0.f, sk2=0.f;
            for (int dd=lane; dd<256; dd+=32){
                float a=qs[r*260+dd]; sq+=a*a;
                float bb=ks[r*260+dd]; sk2+=bb*bb;
            }
            #pragma unroll
            for (int o=16;o;o>>=1){
                sq+=__shfl_xor_sync(0xffffffffu,sq,o);
                sk2+=__shfl_xor_sync(0xffffffffu,sk2,o);
            }
            float rq = rsqrtf(sq+1e-6f), rk = rsqrtf(sk2+1e-6f);
            for (int dd=lane; dd<256; dd+=32){ qs[r*260+dd]*=rq; ks[r*260+dd]*=rk; }
        }
    }
    __syncthreads();
    size_t abase = (size_t)ci*1024;
    for (int pp=tid; pp<1024; pp+=256) {
        int i = pp>>5, j = pp&31;
        float dkk=0.f, dqq=0.f;
        for (int dd=0; dd<256; dd++){
            float kj = ks[j*260+dd];
            dkk += ks[i*260+dd]*kj;
            dqq += qs[i*260+dd]*kj;
        }
        T[i*33+j] = (j<i)? (-bet[i]*dkk) : 0.f;
        attn[abase+pp] = (j<=i)? dqq : 0.f;
    }
    __syncthreads();
    if (tid<32) {
        int lane = tid;
        for (int i=1;i<32;i++){
            float rowv = T[i*33+lane];
            float add = 0.f;
            for (int j=0;j<i;j++) add += __shfl_sync(0xffffffffu, rowv, j)*T[j*33+lane];
            T[i*33+lane] = rowv + add;
            __syncwarp();
        }
        T[lane*33+lane] += 1.0f;
    }
    __syncthreads();
    for (int pp=tid; pp<8192; pp+=256){
        int r = pp>>8, dd = pp&255;
        float su=0.f, sw=0.f;
        #pragma unroll
        for (int j=0;j<32;j++){
            float tj = T[r*33+j]*bet[j];
            su += tj*vs[j*260+dd];
            sw += tj*ks[j*260+dd];
        }
        size_t off = base + (size_t)r*1024 + dd;
        u[off]=su; w[off]=sw;
        q[off]=qs[r*260+dd]; k[off]=ks[r*260+dd];
    }
}

// ---------------- sequential chunk scan, dv-sliced (16 slices of 16) -------
__global__ void __launch_bounds__(512) scan_kernel(
    const float* __restrict__ q, const float* __restrict__ k,
    const float* __restrict__ u, const float* __restrict__ w,
    const float* __restrict__ attn, float* __restrict__ outp)
{
    extern __shared__ float sh[];
    float* S  = sh;
    float* qs = S + 4096;
    float* ks = qs + 8320;
    float* ws = ks + 8320;
    float* as = ws + 8320;
    float* u2 = as + 1024;
    int bid = blockIdx.x;
    int sl = bid & 15;
    int bh = bid >> 4;
    int h = bh & 3, b = bh >> 2;
    int tid = threadIdx.x;
    for (int i=tid;i<4096;i+=512) S[i]=0.f;
    const int iRow = tid >> 4;
    const int q1 = tid & 15;
    const int dd0 = tid >> 2;
    const int c4 = (tid & 3) * 4;
    size_t abh = (size_t)bh * 128 * 1024;
    for (int c=0;c<128;c++){
        size_t base = ((size_t)(b*LSEQ + c*32))*1024 + (size_t)h*256;
        __syncthreads();
        for (int i=tid;i<2048;i+=512){
            int r=i>>6; int d4=(i&63)<<2;
            size_t off = base + (size_t)r*1024 + d4;
            *(float4*)&qs[r*260+d4] = *(const float4*)(q+off);
            *(float4*)&ks[r*260+d4] = *(const float4*)(k+off);
            *(float4*)&ws[r*260+d4] = *(const float4*)(w+off);
        }
        if (tid < 256)
            *(float4*)&as[tid*4] = *(const float4*)(attn + abh + (size_t)c*1024 + tid*4);
        __syncthreads();
        float au = u[base + (size_t)iRow*1024 + sl*16 + q1];
        float ao = 0.f;
        #pragma unroll 8
        for (int dd=0; dd<256; dd++){
            float Sv = S[dd*16+q1];
            au -= ws[iRow*260+dd]*Sv;
            ao += qs[iRow*260+dd]*Sv;
        }
        u2[iRow*16+q1] = au;
        __syncthreads();
        #pragma unroll
        for (int j=0;j<32;j++) ao += as[iRow*32+j]*u2[j*16+q1];
        outp[base + (size_t)iRow*1024 + sl*16 + q1] = ao;
        #pragma unroll
        for (int s2=0; s2<2; s2++){
            int dd = dd0 + s2*128;
            float4 Sv = *(float4*)&S[dd*16+c4];
            #pragma unroll 8
            for (int j=0;j<32;j++){
                float kv = ks[j*260+dd];
                float4 uv = *(float4*)&u2[j*16+c4];
                Sv.x += kv*uv.x; Sv.y += kv*uv.y; Sv.z += kv*uv.z; Sv.w += kv*uv.w;
            }
            *(float4*)&S[dd*16+c4] = Sv;
        }
    }
}

// ---------------- FIR + stats (smem-tiled, bf16 stats plane out) -----------
__global__ void __launch_bounds__(256) fir_stats_kernel(
    const float* __restrict__ v, const float* __restrict__ dlt,
    const float* __restrict__ firS, const float* __restrict__ firL,
    float* __restrict__ fs, float* __restrict__ fl,
    unsigned short* __restrict__ sthi, unsigned short* __restrict__ stlo)
{
    extern __shared__ float vsm[];
    __shared__ float red[8][6];
    const int h  = blockIdx.y;
    const int t0 = blockIdx.x * 32;
    const int l0 = t0 & (LSEQ-1);
    const int tid = threadIdx.x;
    const int d = tid;
    const int cidx = h*256 + d;
    const int lane = tid & 31, wrp = tid >> 5;

    if (h == 0 && tid < 32) {
        size_t dst = (size_t)(t0+tid)*64 + 24;
        #pragma unroll
        for (int j=0;j<5;j++){
            *(uint4*)(sthi + dst + j*8) = make_uint4(0,0,0,0);
            *(uint4*)(stlo + dst + j*8) = make_uint4(0,0,0,0);
        }
    }

    for (int i = tid; i < 62*64; i += 256) {
        int r = i >> 6; int c4 = (i & 63) << 2;
        float4 val = make_float4(0.f,0.f,0.f,0.f);
        if (l0 - 30 + r >= 0)
            val = *(const float4*)(v + (size_t)(t0-30+r)*1024 + h*256 + c4);
        *(float4*)&vsm[r*256 + c4] = val;
    }
    __syncthreads();

    float fS[3], fL[31];
    #pragma unroll
    for (int j=0;j<3;j++)  fS[j] = firS[(size_t)cidx*3+j];
    #pragma unroll
    for (int j=0;j<31;j++) fL[j] = firL[(size_t)cidx*31+j];

    for (int tt = 0; tt < 32; tt++) {
        int row = tt + 30;
        int n = t0 + tt;
        float accS = 0.f;
        #pragma unroll
        for (int j=0;j<3;j++) accS += vsm[(row-2+j)*256 + d]*fS[j];
        float accL = 0.f;
        #pragma unroll
        for (int j=0;j<31;j++) accL += vsm[(row-30+j)*256 + d]*fL[j];
        float dv = dlt[(size_t)n*1024 + cidx];
        fs[(size_t)n*1024 + cidx] = accS;
        fl[(size_t)n*1024 + cidx] = accL;

        float vals[6] = {accS, accS*accS, accL, accL*accL, dv, dv*dv};
        #pragma unroll
        for (int k2=0;k2<6;k2++){
            float s = vals[k2];
            #pragma unroll
            for (int o=16;o;o>>=1) s += __shfl_xor_sync(0xffffffffu, s, o);
            if (lane==0) red[wrp][k2] = s;
        }
        __syncthreads();
        if (tid == 0) {
            float s[6];
            #pragma unroll
            for (int k2=0;k2<6;k2++){
                float a = 0.f;
                #pragma unroll
                for (int ww=0;ww<8;ww++) a += red[ww][k2];
                s[k2] = a;
            }
            float m1 = s[0]*(1.f/256.f), m3 = s[2]*(1.f/256.f), m5 = s[4]*(1.f/256.f);
            float o[6];
            o[0]=m1;
            o[1]=sqrtf(fmaxf(s[1]*(1.f/256.f)-m1*m1,0.f));
            o[2]=m3;
            o[3]=sqrtf(fmaxf(s[3]*(1.f/256.f)-m3*m3,0.f));
            o[4]=m5;
            o[5]=sqrtf(fmaxf(s[5]*(1.f/256.f)-m5*m5,0.f));
            size_t rb = (size_t)n*64 + h;
            #pragma unroll
            for (int k2=0;k2<6;k2++){
                unsigned short hh = f2bf(o[k2]);
                sthi[rb + k2*4] = hh;
                stlo[rb + k2*4] = f2bf(o[k2]-bf2f(hh));
            }
        }
        __syncthreads();
    }
}

// ---------------- softmax over router logits ----------------
__global__ void __launch_bounds__(256) softmax_router_kernel(
    const float* __restrict__ logits, const float* __restrict__ br2,
    const float* __restrict__ ltg, float* __restrict__ p)
{
    int n = blockIdx.x*256 + threadIdx.x;
    if (n >= NTOK) return;
    float lg[12];
    #pragma unroll
    for (int i=0;i<12;i++) lg[i] = logits[(size_t)n*12+i] + br2[i];
    #pragma unroll
    for (int h=0;h<4;h++){
        float tau = expf(ltg[h>>1]);
        float a = lg[h*3+0]/tau, bq = lg[h*3+1]/tau, cq = lg[h*3+2]/tau;
        float m = fmaxf(a, fmaxf(bq,cq));
        float ea=expf(a-m), eb=expf(bq-m), ec=expf(cq-m);
        float inv = 1.f/(ea+eb+ec);
        p[(size_t)n*12 + h*3+0] = ea*inv*0.925f + 0.025f;
        p[(size_t)n*12 + h*3+1] = eb*inv*0.925f + 0.025f;
        p[(size_t)n*12 + h*3+2] = ec*inv*0.925f + 0.025f;
    }
}

// ---------------- gated mix + id + RMS norm -> bf16 hi/lo -------------------
__global__ void __launch_bounds__(256) mix_norm_kernel(
    const float* __restrict__ p, const float* __restrict__ fs,
    const float* __restrict__ fl, const float* __restrict__ dlt,
    const float* __restrict__ v, const float* __restrict__ sid,
    const float* __restrict__ alpha_id, const float* __restrict__ onw,
    unsigned short* __restrict__ omhi, unsigned short* __restrict__ omlo)
{
    int n = blockIdx.x;
    int d = threadIdx.x;
    __shared__ float red[8];
    for (int h=0;h<4;h++){
        size_t idx = (size_t)n*1024 + h*256 + d;
        float p0 = p[(size_t)n*12+h*3+0];
        float p1 = p[(size_t)n*12+h*3+1];
        float p2 = p[(size_t)n*12+h*3+2];
        float ids = 0.06f + sigm(alpha_id[h]) * sid[(size_t)n*4+h];
        float o = p0*fs[idx] + p1*fl[idx] + p2*dlt[idx] + ids*v[idx];
        float ss = blockReduceSum(o*o, red);
        float r = rsqrtf(ss*(1.f/256.f) + 1e-5f);
        float val = o*r*onw[d];
        unsigned short hh = f2bf(val);
        omhi[idx] = hh;
        omlo[idx] = f2bf(val - bf2f(hh));
    }
}

extern "C" void kernel_launch(void* const* d_in, const int* in_sizes, int n_in,
                              void* d_out, int out_size) {
    const float* x    = (const float*)d_in[0];
    const float* Wq   = (const float*)d_in[1];
    const float* Wk   = (const float*)d_in[2];
    const float* Wv   = (const float*)d_in[3];
    const float* Wb   = (const float*)d_in[4];
    const float* cq   = (const float*)d_in[5];
    const float* ck   = (const float*)d_in[6];
    const float* cv   = (const float*)d_in[7];
    const float* firS = (const float*)d_in[8];
    const float* firL = (const float*)d_in[9];
    const float* aid  = (const float*)d_in[10];
    const float* Wid  = (const float*)d_in[11];
    const float* bid  = (const float*)d_in[12];
    const float* Wr1  = (const float*)d_in[13];
    const float* br1  = (const float*)d_in[14];
    const float* Wr2  = (const float*)d_in[15];
    const float* br2  = (const float*)d_in[16];
    const float* ltg  = (const float*)d_in[17];
    const float* onw  = (const float*)d_in[19];
    const float* Wo   = (const float*)d_in[20];
    float* out = (float*)d_out;

    void* bufv = nullptr;
    cudaGetSymbolAddress(&bufv, g_buf);
    float* buf = (float*)bufv;
    void* bbufv = nullptr;
    cudaGetSymbolAddress(&bbufv, g_bf);
    unsigned short* bbuf = (unsigned short*)bbufv;

    float* qkvlin = buf + OFF_QL;
    float* qb   = buf + OFF_Q;
    float* kb   = buf + OFF_K;
    float* vb   = buf + OFF_V;
    float* ub   = buf + OFF_U;
    float* wb   = buf + OFF_W;
    float* dlt  = buf + OFF_DELTA;
    float* fsb  = buf + OFF_FS;
    float* flb  = buf + OFF_FL;
    float* lgts = buf + OFF_LOGITS;
    float* attn = buf + OFF_ATTN;
    float* beta = buf + OFF_BETA;
    float* sidb = buf + OFF_SID;
    float* pb   = buf + OFF_P;

    unsigned short* xhi  = bbuf + BOFF_X_HI;
    unsigned short* xlo  = bbuf + BOFF_X_LO;
    unsigned short* omhi = bbuf + BOFF_OM_HI;
    unsigned short* omlo = bbuf + BOFF_OM_LO;
    unsigned short* sthi = bbuf + BOFF_ST_HI;
    unsigned short* stlo = bbuf + BOFF_ST_LO;
    unsigned short* wqkvhi = bbuf + BOFF_WQKV_HI;
    unsigned short* wqkvlo = bbuf + BOFF_WQKV_LO;
    unsigned short* wohi = bbuf + BOFF_WO_HI;
    unsigned short* wolo = bbuf + BOFF_WO_LO;
    unsigned short* w1hi = bbuf + BOFF_W1_HI;
    unsigned short* w1lo = bbuf + BOFF_W1_LO;

    int smem_prep = (3*32*260 + 32*33 + 32) * 4;
    int smem_scan = (4096 + 3*8320 + 1024 + 512) * 4;
    int smem_fir  = 62*256*4;
    cudaFuncSetAttribute(chunk_prep_kernel, cudaFuncAttributeMaxDynamicSharedMemorySize, smem_prep);
    cudaFuncSetAttribute(scan_kernel, cudaFuncAttributeMaxDynamicSharedMemorySize, smem_scan);
    cudaFuncSetAttribute(fir_stats_kernel, cudaFuncAttributeMaxDynamicSharedMemorySize, smem_fir);
    cudaFuncSetAttribute(tgemm_kernel, cudaFuncAttributeMaxDynamicSharedMemorySize, SMEM_GEMM);
    cudaFuncSetAttribute(tgemm_router_kernel, cudaFuncAttributeMaxDynamicSharedMemorySize, SMEM_GEMM);

    // ---- init + conversions ----
    zero_kernel<<<96, 256>>>(lgts, NTOK*12/4);
    f2bf_split_kernel<<<4096, 256>>>(x, xhi, xlo, 8192*1024/8);
    f2bf_pack_qkv_kernel<<<1600, 256>>>(Wq, Wk, Wv, Wb, Wid, wqkvhi, wqkvlo);
    f2bf_split_kernel<<<512, 256>>>(Wo, wohi, wolo, 1024*1024/8);
    f2bf_split_pad_kernel<<<1088, 256>>>(Wr1, w1hi, w1lo);

    dim3 blk(256);
    dim3 gqkv(25, 64);
    tgemm_kernel<<<gqkv, blk, SMEM_GEMM>>>(xhi, xlo, wqkvhi, wqkvlo, qkvlin, NTOK, 3200, 1024);
    beta_sid_kernel<<<128, 256>>>(qkvlin, bid, beta, sidb);
    conv_silu_kernel<<<3*NTOK*4, 256>>>(qkvlin, cq, ck, cv, qb, kb, vb);
    chunk_prep_kernel<<<1024, 256, smem_prep>>>(qb, kb, vb, beta, ub, wb, attn);
    scan_kernel<<<128, 512, smem_scan>>>(qb, kb, ub, wb, attn, dlt);
    dim3 gfir(NTOK/32, 4);
    fir_stats_kernel<<<gfir, 256, smem_fir>>>(vb, dlt, firS, firL, fsb, flb, sthi, stlo);
    dim3 g2(16, 64);
    tgemm_router_kernel<<<g2, blk, SMEM_GEMM>>>(xhi, xlo, sthi, stlo, w1hi, w1lo, br1, Wr2, lgts);
    softmax_router_kernel<<<32, 256>>>(lgts, br2, ltg, pb);
    mix_norm_kernel<<<NTOK, 256>>>(pb, fsb, flb, dlt, vb, sidb, aid, onw, omhi, omlo);
    dim3 g1(8, 64);
    tgemm_kernel<<<g1, blk, SMEM_GEMM>>>(omhi, omlo, wohi, wolo, out, NTOK, 1024, 1024);
}